// round 7
// baseline (speedup 1.0000x reference)
#include <cuda_runtime.h>
#include <cuda_bf16.h>
#include <math.h>
#include <cstdint>

typedef unsigned long long u64;
typedef unsigned int u32;

#define HEADS 8
#define NDIM  256
#define INNER 512
#define NTOKS 4096
#define BATCH 8
#define MTOT  (BATCH * NTOKS)   // 32768

// ---------------- scratch (device globals: allocation-guard safe) ----------------
__device__ float g_kv  [(size_t)MTOT * 1024];            // fp32 kv raw GEMM output
__device__ float g_dotp[(size_t)64 * 8 * 64 * 64];       // dots split-K partials
__device__ __nv_bfloat16 g_z2  [(size_t)MTOT * 512];     // z split  [M, 2K]
__device__ __nv_bfloat16 g_x2  [(size_t)MTOT * 512];     // x split
__device__ __nv_bfloat16 g_wkv2[(size_t)1024 * 512];     // Wkv^T split [N, 2K]
__device__ __nv_bfloat16 g_wq2 [(size_t)512 * 512];      // Wq^T split
__device__ __nv_bfloat16 g_q2  [(size_t)MTOT * 1024];    // q post-rotary split [M, 2K]
__device__ __nv_bfloat16 g_w2s [(size_t)BATCH * 256 * 1024]; // W2^T split [b][256][1024]

// ---------------- sm_80-class MMA helpers (legal on plain sm_103) ----------------
__device__ __forceinline__ u32 smem_u32(const void* p) {
    u32 a; asm("{ .reg .u64 t; cvta.to.shared.u64 t, %1; cvt.u32.u64 %0, t; }" : "=r"(a) : "l"(p));
    return a;
}
__device__ __forceinline__ void cpa16(u32 dst, const void* src) {
    asm volatile("cp.async.cg.shared.global [%0], [%1], 16;" :: "r"(dst), "l"(src));
}
#define CP_COMMIT() asm volatile("cp.async.commit_group;" ::: "memory")
#define CP_WAIT(n)  asm volatile("cp.async.wait_group %0;" :: "n"(n) : "memory")

__device__ __forceinline__ void ldsm4(u32* r, u32 a) {
    asm volatile("ldmatrix.sync.aligned.m8n8.x4.shared.b16 {%0,%1,%2,%3}, [%4];"
        : "=r"(r[0]), "=r"(r[1]), "=r"(r[2]), "=r"(r[3]) : "r"(a));
}
__device__ __forceinline__ void ldsm4t(u32* r, u32 a) {
    asm volatile("ldmatrix.sync.aligned.m8n8.x4.trans.shared.b16 {%0,%1,%2,%3}, [%4];"
        : "=r"(r[0]), "=r"(r[1]), "=r"(r[2]), "=r"(r[3]) : "r"(a));
}
__device__ __forceinline__ void mma16816(float* c, const u32* a, const u32* b) {
    asm volatile("mma.sync.aligned.m16n8k16.row.col.f32.bf16.bf16.f32 "
        "{%0,%1,%2,%3}, {%4,%5,%6,%7}, {%8,%9}, {%0,%1,%2,%3};"
        : "+f"(c[0]), "+f"(c[1]), "+f"(c[2]), "+f"(c[3])
        : "r"(a[0]), "r"(a[1]), "r"(a[2]), "r"(a[3]), "r"(b[0]), "r"(b[1]));
}

// ---------------- f32x2 helpers ----------------
__device__ __forceinline__ u64 pack2(float x, float y) {
    u64 r; asm("mov.b64 %0, {%1,%2};" : "=l"(r) : "f"(x), "f"(y)); return r;
}
__device__ __forceinline__ u64 ffma2(u64 a, u64 b, u64 c) {
    u64 d; asm("fma.rn.f32x2 %0, %1, %2, %3;" : "=l"(d) : "l"(a), "l"(b), "l"(c)); return d;
}
__device__ __forceinline__ void unpack2(u64 v, float& x, float& y) {
    asm("mov.b64 {%0,%1}, %2;" : "=f"(x), "=f"(y) : "l"(v));
}

// ---------------- split conversion ----------------
__device__ __forceinline__ void split1(float v, __nv_bfloat16& h, __nv_bfloat16& l) {
    h = __float2bfloat16(v);
    l = __float2bfloat16(v - __bfloat162float(h));
}

// in [R,256] fp32 -> out [R,512] bf16 (cols 0..255 hi, 256..511 lo)
__global__ void split_rows(const float* __restrict__ in, __nv_bfloat16* __restrict__ out) {
    size_t idx = (size_t)blockIdx.x * 256 + threadIdx.x;  // one float4
    size_t row = idx >> 6; int c4 = (int)(idx & 63);
    float4 v = ((const float4*)in)[idx];
    __nv_bfloat16 h0, l0, h1, l1, h2, l2, h3, l3;
    split1(v.x, h0, l0); split1(v.y, h1, l1); split1(v.z, h2, l2); split1(v.w, h3, l3);
    __nv_bfloat16* ph = out + row * 512 + c4 * 4;
    *(__nv_bfloat162*)(ph)     = __nv_bfloat162{h0, h1};
    *(__nv_bfloat162*)(ph + 2) = __nv_bfloat162{h2, h3};
    __nv_bfloat16* pl = ph + 256;
    *(__nv_bfloat162*)(pl)     = __nv_bfloat162{l0, l1};
    *(__nv_bfloat162*)(pl + 2) = __nv_bfloat162{l2, l3};
}

// W [256, N] fp32 -> out [N, 512] bf16 (transpose + split)
__global__ void split_wT(const float* __restrict__ W, __nv_bfloat16* __restrict__ out, int N) {
    int n = blockIdx.x, k = threadIdx.x;
    float v = W[(size_t)k * N + n];
    __nv_bfloat16 h, l; split1(v, h, l);
    out[(size_t)n * 512 + k]       = h;
    out[(size_t)n * 512 + 256 + k] = l;
}

// ---------------- split-bf16 HMMA GEMM, 4-stage cp.async pipeline ----------------
#define ROWB 80                  // 32 bf16 + 16B pad
#define TILEB (128 * ROWB)       // 10240
#define STAGEB (2 * TILEB)       // 20480 (A + B)
#define NSTAGE 4
#define GSMEM (NSTAGE * STAGEB)  // 81920

template <int MODE>
__global__ __launch_bounds__(256, 2) void gemm_mma(
    const __nv_bfloat16* __restrict__ A2, const __nv_bfloat16* __restrict__ B2,
    float* __restrict__ C, __nv_bfloat16* __restrict__ Cq,
    const float* __restrict__ pos, int N, int K2,
    long sA, long sB, long sC, const float* __restrict__ bias)
{
    extern __shared__ __align__(1024) char smem[];
    A2 += (size_t)blockIdx.z * sA;
    B2 += (size_t)blockIdx.z * sB;
    if (MODE == 0) C += (size_t)blockIdx.z * sC;
    const int m0 = blockIdx.y * 128, n0 = blockIdx.x * 128;
    const int tid = threadIdx.x, lane = tid & 31, wid = tid >> 5;
    const int wr = wid >> 2, wc = wid & 3;
    const u32 sb = smem_u32(smem);

    const int K = K2 >> 1;
    const int nch = K >> 5;
    const int total = 3 * nch;

    const int lrow = tid >> 1;
    const int lcg = (tid & 1) * 2;

    float acc[4][4][4];
    #pragma unroll
    for (int i = 0; i < 4; i++)
        #pragma unroll
        for (int j = 0; j < 4; j++)
            #pragma unroll
            for (int r = 0; r < 4; r++) acc[i][j][r] = 0.f;

    auto issue = [&](int it) {
        const int stage = it & (NSTAGE - 1);
        const int seg = it / nch;
        const int kk = (it - seg * nch) * 32;
        const int aoff = (seg == 1) ? K : 0;
        const int boff = (seg == 2) ? K : 0;
        const __nv_bfloat16* as = A2 + (size_t)(m0 + lrow) * K2 + aoff + kk + lcg * 8;
        const __nv_bfloat16* bs = B2 + (size_t)(n0 + lrow) * K2 + boff + kk + lcg * 8;
        const u32 da = sb + stage * STAGEB + lrow * ROWB + lcg * 16;
        cpa16(da, as);              cpa16(da + 16, as + 8);
        cpa16(da + TILEB, bs);      cpa16(da + TILEB + 16, bs + 8);
        CP_COMMIT();
    };

    auto compute = [&](int stage) {
        const u32 ab = sb + stage * STAGEB;
        const u32 bb = ab + TILEB;
        #pragma unroll
        for (int kb = 0; kb < 2; kb++) {
            u32 a[4][4], b[2][4];
            #pragma unroll
            for (int mf = 0; mf < 4; mf++) {
                u32 addr = ab + (u32)(wr * 64 + mf * 16 + (lane & 15)) * ROWB
                              + kb * 32 + (lane >> 4) * 16;
                ldsm4(a[mf], addr);
            }
            #pragma unroll
            for (int nfp = 0; nfp < 2; nfp++) {
                u32 addr = bb + (u32)(wc * 32 + nfp * 16 + ((lane >> 4) << 3) + (lane & 7)) * ROWB
                              + kb * 32 + ((lane >> 3) & 1) * 16;
                ldsm4(b[nfp], addr);
            }
            #pragma unroll
            for (int mf = 0; mf < 4; mf++)
                #pragma unroll
                for (int nf = 0; nf < 4; nf++)
                    mma16816(acc[mf][nf], a[mf], &b[nf >> 1][(nf & 1) * 2]);
        }
    };

    issue(0); issue(1); issue(2);
    for (int i = 0; i < total; i++) {
        if (i < total - 2)       CP_WAIT(2);
        else if (i == total - 2) CP_WAIT(1);
        else                     CP_WAIT(0);
        __syncthreads();
        compute(i & (NSTAGE - 1));
        if (i + 3 < total) issue(i + 3);
    }

    if (MODE == 0) {
        const int rbase = m0 + wr * 64 + (lane >> 2);
        const int cbase = n0 + wc * 32 + (lane & 3) * 2;
        #pragma unroll
        for (int nf = 0; nf < 4; nf++) {
            const int c = cbase + nf * 8;
            float bx = 0.f, by = 0.f;
            if (bias) { bx = bias[c]; by = bias[c + 1]; }
            #pragma unroll
            for (int mf = 0; mf < 4; mf++) {
                const int r = rbase + mf * 16;
                *(float2*)&C[(size_t)r * N + c] =
                    make_float2(acc[mf][nf][0] + bx, acc[mf][nf][1] + by);
                *(float2*)&C[(size_t)(r + 8) * N + c] =
                    make_float2(acc[mf][nf][2] + bx, acc[mf][nf][3] + by);
            }
        }
    } else {
        const int half = wc & 1;
        const int lq = lane & 3;
        #pragma unroll
        for (int mf = 0; mf < 4; mf++) {
            #pragma unroll
            for (int rb = 0; rb < 2; rb++) {
                const int r = m0 + wr * 64 + mf * 16 + (lane >> 2) + rb * 8;
                const float pp = pos[(size_t)r * 2 + half] * 64.f;
                const size_t rowb = (size_t)r * (2 * N);
                #pragma unroll
                for (int nf2 = 0; nf2 < 2; nf2++) {
                    float o[4];
                    #pragma unroll
                    for (int cb = 0; cb < 2; cb++) {
                        const int j = nf2 * 8 + lq * 2 + cb;
                        const float invf = exp2f(-(float)j * (13.287712379549449f / 16.f));
                        float s, co; sincosf(pp * invf, &s, &co);
                        const int idx = rb * 2 + cb;
                        const float vlo = acc[mf][nf2][idx];
                        const float vhi = acc[mf][nf2 + 2][idx];
                        o[cb]     = vlo * co - vhi * s;
                        o[2 + cb] = vhi * co + vlo * s;
                    }
                    const int cg = n0 + wc * 32 + nf2 * 8 + lq * 2;
                    __nv_bfloat16 h0, l0, h1, l1;
                    split1(o[0], h0, l0); split1(o[1], h1, l1);
                    *(__nv_bfloat162*)&Cq[rowb + cg]     = __nv_bfloat162{h0, h1};
                    *(__nv_bfloat162*)&Cq[rowb + N + cg] = __nv_bfloat162{l0, l1};
                    split1(o[2], h0, l0); split1(o[3], h1, l1);
                    *(__nv_bfloat162*)&Cq[rowb + cg + 16]     = __nv_bfloat162{h0, h1};
                    *(__nv_bfloat162*)&Cq[rowb + N + cg + 16] = __nv_bfloat162{l0, l1};
                }
            }
        }
    }
}

// ---------------- rotary helper ----------------
__device__ __forceinline__ void warp_rot(float& v0, float& v1, int l, float px, float py) {
    const int j = l & 15;
    const float invf = exp2f(-(float)j * (13.287712379549449f / 16.f));
    float sx, cx, sy, cy;
    sincosf(px * invf, &sx, &cx);
    sincosf(py * invf, &sy, &cy);
    float p0 = __shfl_xor_sync(0xffffffffu, v0, 16);
    float p1 = __shfl_xor_sync(0xffffffffu, v1, 16);
    if (l < 16) { v0 = v0 * cx - p0 * sx; v1 = v1 * cy - p1 * sy; }
    else        { v0 = v0 * cx + p0 * sx; v1 = v1 * cy + p1 * sy; }
}

// ---------------- fused norm+rotary+Gram split-K, register-resident norm ----------------
// smem: kh/kl/vh/vl bf16 [64][72] -> 36864 B total
#define DROWB 144
#define DTILE (64 * DROWB)       // 9216
#define DSM_BYTES (4 * DTILE)    // 36864

__global__ __launch_bounds__(256, 3) void dots_fused(const float* __restrict__ kv,
                                                     const float* __restrict__ z_pos,
                                                     float* __restrict__ part) {
    extern __shared__ __align__(1024) char dsm[];
    const u32 khb = smem_u32(dsm);
    const u32 klb = khb + DTILE;
    const u32 vhb = khb + 2 * DTILE;
    const u32 vlb = khb + 3 * DTILE;
    __nv_bfloat16* kh = (__nv_bfloat16*)dsm;

    const int split = blockIdx.x;   // 0..7
    const int bh = blockIdx.y;      // 0..63
    const int b = bh >> 3, h = bh & 7;
    const int tid = threadIdx.x;
    const int w = tid >> 5, lane = tid & 31;
    const int wr = w >> 1, wc = w & 1;
    const float* kvb = kv + (size_t)b * NTOKS * 1024 + h * 64;

    float acc[4][4];
    #pragma unroll
    for (int i = 0; i < 4; i++)
        #pragma unroll
        for (int j = 0; j < 4; j++) acc[i][j] = 0.f;

    for (int c = 0; c < 8; c++) {
        const int t0 = split * 512 + c * 64;
        // each warp: 8 tokens, load -> norm in regs -> rotary -> split -> smem bf16
        #pragma unroll
        for (int s = 0; s < 8; s++) {
            const int t = s * 8 + w;
            const float* row = kvb + (size_t)(t0 + t) * 1024;
            float k0 = row[lane],       k1 = row[lane + 32];
            float v0 = row[512 + lane], v1 = row[512 + lane + 32];
            // fused sum/sumsq reductions, 4 parallel chains
            float rs0 = k0 + k1, rs1 = k0 * k0 + k1 * k1;
            float rs2 = v0 + v1, rs3 = v0 * v0 + v1 * v1;
            #pragma unroll
            for (int o = 16; o; o >>= 1) {
                rs0 += __shfl_xor_sync(0xffffffffu, rs0, o);
                rs1 += __shfl_xor_sync(0xffffffffu, rs1, o);
                rs2 += __shfl_xor_sync(0xffffffffu, rs2, o);
                rs3 += __shfl_xor_sync(0xffffffffu, rs3, o);
            }
            const float muk = rs0 * (1.f / 64.f);
            const float invk = rsqrtf(fmaxf(rs1 * (1.f / 64.f) - muk * muk, 0.f) + 1e-5f);
            const float muv = rs2 * (1.f / 64.f);
            const float invv = rsqrtf(fmaxf(rs3 * (1.f / 64.f) - muv * muv, 0.f) + 1e-5f);
            float d0 = (k0 - muk) * invk, d1 = (k1 - muk) * invk;
            float e0 = (v0 - muv) * invv, e1 = (v1 - muv) * invv;
            const size_t tg = (size_t)b * NTOKS + t0 + t;
            const float px = z_pos[tg * 2 + 0] * 64.f;
            const float py = z_pos[tg * 2 + 1] * 64.f;
            warp_rot(d0, d1, lane, px, py);
            // split + store (STS.16, merged-word pattern)
            __nv_bfloat16 hh, ll;
            const u32 ro = (u32)t * DROWB + lane * 2;
            split1(d0, hh, ll);
            *(__nv_bfloat16*)(dsm + (ro))              = hh;
            *(__nv_bfloat16*)(dsm + DTILE + ro)        = ll;
            split1(d1, hh, ll);
            *(__nv_bfloat16*)(dsm + ro + 64)           = hh;
            *(__nv_bfloat16*)(dsm + DTILE + ro + 64)   = ll;
            split1(e0, hh, ll);
            *(__nv_bfloat16*)(dsm + 2 * DTILE + ro)      = hh;
            *(__nv_bfloat16*)(dsm + 3 * DTILE + ro)      = ll;
            split1(e1, hh, ll);
            *(__nv_bfloat16*)(dsm + 2 * DTILE + ro + 64) = hh;
            *(__nv_bfloat16*)(dsm + 3 * DTILE + ro + 64) = ll;
        }
        __syncthreads();
        // HMMA: D[64,64] += k~^T v~, split-bf16 3-term
        #pragma unroll
        for (int kt = 0; kt < 4; kt++) {
            const u32 arow = (u32)(kt * 16 + (lane & 7) + ((lane >> 4) << 3));
            const u32 acol = (u32)(wr * 16 + ((lane >> 3) & 1) * 8);
            const u32 aoff = arow * DROWB + acol * 2;
            u32 ah[4], al[4];
            ldsm4t(ah, khb + aoff);
            ldsm4t(al, klb + aoff);
            const u32 brow = (u32)(kt * 16 + (lane & 7) + ((lane >> 3) & 1) * 8);
            const u32 bcol = (u32)(wc * 32 + ((lane >> 4) << 3));
            const u32 boff = brow * DROWB + bcol * 2;
            u32 bh0[4], bl0[4], bh1[4], bl1[4];
            ldsm4t(bh0, vhb + boff);
            ldsm4t(bl0, vlb + boff);
            ldsm4t(bh1, vhb + boff + 32);
            ldsm4t(bl1, vlb + boff + 32);
            mma16816(acc[0], ah, &bh0[0]); mma16816(acc[0], al, &bh0[0]); mma16816(acc[0], ah, &bl0[0]);
            mma16816(acc[1], ah, &bh0[2]); mma16816(acc[1], al, &bh0[2]); mma16816(acc[1], ah, &bl0[2]);
            mma16816(acc[2], ah, &bh1[0]); mma16816(acc[2], al, &bh1[0]); mma16816(acc[2], ah, &bl1[0]);
            mma16816(acc[3], ah, &bh1[2]); mma16816(acc[3], al, &bh1[2]); mma16816(acc[3], ah, &bl1[2]);
        }
        __syncthreads();
    }
    (void)kh;

    float* dst = part + ((size_t)bh * 8 + split) * 4096;
    const int dr = wr * 16 + (lane >> 2);
    const int ec = wc * 32 + (lane & 3) * 2;
    #pragma unroll
    for (int nf = 0; nf < 4; nf++) {
        *(float2*)&dst[(size_t)dr * 64 + ec + nf * 8]       = make_float2(acc[nf][0], acc[nf][1]);
        *(float2*)&dst[(size_t)(dr + 8) * 64 + ec + nf * 8] = make_float2(acc[nf][2], acc[nf][3]);
    }
}

// ---------------- W2s[b][c][.] = split_bf16( ((sum dots)/n2 @ Wout)^T ) ----------------
__global__ __launch_bounds__(256) void w2k(const float* __restrict__ part, const float* __restrict__ Wout,
                                           __nv_bfloat16* __restrict__ W2s) {
    const int bh = blockIdx.x, dhalf = blockIdx.y;
    const int b = bh >> 3, h = bh & 7;
    __shared__ float ds[2048];   // [32 d_rel][64 e]
    const int tid = threadIdx.x;
    #pragma unroll
    for (int j = 0; j < 8; j++) {
        int idx = j * 256 + tid;
        int dr = idx >> 6, e = idx & 63;
        float s = 0.f;
        #pragma unroll
        for (int sp = 0; sp < 8; sp++)
            s += part[((size_t)bh * 8 + sp) * 4096 + (dhalf * 32 + dr) * 64 + e];
        ds[idx] = s * (1.f / 4096.f);
    }
    __syncthreads();

    const int p = tid & 127, g = tid >> 7;
    u64 acc[16];
    #pragma unroll
    for (int d = 0; d < 16; d++) acc[d] = 0ull;
    for (int e = 0; e < 64; e++) {
        u64 w2 = *(const u64*)&Wout[(size_t)(h * 64 + e) * 256 + 2 * p];
        const float* dsr = &ds[(g * 16) * 64 + e];
        #pragma unroll
        for (int d = 0; d < 16; d++) {
            float val = dsr[d * 64];
            acc[d] = ffma2(pack2(val, val), w2, acc[d]);
        }
    }
    #pragma unroll
    for (int d = 0; d < 16; d++) {
        float o0, o1; unpack2(acc[d], o0, o1);
        const int dg = h * 64 + dhalf * 32 + g * 16 + d;
        size_t r0 = ((size_t)b * 256 + 2 * p) * 1024;
        __nv_bfloat16 hh, ll;
        split1(o0, hh, ll);
        W2s[r0 + dg] = hh; W2s[r0 + 512 + dg] = ll;
        split1(o1, hh, ll);
        W2s[r0 + 1024 + dg] = hh; W2s[r0 + 1024 + 512 + dg] = ll;
    }
}

// ---------------- launch ----------------
extern "C" void kernel_launch(void* const* d_in, const int* in_sizes, int n_in,
                              void* d_out, int out_size) {
    const float* x     = (const float*)d_in[0];
    const float* z     = (const float*)d_in[1];
    const float* x_pos = (const float*)d_in[2];
    const float* z_pos = (const float*)d_in[3];
    const float* Wq    = (const float*)d_in[4];
    const float* Wkv   = (const float*)d_in[5];
    const float* Wout  = (const float*)d_in[6];
    const float* bout  = (const float*)d_in[7];
    float* out = (float*)d_out;

    float *kv, *dotp;
    __nv_bfloat16 *z2, *x2, *wkv2, *wq2, *q2, *w2s;
    cudaGetSymbolAddress((void**)&kv,   g_kv);
    cudaGetSymbolAddress((void**)&dotp, g_dotp);
    cudaGetSymbolAddress((void**)&z2,   g_z2);
    cudaGetSymbolAddress((void**)&x2,   g_x2);
    cudaGetSymbolAddress((void**)&wkv2, g_wkv2);
    cudaGetSymbolAddress((void**)&wq2,  g_wq2);
    cudaGetSymbolAddress((void**)&q2,   g_q2);
    cudaGetSymbolAddress((void**)&w2s,  g_w2s);

    cudaFuncSetAttribute(gemm_mma<0>, cudaFuncAttributeMaxDynamicSharedMemorySize, GSMEM);
    cudaFuncSetAttribute(gemm_mma<1>, cudaFuncAttributeMaxDynamicSharedMemorySize, GSMEM);
    cudaFuncSetAttribute(dots_fused,  cudaFuncAttributeMaxDynamicSharedMemorySize, DSM_BYTES);

    // kv chain
    split_rows<<<MTOT * 64 / 256, 256>>>(z, z2);
    split_wT<<<1024, 256>>>(Wkv, wkv2, 1024);
    gemm_mma<0><<<dim3(8, 256, 1), 256, GSMEM>>>(z2, wkv2, kv, nullptr, nullptr,
                                                 1024, 512, 0, 0, 0, nullptr);
    dots_fused<<<dim3(8, 64), 256, DSM_BYTES>>>(kv, z_pos, dotp);
    w2k<<<dim3(64, 2), 256>>>(dotp, Wout, w2s);

    // q chain (rotary + split fused into epilogue)
    split_rows<<<MTOT * 64 / 256, 256>>>(x, x2);
    split_wT<<<512, 256>>>(Wq, wq2, 512);
    gemm_mma<1><<<dim3(4, 256, 1), 256, GSMEM>>>(x2, wq2, nullptr, q2, x_pos,
                                                 512, 512, 0, 0, 0, nullptr);

    // out[b] = q2[b] @ W2s[b]^T + bout
    gemm_mma<0><<<dim3(2, 32, BATCH), 256, GSMEM>>>(
        q2, w2s, out, nullptr, nullptr, 256, 1024,
        (long)NTOKS * 1024, (long)256 * 1024, (long)NTOKS * 256, bout);
}

// round 8
// speedup vs baseline: 1.2586x; 1.2586x over previous
#include <cuda_runtime.h>
#include <cuda_bf16.h>
#include <cuda_fp16.h>
#include <math.h>
#include <cstdint>

typedef unsigned long long u64;
typedef unsigned int u32;

#define HEADS 8
#define NDIM  256
#define INNER 512
#define NTOKS 4096
#define BATCH 8
#define MTOT  (BATCH * NTOKS)   // 32768
#define RSCALE 32.f
#define RINV   0.03125f

// ---------------- scratch (device globals: allocation-guard safe) ----------------
__device__ float g_kv  [(size_t)MTOT * 1024];        // fp32 kv raw GEMM output
__device__ float g_dotp[(size_t)64 * 8 * 64 * 64];   // dots split-K partials
__device__ __half g_z2  [(size_t)MTOT * 512];        // z: [hi(256), 32*resid(256)]
__device__ __half g_x2  [(size_t)MTOT * 512];        // x: same
__device__ __half g_wkv2[(size_t)1024 * 512];        // Wkv^T: [hi(256), hi/32(256)]
__device__ __half g_wq2 [(size_t)512 * 512];         // Wq^T: same
__device__ __half g_q2  [(size_t)MTOT * 1024];       // q rot: [hi(512), 32*resid(512)]
__device__ __half g_w2s [(size_t)BATCH * 256 * 1024]; // W2^T: [hi(512), hi/32(512)]

// ---------------- sm_80-class MMA helpers (legal on plain sm_103) ----------------
__device__ __forceinline__ u32 smem_u32(const void* p) {
    u32 a; asm("{ .reg .u64 t; cvta.to.shared.u64 t, %1; cvt.u32.u64 %0, t; }" : "=r"(a) : "l"(p));
    return a;
}
__device__ __forceinline__ void cpa16(u32 dst, const void* src) {
    asm volatile("cp.async.cg.shared.global [%0], [%1], 16;" :: "r"(dst), "l"(src));
}
#define CP_COMMIT() asm volatile("cp.async.commit_group;" ::: "memory")
#define CP_WAIT(n)  asm volatile("cp.async.wait_group %0;" :: "n"(n) : "memory")

__device__ __forceinline__ void ldsm4(u32* r, u32 a) {
    asm volatile("ldmatrix.sync.aligned.m8n8.x4.shared.b16 {%0,%1,%2,%3}, [%4];"
        : "=r"(r[0]), "=r"(r[1]), "=r"(r[2]), "=r"(r[3]) : "r"(a));
}
__device__ __forceinline__ void ldsm4t(u32* r, u32 a) {
    asm volatile("ldmatrix.sync.aligned.m8n8.x4.trans.shared.b16 {%0,%1,%2,%3}, [%4];"
        : "=r"(r[0]), "=r"(r[1]), "=r"(r[2]), "=r"(r[3]) : "r"(a));
}
// fp16 MMA (fp32 acc)
__device__ __forceinline__ void mma16816h(float* c, const u32* a, const u32* b) {
    asm volatile("mma.sync.aligned.m16n8k16.row.col.f32.f16.f16.f32 "
        "{%0,%1,%2,%3}, {%4,%5,%6,%7}, {%8,%9}, {%0,%1,%2,%3};"
        : "+f"(c[0]), "+f"(c[1]), "+f"(c[2]), "+f"(c[3])
        : "r"(a[0]), "r"(a[1]), "r"(a[2]), "r"(a[3]), "r"(b[0]), "r"(b[1]));
}
// bf16 MMA (for dots)
__device__ __forceinline__ void mma16816(float* c, const u32* a, const u32* b) {
    asm volatile("mma.sync.aligned.m16n8k16.row.col.f32.bf16.bf16.f32 "
        "{%0,%1,%2,%3}, {%4,%5,%6,%7}, {%8,%9}, {%0,%1,%2,%3};"
        : "+f"(c[0]), "+f"(c[1]), "+f"(c[2]), "+f"(c[3])
        : "r"(a[0]), "r"(a[1]), "r"(a[2]), "r"(a[3]), "r"(b[0]), "r"(b[1]));
}

// ---------------- f32x2 helpers ----------------
__device__ __forceinline__ u64 pack2(float x, float y) {
    u64 r; asm("mov.b64 %0, {%1,%2};" : "=l"(r) : "f"(x), "f"(y)); return r;
}
__device__ __forceinline__ u64 ffma2(u64 a, u64 b, u64 c) {
    u64 d; asm("fma.rn.f32x2 %0, %1, %2, %3;" : "=l"(d) : "l"(a), "l"(b), "l"(c)); return d;
}
__device__ __forceinline__ void unpack2(u64 v, float& x, float& y) {
    asm("mov.b64 {%0,%1}, %2;" : "=f"(x), "=f"(y) : "l"(v));
}

// ---------------- split helpers ----------------
// data: x = h + l/32 with h=fp16(x), l=fp16(32*(x-h))
__device__ __forceinline__ void splith_data(float v, __half& h, __half& l) {
    h = __float2half_rn(v);
    l = __float2half_rn(RSCALE * (v - __half2float(h)));
}
// bf16 split (for dots kernel)
__device__ __forceinline__ void split1(float v, __nv_bfloat16& h, __nv_bfloat16& l) {
    h = __float2bfloat16(v);
    l = __float2bfloat16(v - __bfloat162float(h));
}

// in [R,256] fp32 -> out [R,512] fp16: cols [0,256)=hi, [256,512)=32*resid
__global__ void split_rows(const float* __restrict__ in, __half* __restrict__ out) {
    size_t idx = (size_t)blockIdx.x * 256 + threadIdx.x;  // one float4
    size_t row = idx >> 6; int c4 = (int)(idx & 63);
    float4 v = ((const float4*)in)[idx];
    __half h0, l0, h1, l1, h2, l2, h3, l3;
    splith_data(v.x, h0, l0); splith_data(v.y, h1, l1);
    splith_data(v.z, h2, l2); splith_data(v.w, h3, l3);
    __half* ph = out + row * 512 + c4 * 4;
    *(__half2*)(ph)     = __half2{h0, h1};
    *(__half2*)(ph + 2) = __half2{h2, h3};
    __half* pl = ph + 256;
    *(__half2*)(pl)     = __half2{l0, l1};
    *(__half2*)(pl + 2) = __half2{l2, l3};
}

// W [256, N] fp32 -> out [N, 512] fp16 (transpose): [0,256)=hi, [256,512)=hi/32
__global__ void split_wT(const float* __restrict__ W, __half* __restrict__ out, int N) {
    int n = blockIdx.x, k = threadIdx.x;
    float v = W[(size_t)k * N + n];
    __half h = __float2half_rn(v);
    __half s = __float2half_rn(__half2float(h) * RINV);
    out[(size_t)n * 512 + k]       = h;
    out[(size_t)n * 512 + 256 + k] = s;
}

// ---------------- 2-term fp16 HMMA GEMM: C[M,N] = A2[M,K2] x B2[N,K2]^T ----------------
// Planes are pre-aligned (A: [hi, 32*resid], B: [hi, hi/32]) so this is a plain GEMM.
#define ROWB 80                  // 32 fp16 + 16B pad
#define TILEB (128 * ROWB)       // 10240
#define STAGEB (2 * TILEB)       // 20480 (A + B)
#define NSTAGE 4
#define GSMEM (NSTAGE * STAGEB)  // 81920

template <int MODE>
__global__ __launch_bounds__(256, 2) void gemm_mma(
    const __half* __restrict__ A2, const __half* __restrict__ B2,
    float* __restrict__ C, __half* __restrict__ Cq,
    const float* __restrict__ pos, int N, int K2,
    long sA, long sB, long sC, const float* __restrict__ bias)
{
    extern __shared__ __align__(1024) char smem[];
    A2 += (size_t)blockIdx.z * sA;
    B2 += (size_t)blockIdx.z * sB;
    if (MODE == 0) C += (size_t)blockIdx.z * sC;
    const int m0 = blockIdx.y * 128, n0 = blockIdx.x * 128;
    const int tid = threadIdx.x, lane = tid & 31, wid = tid >> 5;
    const int wr = wid >> 2, wc = wid & 3;
    const u32 sb = smem_u32(smem);

    const int total = K2 >> 5;       // 32-wide chunks over full split depth
    const int lrow = tid >> 1;
    const int lcg = (tid & 1) * 2;

    float acc[4][4][4];
    #pragma unroll
    for (int i = 0; i < 4; i++)
        #pragma unroll
        for (int j = 0; j < 4; j++)
            #pragma unroll
            for (int r = 0; r < 4; r++) acc[i][j][r] = 0.f;

    auto issue = [&](int it) {
        const int stage = it & (NSTAGE - 1);
        const int kk = it * 32;
        const __half* as = A2 + (size_t)(m0 + lrow) * K2 + kk + lcg * 8;
        const __half* bs = B2 + (size_t)(n0 + lrow) * K2 + kk + lcg * 8;
        const u32 da = sb + stage * STAGEB + lrow * ROWB + lcg * 16;
        cpa16(da, as);              cpa16(da + 16, as + 8);
        cpa16(da + TILEB, bs);      cpa16(da + TILEB + 16, bs + 8);
        CP_COMMIT();
    };

    auto compute = [&](int stage) {
        const u32 ab = sb + stage * STAGEB;
        const u32 bb = ab + TILEB;
        #pragma unroll
        for (int kb = 0; kb < 2; kb++) {
            u32 a[4][4], b[2][4];
            #pragma unroll
            for (int mf = 0; mf < 4; mf++) {
                u32 addr = ab + (u32)(wr * 64 + mf * 16 + (lane & 15)) * ROWB
                              + kb * 32 + (lane >> 4) * 16;
                ldsm4(a[mf], addr);
            }
            #pragma unroll
            for (int nfp = 0; nfp < 2; nfp++) {
                u32 addr = bb + (u32)(wc * 32 + nfp * 16 + ((lane >> 4) << 3) + (lane & 7)) * ROWB
                              + kb * 32 + ((lane >> 3) & 1) * 16;
                ldsm4(b[nfp], addr);
            }
            #pragma unroll
            for (int mf = 0; mf < 4; mf++)
                #pragma unroll
                for (int nf = 0; nf < 4; nf++)
                    mma16816h(acc[mf][nf], a[mf], &b[nf >> 1][(nf & 1) * 2]);
        }
    };

    issue(0); issue(1); issue(2);
    for (int i = 0; i < total; i++) {
        if (i < total - 2)       CP_WAIT(2);
        else if (i == total - 2) CP_WAIT(1);
        else                     CP_WAIT(0);
        __syncthreads();
        compute(i & (NSTAGE - 1));
        if (i + 3 < total) issue(i + 3);
    }

    if (MODE == 0) {
        const int rbase = m0 + wr * 64 + (lane >> 2);
        const int cbase = n0 + wc * 32 + (lane & 3) * 2;
        #pragma unroll
        for (int nf = 0; nf < 4; nf++) {
            const int c = cbase + nf * 8;
            float bx = 0.f, by = 0.f;
            if (bias) { bx = bias[c]; by = bias[c + 1]; }
            #pragma unroll
            for (int mf = 0; mf < 4; mf++) {
                const int r = rbase + mf * 16;
                *(float2*)&C[(size_t)r * N + c] =
                    make_float2(acc[mf][nf][0] + bx, acc[mf][nf][1] + by);
                *(float2*)&C[(size_t)(r + 8) * N + c] =
                    make_float2(acc[mf][nf][2] + bx, acc[mf][nf][3] + by);
            }
        }
    } else {
        // rotary + fp16 2-term split store: Cq [M, 2N], planes [hi(N), 32*resid(N)]
        const int half = wc & 1;
        const int lq = lane & 3;
        #pragma unroll
        for (int mf = 0; mf < 4; mf++) {
            #pragma unroll
            for (int rb = 0; rb < 2; rb++) {
                const int r = m0 + wr * 64 + mf * 16 + (lane >> 2) + rb * 8;
                const float pp = pos[(size_t)r * 2 + half] * 64.f;
                const size_t rowb = (size_t)r * (2 * N);
                #pragma unroll
                for (int nf2 = 0; nf2 < 2; nf2++) {
                    float o[4];
                    #pragma unroll
                    for (int cb = 0; cb < 2; cb++) {
                        const int j = nf2 * 8 + lq * 2 + cb;
                        const float invf = exp2f(-(float)j * (13.287712379549449f / 16.f));
                        float s, co; sincosf(pp * invf, &s, &co);
                        const int idx = rb * 2 + cb;
                        const float vlo = acc[mf][nf2][idx];
                        const float vhi = acc[mf][nf2 + 2][idx];
                        o[cb]     = vlo * co - vhi * s;
                        o[2 + cb] = vhi * co + vlo * s;
                    }
                    const int cg = n0 + wc * 32 + nf2 * 8 + lq * 2;
                    __half h0, l0, h1, l1;
                    splith_data(o[0], h0, l0); splith_data(o[1], h1, l1);
                    *(__half2*)&Cq[rowb + cg]     = __half2{h0, h1};
                    *(__half2*)&Cq[rowb + N + cg] = __half2{l0, l1};
                    splith_data(o[2], h0, l0); splith_data(o[3], h1, l1);
                    *(__half2*)&Cq[rowb + cg + 16]     = __half2{h0, h1};
                    *(__half2*)&Cq[rowb + N + cg + 16] = __half2{l0, l1};
                }
            }
        }
    }
}

// ---------------- rotary helper ----------------
__device__ __forceinline__ void warp_rot(float& v0, float& v1, int l, float px, float py) {
    const int j = l & 15;
    const float invf = exp2f(-(float)j * (13.287712379549449f / 16.f));
    float sx, cx, sy, cy;
    sincosf(px * invf, &sx, &cx);
    sincosf(py * invf, &sy, &cy);
    float p0 = __shfl_xor_sync(0xffffffffu, v0, 16);
    float p1 = __shfl_xor_sync(0xffffffffu, v1, 16);
    if (l < 16) { v0 = v0 * cx - p0 * sx; v1 = v1 * cy - p1 * sy; }
    else        { v0 = v0 * cx + p0 * sx; v1 = v1 * cy + p1 * sy; }
}

// ---------------- fused norm+rotary+Gram split-K (bf16 3-term, unchanged) ----------------
#define DROWB 144
#define DTILE (64 * DROWB)       // 9216
#define DSM_BYTES (4 * DTILE)    // 36864

__global__ __launch_bounds__(256, 3) void dots_fused(const float* __restrict__ kv,
                                                     const float* __restrict__ z_pos,
                                                     float* __restrict__ part) {
    extern __shared__ __align__(1024) char dsm[];
    const u32 khb = smem_u32(dsm);
    const u32 klb = khb + DTILE;
    const u32 vhb = khb + 2 * DTILE;
    const u32 vlb = khb + 3 * DTILE;

    const int split = blockIdx.x;
    const int bh = blockIdx.y;
    const int b = bh >> 3, h = bh & 7;
    const int tid = threadIdx.x;
    const int w = tid >> 5, lane = tid & 31;
    const int wr = w >> 1, wc = w & 1;
    const float* kvb = kv + (size_t)b * NTOKS * 1024 + h * 64;

    float acc[4][4];
    #pragma unroll
    for (int i = 0; i < 4; i++)
        #pragma unroll
        for (int j = 0; j < 4; j++) acc[i][j] = 0.f;

    for (int c = 0; c < 8; c++) {
        const int t0 = split * 512 + c * 64;
        #pragma unroll
        for (int s = 0; s < 8; s++) {
            const int t = s * 8 + w;
            const float* row = kvb + (size_t)(t0 + t) * 1024;
            float k0 = row[lane],       k1 = row[lane + 32];
            float v0 = row[512 + lane], v1 = row[512 + lane + 32];
            float rs0 = k0 + k1, rs1 = k0 * k0 + k1 * k1;
            float rs2 = v0 + v1, rs3 = v0 * v0 + v1 * v1;
            #pragma unroll
            for (int o = 16; o; o >>= 1) {
                rs0 += __shfl_xor_sync(0xffffffffu, rs0, o);
                rs1 += __shfl_xor_sync(0xffffffffu, rs1, o);
                rs2 += __shfl_xor_sync(0xffffffffu, rs2, o);
                rs3 += __shfl_xor_sync(0xffffffffu, rs3, o);
            }
            const float muk = rs0 * (1.f / 64.f);
            const float invk = rsqrtf(fmaxf(rs1 * (1.f / 64.f) - muk * muk, 0.f) + 1e-5f);
            const float muv = rs2 * (1.f / 64.f);
            const float invv = rsqrtf(fmaxf(rs3 * (1.f / 64.f) - muv * muv, 0.f) + 1e-5f);
            float d0 = (k0 - muk) * invk, d1 = (k1 - muk) * invk;
            float e0 = (v0 - muv) * invv, e1 = (v1 - muv) * invv;
            const size_t tg = (size_t)b * NTOKS + t0 + t;
            const float px = z_pos[tg * 2 + 0] * 64.f;
            const float py = z_pos[tg * 2 + 1] * 64.f;
            warp_rot(d0, d1, lane, px, py);
            __nv_bfloat16 hh, ll;
            const u32 ro = (u32)t * DROWB + lane * 2;
            split1(d0, hh, ll);
            *(__nv_bfloat16*)(dsm + (ro))              = hh;
            *(__nv_bfloat16*)(dsm + DTILE + ro)        = ll;
            split1(d1, hh, ll);
            *(__nv_bfloat16*)(dsm + ro + 64)           = hh;
            *(__nv_bfloat16*)(dsm + DTILE + ro + 64)   = ll;
            split1(e0, hh, ll);
            *(__nv_bfloat16*)(dsm + 2 * DTILE + ro)      = hh;
            *(__nv_bfloat16*)(dsm + 3 * DTILE + ro)      = ll;
            split1(e1, hh, ll);
            *(__nv_bfloat16*)(dsm + 2 * DTILE + ro + 64) = hh;
            *(__nv_bfloat16*)(dsm + 3 * DTILE + ro + 64) = ll;
        }
        __syncthreads();
        #pragma unroll
        for (int kt = 0; kt < 4; kt++) {
            const u32 arow = (u32)(kt * 16 + (lane & 7) + ((lane >> 4) << 3));
            const u32 acol = (u32)(wr * 16 + ((lane >> 3) & 1) * 8);
            const u32 aoff = arow * DROWB + acol * 2;
            u32 ah[4], al[4];
            ldsm4t(ah, khb + aoff);
            ldsm4t(al, klb + aoff);
            const u32 brow = (u32)(kt * 16 + (lane & 7) + ((lane >> 3) & 1) * 8);
            const u32 bcol = (u32)(wc * 32 + ((lane >> 4) << 3));
            const u32 boff = brow * DROWB + bcol * 2;
            u32 bh0[4], bl0[4], bh1[4], bl1[4];
            ldsm4t(bh0, vhb + boff);
            ldsm4t(bl0, vlb + boff);
            ldsm4t(bh1, vhb + boff + 32);
            ldsm4t(bl1, vlb + boff + 32);
            mma16816(acc[0], ah, &bh0[0]); mma16816(acc[0], al, &bh0[0]); mma16816(acc[0], ah, &bl0[0]);
            mma16816(acc[1], ah, &bh0[2]); mma16816(acc[1], al, &bh0[2]); mma16816(acc[1], ah, &bl0[2]);
            mma16816(acc[2], ah, &bh1[0]); mma16816(acc[2], al, &bh1[0]); mma16816(acc[2], ah, &bl1[0]);
            mma16816(acc[3], ah, &bh1[2]); mma16816(acc[3], al, &bh1[2]); mma16816(acc[3], ah, &bl1[2]);
        }
        __syncthreads();
    }

    float* dst = part + ((size_t)bh * 8 + split) * 4096;
    const int dr = wr * 16 + (lane >> 2);
    const int ec = wc * 32 + (lane & 3) * 2;
    #pragma unroll
    for (int nf = 0; nf < 4; nf++) {
        *(float2*)&dst[(size_t)dr * 64 + ec + nf * 8]       = make_float2(acc[nf][0], acc[nf][1]);
        *(float2*)&dst[(size_t)(dr + 8) * 64 + ec + nf * 8] = make_float2(acc[nf][2], acc[nf][3]);
    }
}

// ---------------- W2s[b][c][.] = fp16_2term( ((sum dots)/n2 @ Wout)^T ) ----------------
__global__ __launch_bounds__(256) void w2k(const float* __restrict__ part, const float* __restrict__ Wout,
                                           __half* __restrict__ W2s) {
    const int bh = blockIdx.x, dhalf = blockIdx.y;
    const int b = bh >> 3, h = bh & 7;
    __shared__ float ds[2048];   // [32 d_rel][64 e]
    const int tid = threadIdx.x;
    #pragma unroll
    for (int j = 0; j < 8; j++) {
        int idx = j * 256 + tid;
        int dr = idx >> 6, e = idx & 63;
        float s = 0.f;
        #pragma unroll
        for (int sp = 0; sp < 8; sp++)
            s += part[((size_t)bh * 8 + sp) * 4096 + (dhalf * 32 + dr) * 64 + e];
        ds[idx] = s * (1.f / 4096.f);
    }
    __syncthreads();

    const int p = tid & 127, g = tid >> 7;
    u64 acc[16];
    #pragma unroll
    for (int d = 0; d < 16; d++) acc[d] = 0ull;
    for (int e = 0; e < 64; e++) {
        u64 w2 = *(const u64*)&Wout[(size_t)(h * 64 + e) * 256 + 2 * p];
        const float* dsr = &ds[(g * 16) * 64 + e];
        #pragma unroll
        for (int d = 0; d < 16; d++) {
            float val = dsr[d * 64];
            acc[d] = ffma2(pack2(val, val), w2, acc[d]);
        }
    }
    #pragma unroll
    for (int d = 0; d < 16; d++) {
        float o0, o1; unpack2(acc[d], o0, o1);
        const int dg = h * 64 + dhalf * 32 + g * 16 + d;
        size_t r0 = ((size_t)b * 256 + 2 * p) * 1024;
        __half hh = __float2half_rn(o0);
        W2s[r0 + dg]       = hh;
        W2s[r0 + 512 + dg] = __float2half_rn(__half2float(hh) * RINV);
        hh = __float2half_rn(o1);
        W2s[r0 + 1024 + dg]       = hh;
        W2s[r0 + 1024 + 512 + dg] = __float2half_rn(__half2float(hh) * RINV);
    }
}

// ---------------- launch ----------------
extern "C" void kernel_launch(void* const* d_in, const int* in_sizes, int n_in,
                              void* d_out, int out_size) {
    const float* x     = (const float*)d_in[0];
    const float* z     = (const float*)d_in[1];
    const float* x_pos = (const float*)d_in[2];
    const float* z_pos = (const float*)d_in[3];
    const float* Wq    = (const float*)d_in[4];
    const float* Wkv   = (const float*)d_in[5];
    const float* Wout  = (const float*)d_in[6];
    const float* bout  = (const float*)d_in[7];
    float* out = (float*)d_out;

    float *kv, *dotp;
    __half *z2, *x2, *wkv2, *wq2, *q2, *w2s;
    cudaGetSymbolAddress((void**)&kv,   g_kv);
    cudaGetSymbolAddress((void**)&dotp, g_dotp);
    cudaGetSymbolAddress((void**)&z2,   g_z2);
    cudaGetSymbolAddress((void**)&x2,   g_x2);
    cudaGetSymbolAddress((void**)&wkv2, g_wkv2);
    cudaGetSymbolAddress((void**)&wq2,  g_wq2);
    cudaGetSymbolAddress((void**)&q2,   g_q2);
    cudaGetSymbolAddress((void**)&w2s,  g_w2s);

    cudaFuncSetAttribute(gemm_mma<0>, cudaFuncAttributeMaxDynamicSharedMemorySize, GSMEM);
    cudaFuncSetAttribute(gemm_mma<1>, cudaFuncAttributeMaxDynamicSharedMemorySize, GSMEM);
    cudaFuncSetAttribute(dots_fused,  cudaFuncAttributeMaxDynamicSharedMemorySize, DSM_BYTES);

    // kv chain
    split_rows<<<MTOT * 64 / 256, 256>>>(z, z2);
    split_wT<<<1024, 256>>>(Wkv, wkv2, 1024);
    gemm_mma<0><<<dim3(8, 256, 1), 256, GSMEM>>>(z2, wkv2, kv, nullptr, nullptr,
                                                 1024, 512, 0, 0, 0, nullptr);
    dots_fused<<<dim3(8, 64), 256, DSM_BYTES>>>(kv, z_pos, dotp);
    w2k<<<dim3(64, 2), 256>>>(dotp, Wout, w2s);

    // q chain (rotary + fp16 split fused into epilogue)
    split_rows<<<MTOT * 64 / 256, 256>>>(x, x2);
    split_wT<<<512, 256>>>(Wq, wq2, 512);
    gemm_mma<1><<<dim3(4, 256, 1), 256, GSMEM>>>(x2, wq2, nullptr, q2, x_pos,
                                                 512, 512, 0, 0, 0, nullptr);

    // out[b] = q2[b] @ W2s[b]^T + bout
    gemm_mma<0><<<dim3(2, 32, BATCH), 256, GSMEM>>>(
        q2, w2s, out, nullptr, nullptr, 256, 1024,
        (long)NTOKS * 1024, (long)256 * 1024, (long)NTOKS * 256, bout);
}

// round 9
// speedup vs baseline: 1.3560x; 1.0774x over previous
#include <cuda_runtime.h>
#include <cuda_bf16.h>
#include <cuda_fp16.h>
#include <math.h>
#include <cstdint>

typedef unsigned long long u64;
typedef unsigned int u32;

#define HEADS 8
#define NDIM  256
#define INNER 512
#define NTOKS 4096
#define BATCH 8
#define MTOT  (BATCH * NTOKS)   // 32768
#define RSCALE 32.f
#define RINV   0.03125f
#define NSPLIT 16

// ---------------- scratch (device globals: allocation-guard safe) ----------------
__device__ float g_kv  [(size_t)MTOT * 1024];        // fp32 kv raw GEMM output
__device__ float g_dotp[(size_t)64 * NSPLIT * 64 * 64]; // dots split-K partials
__device__ __half g_z2  [(size_t)MTOT * 512];        // z: [hi(256), 32*resid(256)]
__device__ __half g_x2  [(size_t)MTOT * 512];        // x: same
__device__ __half g_wkv2[(size_t)1024 * 512];        // Wkv^T: [hi(256), hi/32(256)]
__device__ __half g_wq2 [(size_t)512 * 512];         // Wq^T: same
__device__ __half g_q2  [(size_t)MTOT * 1024];       // q rot: [hi(512), 32*resid(512)]
__device__ __half g_w2s [(size_t)BATCH * 256 * 1024]; // W2^T: [hi(512), hi/32(512)]

// ---------------- sm_80-class MMA helpers (legal on plain sm_103) ----------------
__device__ __forceinline__ u32 smem_u32(const void* p) {
    u32 a; asm("{ .reg .u64 t; cvta.to.shared.u64 t, %1; cvt.u32.u64 %0, t; }" : "=r"(a) : "l"(p));
    return a;
}
__device__ __forceinline__ void cpa16(u32 dst, const void* src) {
    asm volatile("cp.async.cg.shared.global [%0], [%1], 16;" :: "r"(dst), "l"(src));
}
#define CP_COMMIT() asm volatile("cp.async.commit_group;" ::: "memory")
#define CP_WAIT(n)  asm volatile("cp.async.wait_group %0;" :: "n"(n) : "memory")

__device__ __forceinline__ void ldsm4(u32* r, u32 a) {
    asm volatile("ldmatrix.sync.aligned.m8n8.x4.shared.b16 {%0,%1,%2,%3}, [%4];"
        : "=r"(r[0]), "=r"(r[1]), "=r"(r[2]), "=r"(r[3]) : "r"(a));
}
__device__ __forceinline__ void ldsm4t(u32* r, u32 a) {
    asm volatile("ldmatrix.sync.aligned.m8n8.x4.trans.shared.b16 {%0,%1,%2,%3}, [%4];"
        : "=r"(r[0]), "=r"(r[1]), "=r"(r[2]), "=r"(r[3]) : "r"(a));
}
// fp16 MMA (fp32 acc)
__device__ __forceinline__ void mma16816h(float* c, const u32* a, const u32* b) {
    asm volatile("mma.sync.aligned.m16n8k16.row.col.f32.f16.f16.f32 "
        "{%0,%1,%2,%3}, {%4,%5,%6,%7}, {%8,%9}, {%0,%1,%2,%3};"
        : "+f"(c[0]), "+f"(c[1]), "+f"(c[2]), "+f"(c[3])
        : "r"(a[0]), "r"(a[1]), "r"(a[2]), "r"(a[3]), "r"(b[0]), "r"(b[1]));
}
// bf16 MMA (for dots)
__device__ __forceinline__ void mma16816(float* c, const u32* a, const u32* b) {
    asm volatile("mma.sync.aligned.m16n8k16.row.col.f32.bf16.bf16.f32 "
        "{%0,%1,%2,%3}, {%4,%5,%6,%7}, {%8,%9}, {%0,%1,%2,%3};"
        : "+f"(c[0]), "+f"(c[1]), "+f"(c[2]), "+f"(c[3])
        : "r"(a[0]), "r"(a[1]), "r"(a[2]), "r"(a[3]), "r"(b[0]), "r"(b[1]));
}

// ---------------- f32x2 helpers ----------------
__device__ __forceinline__ u64 pack2(float x, float y) {
    u64 r; asm("mov.b64 %0, {%1,%2};" : "=l"(r) : "f"(x), "f"(y)); return r;
}
__device__ __forceinline__ u64 ffma2(u64 a, u64 b, u64 c) {
    u64 d; asm("fma.rn.f32x2 %0, %1, %2, %3;" : "=l"(d) : "l"(a), "l"(b), "l"(c)); return d;
}
__device__ __forceinline__ void unpack2(u64 v, float& x, float& y) {
    asm("mov.b64 {%0,%1}, %2;" : "=f"(x), "=f"(y) : "l"(v));
}

// ---------------- split helpers ----------------
__device__ __forceinline__ void splith_data(float v, __half& h, __half& l) {
    h = __float2half_rn(v);
    l = __float2half_rn(RSCALE * (v - __half2float(h)));
}
__device__ __forceinline__ void split1(float v, __nv_bfloat16& h, __nv_bfloat16& l) {
    h = __float2bfloat16(v);
    l = __float2bfloat16(v - __bfloat162float(h));
}

// in [R,256] fp32 -> out [R,512] fp16: cols [0,256)=hi, [256,512)=32*resid
__global__ void split_rows(const float* __restrict__ in, __half* __restrict__ out) {
    size_t idx = (size_t)blockIdx.x * 256 + threadIdx.x;  // one float4
    size_t row = idx >> 6; int c4 = (int)(idx & 63);
    float4 v = ((const float4*)in)[idx];
    __half h0, l0, h1, l1, h2, l2, h3, l3;
    splith_data(v.x, h0, l0); splith_data(v.y, h1, l1);
    splith_data(v.z, h2, l2); splith_data(v.w, h3, l3);
    __half* ph = out + row * 512 + c4 * 4;
    *(__half2*)(ph)     = __half2{h0, h1};
    *(__half2*)(ph + 2) = __half2{h2, h3};
    __half* pl = ph + 256;
    *(__half2*)(pl)     = __half2{l0, l1};
    *(__half2*)(pl + 2) = __half2{l2, l3};
}

// W [256, N] fp32 -> out [N, 512] fp16 (transpose): [0,256)=hi, [256,512)=hi/32
__global__ void split_wT(const float* __restrict__ W, __half* __restrict__ out, int N) {
    int n = blockIdx.x, k = threadIdx.x;
    float v = W[(size_t)k * N + n];
    __half h = __float2half_rn(v);
    __half s = __float2half_rn(__half2float(h) * RINV);
    out[(size_t)n * 512 + k]       = h;
    out[(size_t)n * 512 + 256 + k] = s;
}

// ---------------- 2-term fp16 HMMA GEMM (unchanged from round 8) ----------------
#define ROWB 80
#define TILEB (128 * ROWB)
#define STAGEB (2 * TILEB)
#define NSTAGE 4
#define GSMEM (NSTAGE * STAGEB)

template <int MODE>
__global__ __launch_bounds__(256, 2) void gemm_mma(
    const __half* __restrict__ A2, const __half* __restrict__ B2,
    float* __restrict__ C, __half* __restrict__ Cq,
    const float* __restrict__ pos, int N, int K2,
    long sA, long sB, long sC, const float* __restrict__ bias)
{
    extern __shared__ __align__(1024) char smem[];
    A2 += (size_t)blockIdx.z * sA;
    B2 += (size_t)blockIdx.z * sB;
    if (MODE == 0) C += (size_t)blockIdx.z * sC;
    const int m0 = blockIdx.y * 128, n0 = blockIdx.x * 128;
    const int tid = threadIdx.x, lane = tid & 31, wid = tid >> 5;
    const int wr = wid >> 2, wc = wid & 3;
    const u32 sb = smem_u32(smem);

    const int total = K2 >> 5;
    const int lrow = tid >> 1;
    const int lcg = (tid & 1) * 2;

    float acc[4][4][4];
    #pragma unroll
    for (int i = 0; i < 4; i++)
        #pragma unroll
        for (int j = 0; j < 4; j++)
            #pragma unroll
            for (int r = 0; r < 4; r++) acc[i][j][r] = 0.f;

    auto issue = [&](int it) {
        const int stage = it & (NSTAGE - 1);
        const int kk = it * 32;
        const __half* as = A2 + (size_t)(m0 + lrow) * K2 + kk + lcg * 8;
        const __half* bs = B2 + (size_t)(n0 + lrow) * K2 + kk + lcg * 8;
        const u32 da = sb + stage * STAGEB + lrow * ROWB + lcg * 16;
        cpa16(da, as);              cpa16(da + 16, as + 8);
        cpa16(da + TILEB, bs);      cpa16(da + TILEB + 16, bs + 8);
        CP_COMMIT();
    };

    auto compute = [&](int stage) {
        const u32 ab = sb + stage * STAGEB;
        const u32 bb = ab + TILEB;
        #pragma unroll
        for (int kb = 0; kb < 2; kb++) {
            u32 a[4][4], b[2][4];
            #pragma unroll
            for (int mf = 0; mf < 4; mf++) {
                u32 addr = ab + (u32)(wr * 64 + mf * 16 + (lane & 15)) * ROWB
                              + kb * 32 + (lane >> 4) * 16;
                ldsm4(a[mf], addr);
            }
            #pragma unroll
            for (int nfp = 0; nfp < 2; nfp++) {
                u32 addr = bb + (u32)(wc * 32 + nfp * 16 + ((lane >> 4) << 3) + (lane & 7)) * ROWB
                              + kb * 32 + ((lane >> 3) & 1) * 16;
                ldsm4(b[nfp], addr);
            }
            #pragma unroll
            for (int mf = 0; mf < 4; mf++)
                #pragma unroll
                for (int nf = 0; nf < 4; nf++)
                    mma16816h(acc[mf][nf], a[mf], &b[nf >> 1][(nf & 1) * 2]);
        }
    };

    issue(0); issue(1); issue(2);
    for (int i = 0; i < total; i++) {
        if (i < total - 2)       CP_WAIT(2);
        else if (i == total - 2) CP_WAIT(1);
        else                     CP_WAIT(0);
        __syncthreads();
        compute(i & (NSTAGE - 1));
        if (i + 3 < total) issue(i + 3);
    }

    if (MODE == 0) {
        const int rbase = m0 + wr * 64 + (lane >> 2);
        const int cbase = n0 + wc * 32 + (lane & 3) * 2;
        #pragma unroll
        for (int nf = 0; nf < 4; nf++) {
            const int c = cbase + nf * 8;
            float bx = 0.f, by = 0.f;
            if (bias) { bx = bias[c]; by = bias[c + 1]; }
            #pragma unroll
            for (int mf = 0; mf < 4; mf++) {
                const int r = rbase + mf * 16;
                *(float2*)&C[(size_t)r * N + c] =
                    make_float2(acc[mf][nf][0] + bx, acc[mf][nf][1] + by);
                *(float2*)&C[(size_t)(r + 8) * N + c] =
                    make_float2(acc[mf][nf][2] + bx, acc[mf][nf][3] + by);
            }
        }
    } else {
        const int half = wc & 1;
        const int lq = lane & 3;
        #pragma unroll
        for (int mf = 0; mf < 4; mf++) {
            #pragma unroll
            for (int rb = 0; rb < 2; rb++) {
                const int r = m0 + wr * 64 + mf * 16 + (lane >> 2) + rb * 8;
                const float pp = pos[(size_t)r * 2 + half] * 64.f;
                const size_t rowb = (size_t)r * (2 * N);
                #pragma unroll
                for (int nf2 = 0; nf2 < 2; nf2++) {
                    float o[4];
                    #pragma unroll
                    for (int cb = 0; cb < 2; cb++) {
                        const int j = nf2 * 8 + lq * 2 + cb;
                        const float invf = exp2f(-(float)j * (13.287712379549449f / 16.f));
                        float s, co; sincosf(pp * invf, &s, &co);
                        const int idx = rb * 2 + cb;
                        const float vlo = acc[mf][nf2][idx];
                        const float vhi = acc[mf][nf2 + 2][idx];
                        o[cb]     = vlo * co - vhi * s;
                        o[2 + cb] = vhi * co + vlo * s;
                    }
                    const int cg = n0 + wc * 32 + nf2 * 8 + lq * 2;
                    __half h0, l0, h1, l1;
                    splith_data(o[0], h0, l0); splith_data(o[1], h1, l1);
                    *(__half2*)&Cq[rowb + cg]     = __half2{h0, h1};
                    *(__half2*)&Cq[rowb + N + cg] = __half2{l0, l1};
                    splith_data(o[2], h0, l0); splith_data(o[3], h1, l1);
                    *(__half2*)&Cq[rowb + cg + 16]     = __half2{h0, h1};
                    *(__half2*)&Cq[rowb + N + cg + 16] = __half2{l0, l1};
                }
            }
        }
    }
}

// ---------------- rotary helper ----------------
__device__ __forceinline__ void warp_rot(float& v0, float& v1, int l, float px, float py) {
    const int j = l & 15;
    const float invf = exp2f(-(float)j * (13.287712379549449f / 16.f));
    float sx, cx, sy, cy;
    sincosf(px * invf, &sx, &cx);
    sincosf(py * invf, &sy, &cy);
    float p0 = __shfl_xor_sync(0xffffffffu, v0, 16);
    float p1 = __shfl_xor_sync(0xffffffffu, v1, 16);
    if (l < 16) { v0 = v0 * cx - p0 * sx; v1 = v1 * cy - p1 * sy; }
    else        { v0 = v0 * cx + p0 * sx; v1 = v1 * cy + p1 * sy; }
}

// ---------------- fused norm+rotary+Gram, cp.async staged, 16 splits ----------------
// smem: 2 stage buffers (64 tok x 512B) + 4 bf16 tiles [64][72]
#define DSTG 32768               // one stage buffer
#define DROWB 144
#define DTILE (64 * DROWB)       // 9216
#define DTOFF (2 * DSTG)         // 65536
#define DSM_BYTES (DTOFF + 4 * DTILE)  // 102400

__global__ __launch_bounds__(256, 2) void dots_fused(const float* __restrict__ kv,
                                                     const float* __restrict__ z_pos,
                                                     float* __restrict__ part) {
    extern __shared__ __align__(1024) char dsm[];
    const u32 sb = smem_u32(dsm);
    const u32 khb = sb + DTOFF;
    const u32 klb = khb + DTILE;
    const u32 vhb = khb + 2 * DTILE;
    const u32 vlb = khb + 3 * DTILE;
    char* tiles = dsm + DTOFF;

    const int split = blockIdx.x;   // 0..15
    const int bh = blockIdx.y;      // 0..63
    const int b = bh >> 3, h = bh & 7;
    const int tid = threadIdx.x;
    const int w = tid >> 5, lane = tid & 31;
    const int wr = w >> 1, wc = w & 1;
    const float* kvb = kv + (size_t)b * NTOKS * 1024 + h * 64;

    float acc[4][4];
    #pragma unroll
    for (int i = 0; i < 4; i++)
        #pragma unroll
        for (int j = 0; j < 4; j++) acc[i][j] = 0.f;

    auto issue = [&](int c) {
        const int t0 = split * 256 + c * 64;
        const u32 sbase = sb + (c & 1) * DSTG;
        #pragma unroll
        for (int i = 0; i < 8; i++) {
            const int idx = i * 256 + tid;
            const int token = idx >> 5;
            const int seg = idx & 31;
            const int isv = seg >> 4, s16 = seg & 15;
            const float* src = kvb + (size_t)(t0 + token) * 1024 + isv * 512 + s16 * 4;
            cpa16(sbase + token * 512 + isv * 256 + s16 * 16, src);
        }
        CP_COMMIT();
    };

    issue(0);
    for (int c = 0; c < 4; c++) {
        if (c < 3) { issue(c + 1); CP_WAIT(1); } else { CP_WAIT(0); }
        __syncthreads();
        const float* srow = (const float*)(dsm + (c & 1) * DSTG);
        const int t0 = split * 256 + c * 64;
        #pragma unroll
        for (int s = 0; s < 8; s++) {
            const int t = s * 8 + w;
            const float* row = srow + t * 128;     // [k(64), v(64)]
            float k0 = row[lane],      k1 = row[lane + 32];
            float v0 = row[64 + lane], v1 = row[64 + lane + 32];
            float rs0 = k0 + k1, rs1 = k0 * k0 + k1 * k1;
            float rs2 = v0 + v1, rs3 = v0 * v0 + v1 * v1;
            #pragma unroll
            for (int o = 16; o; o >>= 1) {
                rs0 += __shfl_xor_sync(0xffffffffu, rs0, o);
                rs1 += __shfl_xor_sync(0xffffffffu, rs1, o);
                rs2 += __shfl_xor_sync(0xffffffffu, rs2, o);
                rs3 += __shfl_xor_sync(0xffffffffu, rs3, o);
            }
            const float muk = rs0 * (1.f / 64.f);
            const float invk = rsqrtf(fmaxf(rs1 * (1.f / 64.f) - muk * muk, 0.f) + 1e-5f);
            const float muv = rs2 * (1.f / 64.f);
            const float invv = rsqrtf(fmaxf(rs3 * (1.f / 64.f) - muv * muv, 0.f) + 1e-5f);
            float d0 = (k0 - muk) * invk, d1 = (k1 - muk) * invk;
            float e0 = (v0 - muv) * invv, e1 = (v1 - muv) * invv;
            const size_t tg = (size_t)b * NTOKS + t0 + t;
            const float px = z_pos[tg * 2 + 0] * 64.f;
            const float py = z_pos[tg * 2 + 1] * 64.f;
            warp_rot(d0, d1, lane, px, py);
            __nv_bfloat16 hh, ll;
            const u32 ro = (u32)t * DROWB + lane * 2;
            split1(d0, hh, ll);
            *(__nv_bfloat16*)(tiles + ro)              = hh;
            *(__nv_bfloat16*)(tiles + DTILE + ro)      = ll;
            split1(d1, hh, ll);
            *(__nv_bfloat16*)(tiles + ro + 64)         = hh;
            *(__nv_bfloat16*)(tiles + DTILE + ro + 64) = ll;
            split1(e0, hh, ll);
            *(__nv_bfloat16*)(tiles + 2 * DTILE + ro)      = hh;
            *(__nv_bfloat16*)(tiles + 3 * DTILE + ro)      = ll;
            split1(e1, hh, ll);
            *(__nv_bfloat16*)(tiles + 2 * DTILE + ro + 64) = hh;
            *(__nv_bfloat16*)(tiles + 3 * DTILE + ro + 64) = ll;
        }
        __syncthreads();
        #pragma unroll
        for (int kt = 0; kt < 4; kt++) {
            const u32 arow = (u32)(kt * 16 + (lane & 7) + ((lane >> 4) << 3));
            const u32 acol = (u32)(wr * 16 + ((lane >> 3) & 1) * 8);
            const u32 aoff = arow * DROWB + acol * 2;
            u32 ah[4], al[4];
            ldsm4t(ah, khb + aoff);
            ldsm4t(al, klb + aoff);
            const u32 brow = (u32)(kt * 16 + (lane & 7) + ((lane >> 3) & 1) * 8);
            const u32 bcol = (u32)(wc * 32 + ((lane >> 4) << 3));
            const u32 boff = brow * DROWB + bcol * 2;
            u32 bh0[4], bl0[4], bh1[4], bl1[4];
            ldsm4t(bh0, vhb + boff);
            ldsm4t(bl0, vlb + boff);
            ldsm4t(bh1, vhb + boff + 32);
            ldsm4t(bl1, vlb + boff + 32);
            mma16816(acc[0], ah, &bh0[0]); mma16816(acc[0], al, &bh0[0]); mma16816(acc[0], ah, &bl0[0]);
            mma16816(acc[1], ah, &bh0[2]); mma16816(acc[1], al, &bh0[2]); mma16816(acc[1], ah, &bl0[2]);
            mma16816(acc[2], ah, &bh1[0]); mma16816(acc[2], al, &bh1[0]); mma16816(acc[2], ah, &bl1[0]);
            mma16816(acc[3], ah, &bh1[2]); mma16816(acc[3], al, &bh1[2]); mma16816(acc[3], ah, &bl1[2]);
        }
        __syncthreads();
    }

    float* dst = part + ((size_t)bh * NSPLIT + split) * 4096;
    const int dr = wr * 16 + (lane >> 2);
    const int ec = wc * 32 + (lane & 3) * 2;
    #pragma unroll
    for (int nf = 0; nf < 4; nf++) {
        *(float2*)&dst[(size_t)dr * 64 + ec + nf * 8]       = make_float2(acc[nf][0], acc[nf][1]);
        *(float2*)&dst[(size_t)(dr + 8) * 64 + ec + nf * 8] = make_float2(acc[nf][2], acc[nf][3]);
    }
}

// ---------------- W2s[b][c][.] = fp16_2term( ((sum dots)/n2 @ Wout)^T ) ----------------
__global__ __launch_bounds__(256) void w2k(const float* __restrict__ part, const float* __restrict__ Wout,
                                           __half* __restrict__ W2s) {
    const int bh = blockIdx.x, dhalf = blockIdx.y;
    const int b = bh >> 3, h = bh & 7;
    __shared__ float ds[2048];   // [32 d_rel][64 e]
    const int tid = threadIdx.x;
    #pragma unroll
    for (int j = 0; j < 8; j++) {
        int idx = j * 256 + tid;
        int dr = idx >> 6, e = idx & 63;
        float s = 0.f;
        #pragma unroll
        for (int sp = 0; sp < NSPLIT; sp++)
            s += part[((size_t)bh * NSPLIT + sp) * 4096 + (dhalf * 32 + dr) * 64 + e];
        ds[idx] = s * (1.f / 4096.f);
    }
    __syncthreads();

    const int p = tid & 127, g = tid >> 7;
    u64 acc[16];
    #pragma unroll
    for (int d = 0; d < 16; d++) acc[d] = 0ull;
    for (int e = 0; e < 64; e++) {
        u64 w2 = *(const u64*)&Wout[(size_t)(h * 64 + e) * 256 + 2 * p];
        const float* dsr = &ds[(g * 16) * 64 + e];
        #pragma unroll
        for (int d = 0; d < 16; d++) {
            float val = dsr[d * 64];
            acc[d] = ffma2(pack2(val, val), w2, acc[d]);
        }
    }
    #pragma unroll
    for (int d = 0; d < 16; d++) {
        float o0, o1; unpack2(acc[d], o0, o1);
        const int dg = h * 64 + dhalf * 32 + g * 16 + d;
        size_t r0 = ((size_t)b * 256 + 2 * p) * 1024;
        __half hh = __float2half_rn(o0);
        W2s[r0 + dg]       = hh;
        W2s[r0 + 512 + dg] = __float2half_rn(__half2float(hh) * RINV);
        hh = __float2half_rn(o1);
        W2s[r0 + 1024 + dg]       = hh;
        W2s[r0 + 1024 + 512 + dg] = __float2half_rn(__half2float(hh) * RINV);
    }
}

// ---------------- launch ----------------
extern "C" void kernel_launch(void* const* d_in, const int* in_sizes, int n_in,
                              void* d_out, int out_size) {
    const float* x     = (const float*)d_in[0];
    const float* z     = (const float*)d_in[1];
    const float* x_pos = (const float*)d_in[2];
    const float* z_pos = (const float*)d_in[3];
    const float* Wq    = (const float*)d_in[4];
    const float* Wkv   = (const float*)d_in[5];
    const float* Wout  = (const float*)d_in[6];
    const float* bout  = (const float*)d_in[7];
    float* out = (float*)d_out;

    float *kv, *dotp;
    __half *z2, *x2, *wkv2, *wq2, *q2, *w2s;
    cudaGetSymbolAddress((void**)&kv,   g_kv);
    cudaGetSymbolAddress((void**)&dotp, g_dotp);
    cudaGetSymbolAddress((void**)&z2,   g_z2);
    cudaGetSymbolAddress((void**)&x2,   g_x2);
    cudaGetSymbolAddress((void**)&wkv2, g_wkv2);
    cudaGetSymbolAddress((void**)&wq2,  g_wq2);
    cudaGetSymbolAddress((void**)&q2,   g_q2);
    cudaGetSymbolAddress((void**)&w2s,  g_w2s);

    cudaFuncSetAttribute(gemm_mma<0>, cudaFuncAttributeMaxDynamicSharedMemorySize, GSMEM);
    cudaFuncSetAttribute(gemm_mma<1>, cudaFuncAttributeMaxDynamicSharedMemorySize, GSMEM);
    cudaFuncSetAttribute(dots_fused,  cudaFuncAttributeMaxDynamicSharedMemorySize, DSM_BYTES);

    // kv chain
    split_rows<<<MTOT * 64 / 256, 256>>>(z, z2);
    split_wT<<<1024, 256>>>(Wkv, wkv2, 1024);
    gemm_mma<0><<<dim3(8, 256, 1), 256, GSMEM>>>(z2, wkv2, kv, nullptr, nullptr,
                                                 1024, 512, 0, 0, 0, nullptr);
    dots_fused<<<dim3(NSPLIT, 64), 256, DSM_BYTES>>>(kv, z_pos, dotp);
    w2k<<<dim3(64, 2), 256>>>(dotp, Wout, w2s);

    // q chain (rotary + fp16 split fused into epilogue)
    split_rows<<<MTOT * 64 / 256, 256>>>(x, x2);
    split_wT<<<512, 256>>>(Wq, wq2, 512);
    gemm_mma<1><<<dim3(4, 256, 1), 256, GSMEM>>>(x2, wq2, nullptr, q2, x_pos,
                                                 512, 512, 0, 0, 0, nullptr);

    // out[b] = q2[b] @ W2s[b]^T + bout
    gemm_mma<0><<<dim3(2, 32, BATCH), 256, GSMEM>>>(
        q2, w2s, out, nullptr, nullptr, 256, 1024,
        (long)NTOKS * 1024, (long)256 * 1024, (long)NTOKS * 256, bout);
}

// round 10
// speedup vs baseline: 1.4134x; 1.0423x over previous
#include <cuda_runtime.h>
#include <cuda_bf16.h>
#include <cuda_fp16.h>
#include <math.h>
#include <cstdint>

typedef unsigned long long u64;
typedef unsigned int u32;

#define HEADS 8
#define NDIM  256
#define INNER 512
#define NTOKS 4096
#define BATCH 8
#define MTOT  (BATCH * NTOKS)   // 32768
#define RSCALE 32.f
#define RINV   0.03125f
#define NSPLIT 16
#define PL ((size_t)64 * 4096 * 64)   // one bf16 plane: [b*8+h][t][64]

// ---------------- scratch (device globals: allocation-guard safe) ----------------
__device__ __nv_bfloat16 g_kvs [(size_t)4 * PL];     // planes: kh, kl, vh, vl
__device__ float g_dotp[(size_t)64 * NSPLIT * 64 * 64];
__device__ __half g_z2  [(size_t)MTOT * 512];
__device__ __half g_x2  [(size_t)MTOT * 512];
__device__ __half g_wkv2[(size_t)1024 * 512];
__device__ __half g_wq2 [(size_t)512 * 512];
__device__ __half g_q2  [(size_t)MTOT * 1024];
__device__ __half g_w2s [(size_t)BATCH * 256 * 1024];

// ---------------- MMA / async helpers ----------------
__device__ __forceinline__ u32 smem_u32(const void* p) {
    u32 a; asm("{ .reg .u64 t; cvta.to.shared.u64 t, %1; cvt.u32.u64 %0, t; }" : "=r"(a) : "l"(p));
    return a;
}
__device__ __forceinline__ void cpa16(u32 dst, const void* src) {
    asm volatile("cp.async.cg.shared.global [%0], [%1], 16;" :: "r"(dst), "l"(src));
}
#define CP_COMMIT() asm volatile("cp.async.commit_group;" ::: "memory")
#define CP_WAIT(n)  asm volatile("cp.async.wait_group %0;" :: "n"(n) : "memory")

__device__ __forceinline__ void ldsm4(u32* r, u32 a) {
    asm volatile("ldmatrix.sync.aligned.m8n8.x4.shared.b16 {%0,%1,%2,%3}, [%4];"
        : "=r"(r[0]), "=r"(r[1]), "=r"(r[2]), "=r"(r[3]) : "r"(a));
}
__device__ __forceinline__ void ldsm4t(u32* r, u32 a) {
    asm volatile("ldmatrix.sync.aligned.m8n8.x4.trans.shared.b16 {%0,%1,%2,%3}, [%4];"
        : "=r"(r[0]), "=r"(r[1]), "=r"(r[2]), "=r"(r[3]) : "r"(a));
}
__device__ __forceinline__ void mma16816h(float* c, const u32* a, const u32* b) {
    asm volatile("mma.sync.aligned.m16n8k16.row.col.f32.f16.f16.f32 "
        "{%0,%1,%2,%3}, {%4,%5,%6,%7}, {%8,%9}, {%0,%1,%2,%3};"
        : "+f"(c[0]), "+f"(c[1]), "+f"(c[2]), "+f"(c[3])
        : "r"(a[0]), "r"(a[1]), "r"(a[2]), "r"(a[3]), "r"(b[0]), "r"(b[1]));
}
__device__ __forceinline__ void mma16816(float* c, const u32* a, const u32* b) {
    asm volatile("mma.sync.aligned.m16n8k16.row.col.f32.bf16.bf16.f32 "
        "{%0,%1,%2,%3}, {%4,%5,%6,%7}, {%8,%9}, {%0,%1,%2,%3};"
        : "+f"(c[0]), "+f"(c[1]), "+f"(c[2]), "+f"(c[3])
        : "r"(a[0]), "r"(a[1]), "r"(a[2]), "r"(a[3]), "r"(b[0]), "r"(b[1]));
}

// ---------------- f32x2 helpers ----------------
__device__ __forceinline__ u64 pack2(float x, float y) {
    u64 r; asm("mov.b64 %0, {%1,%2};" : "=l"(r) : "f"(x), "f"(y)); return r;
}
__device__ __forceinline__ u64 ffma2(u64 a, u64 b, u64 c) {
    u64 d; asm("fma.rn.f32x2 %0, %1, %2, %3;" : "=l"(d) : "l"(a), "l"(b), "l"(c)); return d;
}
__device__ __forceinline__ void unpack2(u64 v, float& x, float& y) {
    asm("mov.b64 {%0,%1}, %2;" : "=f"(x), "=f"(y) : "l"(v));
}

// ---------------- split helpers ----------------
__device__ __forceinline__ void splith_data(float v, __half& h, __half& l) {
    h = __float2half_rn(v);
    l = __float2half_rn(RSCALE * (v - __half2float(h)));
}
__device__ __forceinline__ void split1(float v, __nv_bfloat16& h, __nv_bfloat16& l) {
    h = __float2bfloat16(v);
    l = __float2bfloat16(v - __bfloat162float(h));
}

// in [R,256] fp32 -> out [R,512] fp16
__global__ void split_rows(const float* __restrict__ in, __half* __restrict__ out) {
    size_t idx = (size_t)blockIdx.x * 256 + threadIdx.x;
    size_t row = idx >> 6; int c4 = (int)(idx & 63);
    float4 v = ((const float4*)in)[idx];
    __half h0, l0, h1, l1, h2, l2, h3, l3;
    splith_data(v.x, h0, l0); splith_data(v.y, h1, l1);
    splith_data(v.z, h2, l2); splith_data(v.w, h3, l3);
    __half* ph = out + row * 512 + c4 * 4;
    *(__half2*)(ph)     = __half2{h0, h1};
    *(__half2*)(ph + 2) = __half2{h2, h3};
    __half* pl = ph + 256;
    *(__half2*)(pl)     = __half2{l0, l1};
    *(__half2*)(pl + 2) = __half2{l2, l3};
}

// W [256, N] fp32 -> out [N, 512] fp16 (transpose)
__global__ void split_wT(const float* __restrict__ W, __half* __restrict__ out, int N) {
    int n = blockIdx.x, k = threadIdx.x;
    float v = W[(size_t)k * N + n];
    __half h = __float2half_rn(v);
    __half s = __float2half_rn(__half2float(h) * RINV);
    out[(size_t)n * 512 + k]       = h;
    out[(size_t)n * 512 + 256 + k] = s;
}

// ---------------- 2-term fp16 HMMA GEMM ----------------
// MODE 0: fp32 C (+bias). MODE 1: rotary + fp16 split -> Cq. MODE 2 (kv):
// instance-norm per head + rotary(k) + bf16 split -> planes Cb.
#define ROWB 80
#define TILEB (128 * ROWB)
#define STAGEB (2 * TILEB)
#define NSTAGE 4
#define GSMEM (NSTAGE * STAGEB)

template <int MODE>
__global__ __launch_bounds__(256, 2) void gemm_mma(
    const __half* __restrict__ A2, const __half* __restrict__ B2,
    float* __restrict__ C, __half* __restrict__ Cq, __nv_bfloat16* __restrict__ Cb,
    const float* __restrict__ pos, int N, int K2,
    long sA, long sB, long sC, const float* __restrict__ bias)
{
    extern __shared__ __align__(1024) char smem[];
    A2 += (size_t)blockIdx.z * sA;
    B2 += (size_t)blockIdx.z * sB;
    if (MODE == 0) C += (size_t)blockIdx.z * sC;
    const int m0 = blockIdx.y * 128, n0 = blockIdx.x * 128;
    const int tid = threadIdx.x, lane = tid & 31, wid = tid >> 5;
    const int wr = wid >> 2, wc = wid & 3;
    const u32 sb = smem_u32(smem);

    const int total = K2 >> 5;
    const int lrow = tid >> 1;
    const int lcg = (tid & 1) * 2;

    float acc[4][4][4];
    #pragma unroll
    for (int i = 0; i < 4; i++)
        #pragma unroll
        for (int j = 0; j < 4; j++)
            #pragma unroll
            for (int r = 0; r < 4; r++) acc[i][j][r] = 0.f;

    auto issue = [&](int it) {
        const int stage = it & (NSTAGE - 1);
        const int kk = it * 32;
        const __half* as = A2 + (size_t)(m0 + lrow) * K2 + kk + lcg * 8;
        const __half* bs = B2 + (size_t)(n0 + lrow) * K2 + kk + lcg * 8;
        const u32 da = sb + stage * STAGEB + lrow * ROWB + lcg * 16;
        cpa16(da, as);              cpa16(da + 16, as + 8);
        cpa16(da + TILEB, bs);      cpa16(da + TILEB + 16, bs + 8);
        CP_COMMIT();
    };

    auto compute = [&](int stage) {
        const u32 ab = sb + stage * STAGEB;
        const u32 bb = ab + TILEB;
        #pragma unroll
        for (int kb = 0; kb < 2; kb++) {
            u32 a[4][4], b[2][4];
            #pragma unroll
            for (int mf = 0; mf < 4; mf++) {
                u32 addr = ab + (u32)(wr * 64 + mf * 16 + (lane & 15)) * ROWB
                              + kb * 32 + (lane >> 4) * 16;
                ldsm4(a[mf], addr);
            }
            #pragma unroll
            for (int nfp = 0; nfp < 2; nfp++) {
                u32 addr = bb + (u32)(wc * 32 + nfp * 16 + ((lane >> 4) << 3) + (lane & 7)) * ROWB
                              + kb * 32 + ((lane >> 3) & 1) * 16;
                ldsm4(b[nfp], addr);
            }
            #pragma unroll
            for (int mf = 0; mf < 4; mf++)
                #pragma unroll
                for (int nf = 0; nf < 4; nf++)
                    mma16816h(acc[mf][nf], a[mf], &b[nf >> 1][(nf & 1) * 2]);
        }
    };

    issue(0); issue(1); issue(2);
    for (int i = 0; i < total; i++) {
        if (i < total - 2)       CP_WAIT(2);
        else if (i == total - 2) CP_WAIT(1);
        else                     CP_WAIT(0);
        __syncthreads();
        compute(i & (NSTAGE - 1));
        if (i + 3 < total) issue(i + 3);
    }

    if (MODE == 0) {
        const int rbase = m0 + wr * 64 + (lane >> 2);
        const int cbase = n0 + wc * 32 + (lane & 3) * 2;
        #pragma unroll
        for (int nf = 0; nf < 4; nf++) {
            const int c = cbase + nf * 8;
            float bx = 0.f, by = 0.f;
            if (bias) { bx = bias[c]; by = bias[c + 1]; }
            #pragma unroll
            for (int mf = 0; mf < 4; mf++) {
                const int r = rbase + mf * 16;
                *(float2*)&C[(size_t)r * N + c] =
                    make_float2(acc[mf][nf][0] + bx, acc[mf][nf][1] + by);
                *(float2*)&C[(size_t)(r + 8) * N + c] =
                    make_float2(acc[mf][nf][2] + bx, acc[mf][nf][3] + by);
            }
        }
    } else if (MODE == 1) {
        const int half = wc & 1;
        const int lq = lane & 3;
        #pragma unroll
        for (int mf = 0; mf < 4; mf++) {
            #pragma unroll
            for (int rb = 0; rb < 2; rb++) {
                const int r = m0 + wr * 64 + mf * 16 + (lane >> 2) + rb * 8;
                const float pp = pos[(size_t)r * 2 + half] * 64.f;
                const size_t rowb = (size_t)r * (2 * N);
                #pragma unroll
                for (int nf2 = 0; nf2 < 2; nf2++) {
                    float o[4];
                    #pragma unroll
                    for (int cb = 0; cb < 2; cb++) {
                        const int j = nf2 * 8 + lq * 2 + cb;
                        const float invf = exp2f(-(float)j * (13.287712379549449f / 16.f));
                        float s, co; sincosf(pp * invf, &s, &co);
                        const int idx = rb * 2 + cb;
                        const float vlo = acc[mf][nf2][idx];
                        const float vhi = acc[mf][nf2 + 2][idx];
                        o[cb]     = vlo * co - vhi * s;
                        o[2 + cb] = vhi * co + vlo * s;
                    }
                    const int cg = n0 + wc * 32 + nf2 * 8 + lq * 2;
                    __half h0, l0, h1, l1;
                    splith_data(o[0], h0, l0); splith_data(o[1], h1, l1);
                    *(__half2*)&Cq[rowb + cg]     = __half2{h0, h1};
                    *(__half2*)&Cq[rowb + N + cg] = __half2{l0, l1};
                    splith_data(o[2], h0, l0); splith_data(o[3], h1, l1);
                    *(__half2*)&Cq[rowb + cg + 16]     = __half2{h0, h1};
                    *(__half2*)&Cq[rowb + N + cg + 16] = __half2{l0, l1};
                }
            }
        }
    } else {
        // MODE 2: per-head instance norm (+rotary on k) + bf16 split -> planes.
        // Tile cols (128) cover 2 complete heads: head-in-tile = wc>>1, half = wc&1.
        __syncthreads();                       // mainloop smem dead; reuse for reduction
        float* red = (float*)smem;             // [wr][wc][ri(8)][rowlane(8)] x {sum,sq}
        float s8[8], q8[8], mean[8], inv[8];
        #pragma unroll
        for (int mf = 0; mf < 4; mf++)
            #pragma unroll
            for (int rb = 0; rb < 2; rb++) {
                const int ri = mf * 2 + rb;
                float s = 0.f, q = 0.f;
                #pragma unroll
                for (int nf = 0; nf < 4; nf++)
                    #pragma unroll
                    for (int cb = 0; cb < 2; cb++) {
                        float a = acc[mf][nf][rb * 2 + cb];
                        s += a; q += a * a;
                    }
                s += __shfl_xor_sync(0xffffffffu, s, 1); q += __shfl_xor_sync(0xffffffffu, q, 1);
                s += __shfl_xor_sync(0xffffffffu, s, 2); q += __shfl_xor_sync(0xffffffffu, q, 2);
                s8[ri] = s; q8[ri] = q;
            }
        if ((lane & 3) == 0) {
            #pragma unroll
            for (int ri = 0; ri < 8; ri++) {
                const int idx = (((wr * 4 + wc) * 8) + ri) * 8 + (lane >> 2);
                red[idx * 2] = s8[ri]; red[idx * 2 + 1] = q8[ri];
            }
        }
        __syncthreads();
        #pragma unroll
        for (int ri = 0; ri < 8; ri++) {
            const int idx = (((wr * 4 + (wc ^ 1)) * 8) + ri) * 8 + (lane >> 2);
            const float ts = s8[ri] + red[idx * 2];
            const float tq = q8[ri] + red[idx * 2 + 1];
            const float mu = ts * (1.f / 64.f);
            mean[ri] = mu;
            inv[ri] = rsqrtf(fmaxf(tq * (1.f / 64.f) - mu * mu, 0.f) + 1e-5f);
        }

        const int isK = (blockIdx.x < 4);
        const int g = (isK ? blockIdx.x : blockIdx.x - 4) * 2 + (wc >> 1);
        const int half = wc & 1;
        const int lq = lane & 3;
        __nv_bfloat16* base0 = Cb + (isK ? 0 : 2 * PL);
        #pragma unroll
        for (int mf = 0; mf < 4; mf++)
            #pragma unroll
            for (int rb = 0; rb < 2; rb++) {
                const int ri = mf * 2 + rb;
                const int m = m0 + wr * 64 + mf * 16 + (lane >> 2) + rb * 8;
                const int bb = m >> 12, tt = m & 4095;
                const size_t rowoff = ((size_t)(bb * 8 + g) * 4096 + tt) * 64;
                const float mu = mean[ri], iv = inv[ri];
                if (isK) {
                    const float pp = pos[(size_t)m * 2 + half] * 64.f;
                    #pragma unroll
                    for (int nf2 = 0; nf2 < 2; nf2++) {
                        float o[4];
                        #pragma unroll
                        for (int cb = 0; cb < 2; cb++) {
                            const int j = nf2 * 8 + lq * 2 + cb;
                            const float invf = exp2f(-(float)j * (13.287712379549449f / 16.f));
                            float sn, co; sincosf(pp * invf, &sn, &co);
                            const float vlo = (acc[mf][nf2][rb * 2 + cb]     - mu) * iv;
                            const float vhi = (acc[mf][nf2 + 2][rb * 2 + cb] - mu) * iv;
                            o[cb]     = vlo * co - vhi * sn;
                            o[2 + cb] = vhi * co + vlo * sn;
                        }
                        const int cg = half * 32 + nf2 * 8 + lq * 2;
                        __nv_bfloat16 h0, l0, h1, l1;
                        split1(o[0], h0, l0); split1(o[1], h1, l1);
                        *(__nv_bfloat162*)&base0[rowoff + cg]      = __nv_bfloat162{h0, h1};
                        *(__nv_bfloat162*)&base0[PL + rowoff + cg] = __nv_bfloat162{l0, l1};
                        split1(o[2], h0, l0); split1(o[3], h1, l1);
                        *(__nv_bfloat162*)&base0[rowoff + cg + 16]      = __nv_bfloat162{h0, h1};
                        *(__nv_bfloat162*)&base0[PL + rowoff + cg + 16] = __nv_bfloat162{l0, l1};
                    }
                } else {
                    #pragma unroll
                    for (int nf = 0; nf < 4; nf++) {
                        const int cg = half * 32 + nf * 8 + lq * 2;
                        const float a0 = (acc[mf][nf][rb * 2]     - mu) * iv;
                        const float a1 = (acc[mf][nf][rb * 2 + 1] - mu) * iv;
                        __nv_bfloat16 h0, l0, h1, l1;
                        split1(a0, h0, l0); split1(a1, h1, l1);
                        *(__nv_bfloat162*)&base0[rowoff + cg]      = __nv_bfloat162{h0, h1};
                        *(__nv_bfloat162*)&base0[PL + rowoff + cg] = __nv_bfloat162{l0, l1};
                    }
                }
            }
    }
}

// ---------------- dots: pure streaming bf16 3-term Gram MMA ----------------
#define DROWB 144
#define DTILE (64 * DROWB)       // 9216
#define DSTG4 (4 * DTILE)        // 36864: kh, kl, vh, vl tiles for one chunk
#define DSM_BYTES (2 * DSTG4)    // 73728

__global__ __launch_bounds__(256, 2) void dots_pure(const __nv_bfloat16* __restrict__ kvs,
                                                    float* __restrict__ part) {
    extern __shared__ __align__(1024) char dsm[];
    const u32 sb = smem_u32(dsm);

    const int split = blockIdx.x;   // 0..15
    const int bh = blockIdx.y;      // 0..63
    const int tid = threadIdx.x;
    const int w = tid >> 5, lane = tid & 31;
    const int wr = w >> 1, wc = w & 1;

    float acc[4][4];
    #pragma unroll
    for (int i = 0; i < 4; i++)
        #pragma unroll
        for (int j = 0; j < 4; j++) acc[i][j] = 0.f;

    auto issue = [&](int c) {
        const int t0 = split * 256 + c * 64;
        const u32 sbase = sb + (c & 1) * DSTG4;
        #pragma unroll
        for (int i = 0; i < 8; i++) {
            const int idx = i * 256 + tid;      // 0..2047
            const int plane = idx >> 9;
            const int r = (idx >> 3) & 63;
            const int seg = idx & 7;
            const __nv_bfloat16* src = kvs + (size_t)plane * PL
                + ((size_t)bh * 4096 + t0 + r) * 64 + seg * 8;
            cpa16(sbase + plane * DTILE + r * DROWB + seg * 16, src);
        }
        CP_COMMIT();
    };

    issue(0);
    for (int c = 0; c < 4; c++) {
        if (c < 3) { issue(c + 1); CP_WAIT(1); } else { CP_WAIT(0); }
        __syncthreads();
        const u32 khb = sb + (c & 1) * DSTG4;
        const u32 klb = khb + DTILE;
        const u32 vhb = khb + 2 * DTILE;
        const u32 vlb = khb + 3 * DTILE;
        #pragma unroll
        for (int kt = 0; kt < 4; kt++) {
            const u32 arow = (u32)(kt * 16 + (lane & 7) + ((lane >> 4) << 3));
            const u32 acol = (u32)(wr * 16 + ((lane >> 3) & 1) * 8);
            const u32 aoff = arow * DROWB + acol * 2;
            u32 ah[4], al[4];
            ldsm4t(ah, khb + aoff);
            ldsm4t(al, klb + aoff);
            const u32 brow = (u32)(kt * 16 + (lane & 7) + ((lane >> 3) & 1) * 8);
            const u32 bcol = (u32)(wc * 32 + ((lane >> 4) << 3));
            const u32 boff = brow * DROWB + bcol * 2;
            u32 bh0[4], bl0[4], bh1[4], bl1[4];
            ldsm4t(bh0, vhb + boff);
            ldsm4t(bl0, vlb + boff);
            ldsm4t(bh1, vhb + boff + 32);
            ldsm4t(bl1, vlb + boff + 32);
            mma16816(acc[0], ah, &bh0[0]); mma16816(acc[0], al, &bh0[0]); mma16816(acc[0], ah, &bl0[0]);
            mma16816(acc[1], ah, &bh0[2]); mma16816(acc[1], al, &bh0[2]); mma16816(acc[1], ah, &bl0[2]);
            mma16816(acc[2], ah, &bh1[0]); mma16816(acc[2], al, &bh1[0]); mma16816(acc[2], ah, &bl1[0]);
            mma16816(acc[3], ah, &bh1[2]); mma16816(acc[3], al, &bh1[2]); mma16816(acc[3], ah, &bl1[2]);
        }
        __syncthreads();
    }

    float* dst = part + ((size_t)bh * NSPLIT + split) * 4096;
    const int dr = wr * 16 + (lane >> 2);
    const int ec = wc * 32 + (lane & 3) * 2;
    #pragma unroll
    for (int nf = 0; nf < 4; nf++) {
        *(float2*)&dst[(size_t)dr * 64 + ec + nf * 8]       = make_float2(acc[nf][0], acc[nf][1]);
        *(float2*)&dst[(size_t)(dr + 8) * 64 + ec + nf * 8] = make_float2(acc[nf][2], acc[nf][3]);
    }
}

// ---------------- W2s[b][c][.] = fp16_2term( ((sum dots)/n2 @ Wout)^T ) ----------------
__global__ __launch_bounds__(256) void w2k(const float* __restrict__ part, const float* __restrict__ Wout,
                                           __half* __restrict__ W2s) {
    const int bh = blockIdx.x, dhalf = blockIdx.y;
    const int b = bh >> 3, h = bh & 7;
    __shared__ float ds[2048];
    const int tid = threadIdx.x;
    #pragma unroll
    for (int j = 0; j < 8; j++) {
        int idx = j * 256 + tid;
        int dr = idx >> 6, e = idx & 63;
        float s = 0.f;
        #pragma unroll
        for (int sp = 0; sp < NSPLIT; sp++)
            s += part[((size_t)bh * NSPLIT + sp) * 4096 + (dhalf * 32 + dr) * 64 + e];
        ds[idx] = s * (1.f / 4096.f);
    }
    __syncthreads();

    const int p = tid & 127, g = tid >> 7;
    u64 acc[16];
    #pragma unroll
    for (int d = 0; d < 16; d++) acc[d] = 0ull;
    for (int e = 0; e < 64; e++) {
        u64 w2 = *(const u64*)&Wout[(size_t)(h * 64 + e) * 256 + 2 * p];
        const float* dsr = &ds[(g * 16) * 64 + e];
        #pragma unroll
        for (int d = 0; d < 16; d++) {
            float val = dsr[d * 64];
            acc[d] = ffma2(pack2(val, val), w2, acc[d]);
        }
    }
    #pragma unroll
    for (int d = 0; d < 16; d++) {
        float o0, o1; unpack2(acc[d], o0, o1);
        const int dg = h * 64 + dhalf * 32 + g * 16 + d;
        size_t r0 = ((size_t)b * 256 + 2 * p) * 1024;
        __half hh = __float2half_rn(o0);
        W2s[r0 + dg]       = hh;
        W2s[r0 + 512 + dg] = __float2half_rn(__half2float(hh) * RINV);
        hh = __float2half_rn(o1);
        W2s[r0 + 1024 + dg]       = hh;
        W2s[r0 + 1024 + 512 + dg] = __float2half_rn(__half2float(hh) * RINV);
    }
}

// ---------------- launch ----------------
extern "C" void kernel_launch(void* const* d_in, const int* in_sizes, int n_in,
                              void* d_out, int out_size) {
    const float* x     = (const float*)d_in[0];
    const float* z     = (const float*)d_in[1];
    const float* x_pos = (const float*)d_in[2];
    const float* z_pos = (const float*)d_in[3];
    const float* Wq    = (const float*)d_in[4];
    const float* Wkv   = (const float*)d_in[5];
    const float* Wout  = (const float*)d_in[6];
    const float* bout  = (const float*)d_in[7];
    float* out = (float*)d_out;

    float* dotp;
    __nv_bfloat16* kvs;
    __half *z2, *x2, *wkv2, *wq2, *q2, *w2s;
    cudaGetSymbolAddress((void**)&kvs,  g_kvs);
    cudaGetSymbolAddress((void**)&dotp, g_dotp);
    cudaGetSymbolAddress((void**)&z2,   g_z2);
    cudaGetSymbolAddress((void**)&x2,   g_x2);
    cudaGetSymbolAddress((void**)&wkv2, g_wkv2);
    cudaGetSymbolAddress((void**)&wq2,  g_wq2);
    cudaGetSymbolAddress((void**)&q2,   g_q2);
    cudaGetSymbolAddress((void**)&w2s,  g_w2s);

    cudaFuncSetAttribute(gemm_mma<0>, cudaFuncAttributeMaxDynamicSharedMemorySize, GSMEM);
    cudaFuncSetAttribute(gemm_mma<1>, cudaFuncAttributeMaxDynamicSharedMemorySize, GSMEM);
    cudaFuncSetAttribute(gemm_mma<2>, cudaFuncAttributeMaxDynamicSharedMemorySize, GSMEM);
    cudaFuncSetAttribute(dots_pure,   cudaFuncAttributeMaxDynamicSharedMemorySize, DSM_BYTES);

    // kv chain: GEMM fuses norm + rotary + bf16 split into epilogue
    split_rows<<<MTOT * 64 / 256, 256>>>(z, z2);
    split_wT<<<1024, 256>>>(Wkv, wkv2, 1024);
    gemm_mma<2><<<dim3(8, 256, 1), 256, GSMEM>>>(z2, wkv2, nullptr, nullptr, kvs, z_pos,
                                                 1024, 512, 0, 0, 0, nullptr);
    dots_pure<<<dim3(NSPLIT, 64), 256, DSM_BYTES>>>(kvs, dotp);
    w2k<<<dim3(64, 2), 256>>>(dotp, Wout, w2s);

    // q chain (rotary + fp16 split fused into epilogue)
    split_rows<<<MTOT * 64 / 256, 256>>>(x, x2);
    split_wT<<<512, 256>>>(Wq, wq2, 512);
    gemm_mma<1><<<dim3(4, 256, 1), 256, GSMEM>>>(x2, wq2, nullptr, q2, nullptr, x_pos,
                                                 512, 512, 0, 0, 0, nullptr);

    // out[b] = q2[b] @ W2s[b]^T + bout
    gemm_mma<0><<<dim3(2, 32, BATCH), 256, GSMEM>>>(
        q2, w2s, out, nullptr, nullptr, nullptr, 256, 1024,
        (long)NTOKS * 1024, (long)256 * 1024, (long)NTOKS * 256, bout);
}

// round 11
// speedup vs baseline: 1.6299x; 1.1532x over previous
#include <cuda_runtime.h>
#include <cuda_bf16.h>
#include <cuda_fp16.h>
#include <math.h>
#include <cstdint>

typedef unsigned long long u64;
typedef unsigned int u32;

#define HEADS 8
#define NDIM  256
#define INNER 512
#define NTOKS 4096
#define BATCH 8
#define MTOT  (BATCH * NTOKS)   // 32768
#define RSCALE 32.f
#define RINV   0.03125f
#define NSPLIT 16
#define PL ((size_t)64 * 4096 * 64)   // one bf16 plane: [b*8+h][t][64]

// ---------------- scratch (device globals: allocation-guard safe) ----------------
__device__ __nv_bfloat16 g_kvs [(size_t)4 * PL];     // planes: kh, kl, vh, vl
__device__ float g_dotp[(size_t)64 * NSPLIT * 64 * 64];
__device__ __half g_z2  [(size_t)MTOT * 512];        // z: [hi(256), 32*resid(256)]
__device__ __half g_x2  [(size_t)MTOT * 512];
__device__ __half g_wkv2[(size_t)1024 * 512];
__device__ __half g_wq2 [(size_t)512 * 512];
__device__ __half g_q2  [(size_t)MTOT * 512];        // q rot: single fp16 plane
__device__ __half g_w2s [(size_t)BATCH * 256 * 512]; // W2^T: single fp16 plane

// ---------------- MMA / async helpers ----------------
__device__ __forceinline__ u32 smem_u32(const void* p) {
    u32 a; asm("{ .reg .u64 t; cvta.to.shared.u64 t, %1; cvt.u32.u64 %0, t; }" : "=r"(a) : "l"(p));
    return a;
}
__device__ __forceinline__ void cpa16(u32 dst, const void* src) {
    asm volatile("cp.async.cg.shared.global [%0], [%1], 16;" :: "r"(dst), "l"(src));
}
#define CP_COMMIT() asm volatile("cp.async.commit_group;" ::: "memory")
#define CP_WAIT(n)  asm volatile("cp.async.wait_group %0;" :: "n"(n) : "memory")

__device__ __forceinline__ void ldsm4(u32* r, u32 a) {
    asm volatile("ldmatrix.sync.aligned.m8n8.x4.shared.b16 {%0,%1,%2,%3}, [%4];"
        : "=r"(r[0]), "=r"(r[1]), "=r"(r[2]), "=r"(r[3]) : "r"(a));
}
__device__ __forceinline__ void ldsm4t(u32* r, u32 a) {
    asm volatile("ldmatrix.sync.aligned.m8n8.x4.trans.shared.b16 {%0,%1,%2,%3}, [%4];"
        : "=r"(r[0]), "=r"(r[1]), "=r"(r[2]), "=r"(r[3]) : "r"(a));
}
__device__ __forceinline__ void mma16816h(float* c, const u32* a, const u32* b) {
    asm volatile("mma.sync.aligned.m16n8k16.row.col.f32.f16.f16.f32 "
        "{%0,%1,%2,%3}, {%4,%5,%6,%7}, {%8,%9}, {%0,%1,%2,%3};"
        : "+f"(c[0]), "+f"(c[1]), "+f"(c[2]), "+f"(c[3])
        : "r"(a[0]), "r"(a[1]), "r"(a[2]), "r"(a[3]), "r"(b[0]), "r"(b[1]));
}
__device__ __forceinline__ void mma16816(float* c, const u32* a, const u32* b) {
    asm volatile("mma.sync.aligned.m16n8k16.row.col.f32.bf16.bf16.f32 "
        "{%0,%1,%2,%3}, {%4,%5,%6,%7}, {%8,%9}, {%0,%1,%2,%3};"
        : "+f"(c[0]), "+f"(c[1]), "+f"(c[2]), "+f"(c[3])
        : "r"(a[0]), "r"(a[1]), "r"(a[2]), "r"(a[3]), "r"(b[0]), "r"(b[1]));
}

// ---------------- f32x2 helpers ----------------
__device__ __forceinline__ u64 pack2(float x, float y) {
    u64 r; asm("mov.b64 %0, {%1,%2};" : "=l"(r) : "f"(x), "f"(y)); return r;
}
__device__ __forceinline__ u64 ffma2(u64 a, u64 b, u64 c) {
    u64 d; asm("fma.rn.f32x2 %0, %1, %2, %3;" : "=l"(d) : "l"(a), "l"(b), "l"(c)); return d;
}
__device__ __forceinline__ void unpack2(u64 v, float& x, float& y) {
    asm("mov.b64 {%0,%1}, %2;" : "=f"(x), "=f"(y) : "l"(v));
}

// ---------------- split helpers ----------------
__device__ __forceinline__ void splith_data(float v, __half& h, __half& l) {
    h = __float2half_rn(v);
    l = __float2half_rn(RSCALE * (v - __half2float(h)));
}
__device__ __forceinline__ void split1(float v, __nv_bfloat16& h, __nv_bfloat16& l) {
    h = __float2bfloat16(v);
    l = __float2bfloat16(v - __bfloat162float(h));
}

// ---------------- unified prep: split z, x (rows) + Wkv, Wq (transpose) ----------------
// blocks: [0,8192) z rows, [8192,16384) x rows, [16384,17408) Wkv cols, [17408,17920) Wq cols
__global__ void prep(const float* __restrict__ z, const float* __restrict__ x,
                     const float* __restrict__ Wkv, const float* __restrict__ Wq,
                     __half* __restrict__ z2, __half* __restrict__ x2,
                     __half* __restrict__ wkv2, __half* __restrict__ wq2) {
    const int bid = blockIdx.x;
    const int tid = threadIdx.x;
    if (bid < 16384) {
        const float* in = (bid < 8192) ? z : x;
        __half* out = (bid < 8192) ? z2 : x2;
        size_t idx = (size_t)(bid & 8191) * 256 + tid;
        size_t row = idx >> 6; int c4 = (int)(idx & 63);
        float4 v = ((const float4*)in)[idx];
        __half h0, l0, h1, l1, h2, l2, h3, l3;
        splith_data(v.x, h0, l0); splith_data(v.y, h1, l1);
        splith_data(v.z, h2, l2); splith_data(v.w, h3, l3);
        __half* ph = out + row * 512 + c4 * 4;
        *(__half2*)(ph)     = __half2{h0, h1};
        *(__half2*)(ph + 2) = __half2{h2, h3};
        __half* pl = ph + 256;
        *(__half2*)(pl)     = __half2{l0, l1};
        *(__half2*)(pl + 2) = __half2{l2, l3};
    } else {
        const int isKv = (bid < 17408);
        const int n = isKv ? (bid - 16384) : (bid - 17408);
        const int N = isKv ? 1024 : 512;
        const float* W = isKv ? Wkv : Wq;
        __half* out = isKv ? wkv2 : wq2;
        float v = W[(size_t)tid * N + n];
        __half h = __float2half_rn(v);
        __half s = __float2half_rn(__half2float(h) * RINV);
        out[(size_t)n * 512 + tid]       = h;
        out[(size_t)n * 512 + 256 + tid] = s;
    }
}

// ---------------- main GEMM: kv (norm+rot+bf16 planes) and q (rot+fp16) in ONE launch ----
// grid (12, 256): bx<8 -> kv GEMM CTA (N=1024), bx>=8 -> q GEMM CTA (N=512). K2=512 both.
#define ROWB 80
#define TILEB (128 * ROWB)
#define STAGEB (2 * TILEB)
#define NSTAGE 4
#define GSMEM (NSTAGE * STAGEB)

__global__ __launch_bounds__(256, 2) void gemm_main(
    const __half* __restrict__ z2, const __half* __restrict__ wkv2,
    const __half* __restrict__ x2, const __half* __restrict__ wq2,
    __nv_bfloat16* __restrict__ Cb, __half* __restrict__ Cq,
    const float* __restrict__ z_pos, const float* __restrict__ x_pos)
{
    extern __shared__ __align__(1024) char smem[];
    const int bx = blockIdx.x;
    const int isKv = (bx < 8);
    const __half* A2 = isKv ? z2 : x2;
    const __half* B2 = isKv ? wkv2 : wq2;
    const int n0 = (isKv ? bx : bx - 8) * 128;
    const int m0 = blockIdx.y * 128;
    const int tid = threadIdx.x, lane = tid & 31, wid = tid >> 5;
    const int wr = wid >> 2, wc = wid & 3;
    const u32 sb = smem_u32(smem);

    const int K2 = 512, total = 16;
    const int lrow = tid >> 1;
    const int lcg = (tid & 1) * 2;

    float acc[4][4][4];
    #pragma unroll
    for (int i = 0; i < 4; i++)
        #pragma unroll
        for (int j = 0; j < 4; j++)
            #pragma unroll
            for (int r = 0; r < 4; r++) acc[i][j][r] = 0.f;

    auto issue = [&](int it) {
        const int stage = it & (NSTAGE - 1);
        const int kk = it * 32;
        const __half* as = A2 + (size_t)(m0 + lrow) * K2 + kk + lcg * 8;
        const __half* bs = B2 + (size_t)(n0 + lrow) * K2 + kk + lcg * 8;
        const u32 da = sb + stage * STAGEB + lrow * ROWB + lcg * 16;
        cpa16(da, as);              cpa16(da + 16, as + 8);
        cpa16(da + TILEB, bs);      cpa16(da + TILEB + 16, bs + 8);
        CP_COMMIT();
    };

    auto compute = [&](int stage) {
        const u32 ab = sb + stage * STAGEB;
        const u32 bb = ab + TILEB;
        #pragma unroll
        for (int kb = 0; kb < 2; kb++) {
            u32 a[4][4], b[2][4];
            #pragma unroll
            for (int mf = 0; mf < 4; mf++) {
                u32 addr = ab + (u32)(wr * 64 + mf * 16 + (lane & 15)) * ROWB
                              + kb * 32 + (lane >> 4) * 16;
                ldsm4(a[mf], addr);
            }
            #pragma unroll
            for (int nfp = 0; nfp < 2; nfp++) {
                u32 addr = bb + (u32)(wc * 32 + nfp * 16 + ((lane >> 4) << 3) + (lane & 7)) * ROWB
                              + kb * 32 + ((lane >> 3) & 1) * 16;
                ldsm4(b[nfp], addr);
            }
            #pragma unroll
            for (int mf = 0; mf < 4; mf++)
                #pragma unroll
                for (int nf = 0; nf < 4; nf++)
                    mma16816h(acc[mf][nf], a[mf], &b[nf >> 1][(nf & 1) * 2]);
        }
    };

    issue(0); issue(1); issue(2);
    for (int i = 0; i < total; i++) {
        if (i < total - 2)       CP_WAIT(2);
        else if (i == total - 2) CP_WAIT(1);
        else                     CP_WAIT(0);
        __syncthreads();
        compute(i & (NSTAGE - 1));
        if (i + 3 < total) issue(i + 3);
    }

    if (isKv) {
        // per-head instance norm (+rotary on k) + bf16 split -> planes.
        // Tile cols (128) cover 2 complete heads: head-in-tile = wc>>1, half = wc&1.
        __syncthreads();                       // mainloop smem dead; reuse for reduction
        float* red = (float*)smem;             // [wr][wc][ri(8)][rowlane(8)] x {sum,sq}
        float s8[8], q8[8], mean[8], inv[8];
        #pragma unroll
        for (int mf = 0; mf < 4; mf++)
            #pragma unroll
            for (int rb = 0; rb < 2; rb++) {
                const int ri = mf * 2 + rb;
                float s = 0.f, q = 0.f;
                #pragma unroll
                for (int nf = 0; nf < 4; nf++)
                    #pragma unroll
                    for (int cb = 0; cb < 2; cb++) {
                        float a = acc[mf][nf][rb * 2 + cb];
                        s += a; q += a * a;
                    }
                s += __shfl_xor_sync(0xffffffffu, s, 1); q += __shfl_xor_sync(0xffffffffu, q, 1);
                s += __shfl_xor_sync(0xffffffffu, s, 2); q += __shfl_xor_sync(0xffffffffu, q, 2);
                s8[ri] = s; q8[ri] = q;
            }
        if ((lane & 3) == 0) {
            #pragma unroll
            for (int ri = 0; ri < 8; ri++) {
                const int idx = (((wr * 4 + wc) * 8) + ri) * 8 + (lane >> 2);
                red[idx * 2] = s8[ri]; red[idx * 2 + 1] = q8[ri];
            }
        }
        __syncthreads();
        #pragma unroll
        for (int ri = 0; ri < 8; ri++) {
            const int idx = (((wr * 4 + (wc ^ 1)) * 8) + ri) * 8 + (lane >> 2);
            const float ts = s8[ri] + red[idx * 2];
            const float tq = q8[ri] + red[idx * 2 + 1];
            const float mu = ts * (1.f / 64.f);
            mean[ri] = mu;
            inv[ri] = rsqrtf(fmaxf(tq * (1.f / 64.f) - mu * mu, 0.f) + 1e-5f);
        }

        const int isK = (bx < 4);
        const int g = (isK ? bx : bx - 4) * 2 + (wc >> 1);
        const int half = wc & 1;
        const int lq = lane & 3;
        __nv_bfloat16* base0 = Cb + (isK ? 0 : 2 * PL);
        #pragma unroll
        for (int mf = 0; mf < 4; mf++)
            #pragma unroll
            for (int rb = 0; rb < 2; rb++) {
                const int ri = mf * 2 + rb;
                const int m = m0 + wr * 64 + mf * 16 + (lane >> 2) + rb * 8;
                const int bb = m >> 12, tt = m & 4095;
                const size_t rowoff = ((size_t)(bb * 8 + g) * 4096 + tt) * 64;
                const float mu = mean[ri], iv = inv[ri];
                if (isK) {
                    const float pp = z_pos[(size_t)m * 2 + half] * 64.f;
                    #pragma unroll
                    for (int nf2 = 0; nf2 < 2; nf2++) {
                        float o[4];
                        #pragma unroll
                        for (int cb = 0; cb < 2; cb++) {
                            const int j = nf2 * 8 + lq * 2 + cb;
                            const float invf = exp2f(-(float)j * (13.287712379549449f / 16.f));
                            float sn, co; sincosf(pp * invf, &sn, &co);
                            const float vlo = (acc[mf][nf2][rb * 2 + cb]     - mu) * iv;
                            const float vhi = (acc[mf][nf2 + 2][rb * 2 + cb] - mu) * iv;
                            o[cb]     = vlo * co - vhi * sn;
                            o[2 + cb] = vhi * co + vlo * sn;
                        }
                        const int cg = half * 32 + nf2 * 8 + lq * 2;
                        __nv_bfloat16 h0, l0, h1, l1;
                        split1(o[0], h0, l0); split1(o[1], h1, l1);
                        *(__nv_bfloat162*)&base0[rowoff + cg]      = __nv_bfloat162{h0, h1};
                        *(__nv_bfloat162*)&base0[PL + rowoff + cg] = __nv_bfloat162{l0, l1};
                        split1(o[2], h0, l0); split1(o[3], h1, l1);
                        *(__nv_bfloat162*)&base0[rowoff + cg + 16]      = __nv_bfloat162{h0, h1};
                        *(__nv_bfloat162*)&base0[PL + rowoff + cg + 16] = __nv_bfloat162{l0, l1};
                    }
                } else {
                    #pragma unroll
                    for (int nf = 0; nf < 4; nf++) {
                        const int cg = half * 32 + nf * 8 + lq * 2;
                        const float a0 = (acc[mf][nf][rb * 2]     - mu) * iv;
                        const float a1 = (acc[mf][nf][rb * 2 + 1] - mu) * iv;
                        __nv_bfloat16 h0, l0, h1, l1;
                        split1(a0, h0, l0); split1(a1, h1, l1);
                        *(__nv_bfloat162*)&base0[rowoff + cg]      = __nv_bfloat162{h0, h1};
                        *(__nv_bfloat162*)&base0[PL + rowoff + cg] = __nv_bfloat162{l0, l1};
                    }
                }
            }
    } else {
        // q branch: rotary + single fp16 plane store -> Cq [M, 512]
        const int half = wc & 1;
        const int lq = lane & 3;
        #pragma unroll
        for (int mf = 0; mf < 4; mf++) {
            #pragma unroll
            for (int rb = 0; rb < 2; rb++) {
                const int r = m0 + wr * 64 + mf * 16 + (lane >> 2) + rb * 8;
                const float pp = x_pos[(size_t)r * 2 + half] * 64.f;
                const size_t rowb = (size_t)r * 512;
                #pragma unroll
                for (int nf2 = 0; nf2 < 2; nf2++) {
                    float o[4];
                    #pragma unroll
                    for (int cb = 0; cb < 2; cb++) {
                        const int j = nf2 * 8 + lq * 2 + cb;
                        const float invf = exp2f(-(float)j * (13.287712379549449f / 16.f));
                        float s, co; sincosf(pp * invf, &s, &co);
                        const int idx = rb * 2 + cb;
                        const float vlo = acc[mf][nf2][idx];
                        const float vhi = acc[mf][nf2 + 2][idx];
                        o[cb]     = vlo * co - vhi * s;
                        o[2 + cb] = vhi * co + vlo * s;
                    }
                    const int cg = n0 + wc * 32 + nf2 * 8 + lq * 2;
                    *(__half2*)&Cq[rowb + cg] =
                        __half2{__float2half_rn(o[0]), __float2half_rn(o[1])};
                    *(__half2*)&Cq[rowb + cg + 16] =
                        __half2{__float2half_rn(o[2]), __float2half_rn(o[3])};
                }
            }
        }
    }
}

// ---------------- epilogue GEMM: out[b] = q2[b] @ W2s[b]^T + bout (single fp16 plane) ----
__global__ __launch_bounds__(256, 2) void gemm_epi(
    const __half* __restrict__ A2, const __half* __restrict__ B2,
    float* __restrict__ C, const float* __restrict__ bias)
{
    extern __shared__ __align__(1024) char smem[];
    A2 += (size_t)blockIdx.z * ((long)NTOKS * 512);
    B2 += (size_t)blockIdx.z * ((long)256 * 512);
    C  += (size_t)blockIdx.z * ((long)NTOKS * 256);
    const int m0 = blockIdx.y * 128, n0 = blockIdx.x * 128;
    const int tid = threadIdx.x, lane = tid & 31, wid = tid >> 5;
    const int wr = wid >> 2, wc = wid & 3;
    const u32 sb = smem_u32(smem);

    const int K2 = 512, total = 16;
    const int lrow = tid >> 1;
    const int lcg = (tid & 1) * 2;

    float acc[4][4][4];
    #pragma unroll
    for (int i = 0; i < 4; i++)
        #pragma unroll
        for (int j = 0; j < 4; j++)
            #pragma unroll
            for (int r = 0; r < 4; r++) acc[i][j][r] = 0.f;

    auto issue = [&](int it) {
        const int stage = it & (NSTAGE - 1);
        const int kk = it * 32;
        const __half* as = A2 + (size_t)(m0 + lrow) * K2 + kk + lcg * 8;
        const __half* bs = B2 + (size_t)(n0 + lrow) * K2 + kk + lcg * 8;
        const u32 da = sb + stage * STAGEB + lrow * ROWB + lcg * 16;
        cpa16(da, as);              cpa16(da + 16, as + 8);
        cpa16(da + TILEB, bs);      cpa16(da + TILEB + 16, bs + 8);
        CP_COMMIT();
    };

    auto compute = [&](int stage) {
        const u32 ab = sb + stage * STAGEB;
        const u32 bb = ab + TILEB;
        #pragma unroll
        for (int kb = 0; kb < 2; kb++) {
            u32 a[4][4], b[2][4];
            #pragma unroll
            for (int mf = 0; mf < 4; mf++) {
                u32 addr = ab + (u32)(wr * 64 + mf * 16 + (lane & 15)) * ROWB
                              + kb * 32 + (lane >> 4) * 16;
                ldsm4(a[mf], addr);
            }
            #pragma unroll
            for (int nfp = 0; nfp < 2; nfp++) {
                u32 addr = bb + (u32)(wc * 32 + nfp * 16 + ((lane >> 4) << 3) + (lane & 7)) * ROWB
                              + kb * 32 + ((lane >> 3) & 1) * 16;
                ldsm4(b[nfp], addr);
            }
            #pragma unroll
            for (int mf = 0; mf < 4; mf++)
                #pragma unroll
                for (int nf = 0; nf < 4; nf++)
                    mma16816h(acc[mf][nf], a[mf], &b[nf >> 1][(nf & 1) * 2]);
        }
    };

    issue(0); issue(1); issue(2);
    for (int i = 0; i < total; i++) {
        if (i < total - 2)       CP_WAIT(2);
        else if (i == total - 2) CP_WAIT(1);
        else                     CP_WAIT(0);
        __syncthreads();
        compute(i & (NSTAGE - 1));
        if (i + 3 < total) issue(i + 3);
    }

    const int rbase = m0 + wr * 64 + (lane >> 2);
    const int cbase = n0 + wc * 32 + (lane & 3) * 2;
    #pragma unroll
    for (int nf = 0; nf < 4; nf++) {
        const int c = cbase + nf * 8;
        const float bx = bias[c], by = bias[c + 1];
        #pragma unroll
        for (int mf = 0; mf < 4; mf++) {
            const int r = rbase + mf * 16;
            *(float2*)&C[(size_t)r * 256 + c] =
                make_float2(acc[mf][nf][0] + bx, acc[mf][nf][1] + by);
            *(float2*)&C[(size_t)(r + 8) * 256 + c] =
                make_float2(acc[mf][nf][2] + bx, acc[mf][nf][3] + by);
        }
    }
}

// ---------------- dots: pure streaming bf16 3-term Gram MMA ----------------
#define DROWB 144
#define DTILE (64 * DROWB)       // 9216
#define DSTG4 (4 * DTILE)        // 36864
#define DSM_BYTES (2 * DSTG4)    // 73728

__global__ __launch_bounds__(256, 2) void dots_pure(const __nv_bfloat16* __restrict__ kvs,
                                                    float* __restrict__ part) {
    extern __shared__ __align__(1024) char dsm[];
    const u32 sb = smem_u32(dsm);

    const int split = blockIdx.x;
    const int bh = blockIdx.y;
    const int tid = threadIdx.x;
    const int w = tid >> 5, lane = tid & 31;
    const int wr = w >> 1, wc = w & 1;

    float acc[4][4];
    #pragma unroll
    for (int i = 0; i < 4; i++)
        #pragma unroll
        for (int j = 0; j < 4; j++) acc[i][j] = 0.f;

    auto issue = [&](int c) {
        const int t0 = split * 256 + c * 64;
        const u32 sbase = sb + (c & 1) * DSTG4;
        #pragma unroll
        for (int i = 0; i < 8; i++) {
            const int idx = i * 256 + tid;
            const int plane = idx >> 9;
            const int r = (idx >> 3) & 63;
            const int seg = idx & 7;
            const __nv_bfloat16* src = kvs + (size_t)plane * PL
                + ((size_t)bh * 4096 + t0 + r) * 64 + seg * 8;
            cpa16(sbase + plane * DTILE + r * DROWB + seg * 16, src);
        }
        CP_COMMIT();
    };

    issue(0);
    for (int c = 0; c < 4; c++) {
        if (c < 3) { issue(c + 1); CP_WAIT(1); } else { CP_WAIT(0); }
        __syncthreads();
        const u32 khb = sb + (c & 1) * DSTG4;
        const u32 klb = khb + DTILE;
        const u32 vhb = khb + 2 * DTILE;
        const u32 vlb = khb + 3 * DTILE;
        #pragma unroll
        for (int kt = 0; kt < 4; kt++) {
            const u32 arow = (u32)(kt * 16 + (lane & 7) + ((lane >> 4) << 3));
            const u32 acol = (u32)(wr * 16 + ((lane >> 3) & 1) * 8);
            const u32 aoff = arow * DROWB + acol * 2;
            u32 ah[4], al[4];
            ldsm4t(ah, khb + aoff);
            ldsm4t(al, klb + aoff);
            const u32 brow = (u32)(kt * 16 + (lane & 7) + ((lane >> 3) & 1) * 8);
            const u32 bcol = (u32)(wc * 32 + ((lane >> 4) << 3));
            const u32 boff = brow * DROWB + bcol * 2;
            u32 bh0[4], bl0[4], bh1[4], bl1[4];
            ldsm4t(bh0, vhb + boff);
            ldsm4t(bl0, vlb + boff);
            ldsm4t(bh1, vhb + boff + 32);
            ldsm4t(bl1, vlb + boff + 32);
            mma16816(acc[0], ah, &bh0[0]); mma16816(acc[0], al, &bh0[0]); mma16816(acc[0], ah, &bl0[0]);
            mma16816(acc[1], ah, &bh0[2]); mma16816(acc[1], al, &bh0[2]); mma16816(acc[1], ah, &bl0[2]);
            mma16816(acc[2], ah, &bh1[0]); mma16816(acc[2], al, &bh1[0]); mma16816(acc[2], ah, &bl1[0]);
            mma16816(acc[3], ah, &bh1[2]); mma16816(acc[3], al, &bh1[2]); mma16816(acc[3], ah, &bl1[2]);
        }
        __syncthreads();
    }

    float* dst = part + ((size_t)bh * NSPLIT + split) * 4096;
    const int dr = wr * 16 + (lane >> 2);
    const int ec = wc * 32 + (lane & 3) * 2;
    #pragma unroll
    for (int nf = 0; nf < 4; nf++) {
        *(float2*)&dst[(size_t)dr * 64 + ec + nf * 8]       = make_float2(acc[nf][0], acc[nf][1]);
        *(float2*)&dst[(size_t)(dr + 8) * 64 + ec + nf * 8] = make_float2(acc[nf][2], acc[nf][3]);
    }
}

// ---------------- W2s[b][c][.] = fp16( ((sum dots)/n2 @ Wout)^T ), single plane ----------
__global__ __launch_bounds__(256) void w2k(const float* __restrict__ part, const float* __restrict__ Wout,
                                           __half* __restrict__ W2s) {
    const int bh = blockIdx.x, dhalf = blockIdx.y;
    const int b = bh >> 3, h = bh & 7;
    __shared__ float ds[2048];
    const int tid = threadIdx.x;
    #pragma unroll
    for (int j = 0; j < 8; j++) {
        int idx = j * 256 + tid;
        int dr = idx >> 6, e = idx & 63;
        float s = 0.f;
        #pragma unroll
        for (int sp = 0; sp < NSPLIT; sp++)
            s += part[((size_t)bh * NSPLIT + sp) * 4096 + (dhalf * 32 + dr) * 64 + e];
        ds[idx] = s * (1.f / 4096.f);
    }
    __syncthreads();

    const int p = tid & 127, g = tid >> 7;
    u64 acc[16];
    #pragma unroll
    for (int d = 0; d < 16; d++) acc[d] = 0ull;
    for (int e = 0; e < 64; e++) {
        u64 w2 = *(const u64*)&Wout[(size_t)(h * 64 + e) * 256 + 2 * p];
        const float* dsr = &ds[(g * 16) * 64 + e];
        #pragma unroll
        for (int d = 0; d < 16; d++) {
            float val = dsr[d * 64];
            acc[d] = ffma2(pack2(val, val), w2, acc[d]);
        }
    }
    #pragma unroll
    for (int d = 0; d < 16; d++) {
        float o0, o1; unpack2(acc[d], o0, o1);
        const int dg = h * 64 + dhalf * 32 + g * 16 + d;
        size_t r0 = ((size_t)b * 256 + 2 * p) * 512;
        W2s[r0 + dg]       = __float2half_rn(o0);
        W2s[r0 + 512 + dg] = __float2half_rn(o1);
    }
}

// ---------------- launch ----------------
extern "C" void kernel_launch(void* const* d_in, const int* in_sizes, int n_in,
                              void* d_out, int out_size) {
    const float* x     = (const float*)d_in[0];
    const float* z     = (const float*)d_in[1];
    const float* x_pos = (const float*)d_in[2];
    const float* z_pos = (const float*)d_in[3];
    const float* Wq    = (const float*)d_in[4];
    const float* Wkv   = (const float*)d_in[5];
    const float* Wout  = (const float*)d_in[6];
    const float* bout  = (const float*)d_in[7];
    float* out = (float*)d_out;

    float* dotp;
    __nv_bfloat16* kvs;
    __half *z2, *x2, *wkv2, *wq2, *q2, *w2s;
    cudaGetSymbolAddress((void**)&kvs,  g_kvs);
    cudaGetSymbolAddress((void**)&dotp, g_dotp);
    cudaGetSymbolAddress((void**)&z2,   g_z2);
    cudaGetSymbolAddress((void**)&x2,   g_x2);
    cudaGetSymbolAddress((void**)&wkv2, g_wkv2);
    cudaGetSymbolAddress((void**)&wq2,  g_wq2);
    cudaGetSymbolAddress((void**)&q2,   g_q2);
    cudaGetSymbolAddress((void**)&w2s,  g_w2s);

    cudaFuncSetAttribute(gemm_main, cudaFuncAttributeMaxDynamicSharedMemorySize, GSMEM);
    cudaFuncSetAttribute(gemm_epi,  cudaFuncAttributeMaxDynamicSharedMemorySize, GSMEM);
    cudaFuncSetAttribute(dots_pure, cudaFuncAttributeMaxDynamicSharedMemorySize, DSM_BYTES);

    // one prep launch: splits of z, x, Wkv, Wq
    prep<<<17920, 256>>>(z, x, Wkv, Wq, z2, x2, wkv2, wq2);

    // kv GEMM (norm+rot+bf16 planes) and q GEMM (rot+fp16) in one launch
    gemm_main<<<dim3(12, 256), 256, GSMEM>>>(z2, wkv2, x2, wq2, kvs, q2, z_pos, x_pos);

    // Gram partials + W2
    dots_pure<<<dim3(NSPLIT, 64), 256, DSM_BYTES>>>(kvs, dotp);
    w2k<<<dim3(64, 2), 256>>>(dotp, Wout, w2s);

    // out[b] = q2[b] @ W2s[b]^T + bout
    gemm_epi<<<dim3(2, 32, BATCH), 256, GSMEM>>>(q2, w2s, out, bout);
}

// round 12
// speedup vs baseline: 2.0910x; 1.2829x over previous
#include <cuda_runtime.h>
#include <cuda_bf16.h>
#include <cuda_fp16.h>
#include <math.h>
#include <cstdint>

typedef unsigned long long u64;
typedef unsigned int u32;

#define HEADS 8
#define NDIM  256
#define INNER 512
#define NTOKS 4096
#define BATCH 8
#define MTOT  (BATCH * NTOKS)   // 32768
#define NSPLIT 16
#define PL ((size_t)64 * 4096 * 64)   // one bf16 plane: [b*8+h][t][64]

// ---------------- scratch (device globals: allocation-guard safe) ----------------
__device__ __nv_bfloat16 g_kvs [(size_t)4 * PL];     // planes: kh, kl, vh, vl
__device__ float g_dotp[(size_t)64 * NSPLIT * 64 * 64];
__device__ __half g_z2  [(size_t)MTOT * 256];        // z: single fp16 plane
__device__ __half g_x2  [(size_t)MTOT * 256];
__device__ __half g_wkv2[(size_t)1024 * 256];        // Wkv^T fp16
__device__ __half g_wq2 [(size_t)512 * 256];         // Wq^T fp16
__device__ __half g_q2  [(size_t)MTOT * 512];        // q rot fp16 [M, INNER]
__device__ __half g_w2s [(size_t)BATCH * 256 * 512]; // W2^T fp16

// ---------------- MMA / async helpers ----------------
__device__ __forceinline__ u32 smem_u32(const void* p) {
    u32 a; asm("{ .reg .u64 t; cvta.to.shared.u64 t, %1; cvt.u32.u64 %0, t; }" : "=r"(a) : "l"(p));
    return a;
}
__device__ __forceinline__ void cpa16(u32 dst, const void* src) {
    asm volatile("cp.async.cg.shared.global [%0], [%1], 16;" :: "r"(dst), "l"(src));
}
#define CP_COMMIT() asm volatile("cp.async.commit_group;" ::: "memory")
#define CP_WAIT(n)  asm volatile("cp.async.wait_group %0;" :: "n"(n) : "memory")

__device__ __forceinline__ void ldsm4(u32* r, u32 a) {
    asm volatile("ldmatrix.sync.aligned.m8n8.x4.shared.b16 {%0,%1,%2,%3}, [%4];"
        : "=r"(r[0]), "=r"(r[1]), "=r"(r[2]), "=r"(r[3]) : "r"(a));
}
__device__ __forceinline__ void ldsm4t(u32* r, u32 a) {
    asm volatile("ldmatrix.sync.aligned.m8n8.x4.trans.shared.b16 {%0,%1,%2,%3}, [%4];"
        : "=r"(r[0]), "=r"(r[1]), "=r"(r[2]), "=r"(r[3]) : "r"(a));
}
__device__ __forceinline__ void mma16816h(float* c, const u32* a, const u32* b) {
    asm volatile("mma.sync.aligned.m16n8k16.row.col.f32.f16.f16.f32 "
        "{%0,%1,%2,%3}, {%4,%5,%6,%7}, {%8,%9}, {%0,%1,%2,%3};"
        : "+f"(c[0]), "+f"(c[1]), "+f"(c[2]), "+f"(c[3])
        : "r"(a[0]), "r"(a[1]), "r"(a[2]), "r"(a[3]), "r"(b[0]), "r"(b[1]));
}
__device__ __forceinline__ void mma16816(float* c, const u32* a, const u32* b) {
    asm volatile("mma.sync.aligned.m16n8k16.row.col.f32.bf16.bf16.f32 "
        "{%0,%1,%2,%3}, {%4,%5,%6,%7}, {%8,%9}, {%0,%1,%2,%3};"
        : "+f"(c[0]), "+f"(c[1]), "+f"(c[2]), "+f"(c[3])
        : "r"(a[0]), "r"(a[1]), "r"(a[2]), "r"(a[3]), "r"(b[0]), "r"(b[1]));
}

// ---------------- f32x2 helpers ----------------
__device__ __forceinline__ u64 pack2(float x, float y) {
    u64 r; asm("mov.b64 %0, {%1,%2};" : "=l"(r) : "f"(x), "f"(y)); return r;
}
__device__ __forceinline__ u64 ffma2(u64 a, u64 b, u64 c) {
    u64 d; asm("fma.rn.f32x2 %0, %1, %2, %3;" : "=l"(d) : "l"(a), "l"(b), "l"(c)); return d;
}
__device__ __forceinline__ void unpack2(u64 v, float& x, float& y) {
    asm("mov.b64 {%0,%1}, %2;" : "=f"(x), "=f"(y) : "l"(v));
}

// ---------------- split helper (dots planes only) ----------------
__device__ __forceinline__ void split1(float v, __nv_bfloat16& h, __nv_bfloat16& l) {
    h = __float2bfloat16(v);
    l = __float2bfloat16(v - __bfloat162float(h));
}

// ---------------- unified prep: fp16 convert z, x (rows) + Wkv, Wq (transpose) ----------
// blocks: [0,8192) z, [8192,16384) x, [16384,17408) Wkv cols, [17408,17920) Wq cols
__global__ void prep(const float* __restrict__ z, const float* __restrict__ x,
                     const float* __restrict__ Wkv, const float* __restrict__ Wq,
                     __half* __restrict__ z2, __half* __restrict__ x2,
                     __half* __restrict__ wkv2, __half* __restrict__ wq2) {
    const int bid = blockIdx.x;
    const int tid = threadIdx.x;
    if (bid < 16384) {
        const float* in = (bid < 8192) ? z : x;
        __half* out = (bid < 8192) ? z2 : x2;
        size_t idx = (size_t)(bid & 8191) * 256 + tid;     // one float4
        float4 v = ((const float4*)in)[idx];
        __half2 p0 = __half2{__float2half_rn(v.x), __float2half_rn(v.y)};
        __half2 p1 = __half2{__float2half_rn(v.z), __float2half_rn(v.w)};
        __half2* dst = (__half2*)(out + idx * 4);
        dst[0] = p0; dst[1] = p1;
    } else {
        const int isKv = (bid < 17408);
        const int n = isKv ? (bid - 16384) : (bid - 17408);
        const int N = isKv ? 1024 : 512;
        const float* W = isKv ? Wkv : Wq;
        __half* out = isKv ? wkv2 : wq2;
        out[(size_t)n * 256 + tid] = __float2half_rn(W[(size_t)tid * N + n]);
    }
}

// ---------------- main GEMM (K2=256): kv (norm+rot+bf16 planes) and q (rot+fp16) -------
// grid (12, 256): bx<8 -> kv GEMM CTA (N=1024), bx>=8 -> q GEMM CTA (N=512).
#define ROWB 80
#define TILEB (128 * ROWB)
#define STAGEB (2 * TILEB)
#define NSTAGE 4
#define GSMEM (NSTAGE * STAGEB)

__global__ __launch_bounds__(256, 2) void gemm_main(
    const __half* __restrict__ z2, const __half* __restrict__ wkv2,
    const __half* __restrict__ x2, const __half* __restrict__ wq2,
    __nv_bfloat16* __restrict__ Cb, __half* __restrict__ Cq,
    const float* __restrict__ z_pos, const float* __restrict__ x_pos)
{
    extern __shared__ __align__(1024) char smem[];
    const int bx = blockIdx.x;
    const int isKv = (bx < 8);
    const __half* A2 = isKv ? z2 : x2;
    const __half* B2 = isKv ? wkv2 : wq2;
    const int n0 = (isKv ? bx : bx - 8) * 128;
    const int m0 = blockIdx.y * 128;
    const int tid = threadIdx.x, lane = tid & 31, wid = tid >> 5;
    const int wr = wid >> 2, wc = wid & 3;
    const u32 sb = smem_u32(smem);

    const int K2 = 256, total = 8;
    const int lrow = tid >> 1;
    const int lcg = (tid & 1) * 2;

    float acc[4][4][4];
    #pragma unroll
    for (int i = 0; i < 4; i++)
        #pragma unroll
        for (int j = 0; j < 4; j++)
            #pragma unroll
            for (int r = 0; r < 4; r++) acc[i][j][r] = 0.f;

    auto issue = [&](int it) {
        const int stage = it & (NSTAGE - 1);
        const int kk = it * 32;
        const __half* as = A2 + (size_t)(m0 + lrow) * K2 + kk + lcg * 8;
        const __half* bs = B2 + (size_t)(n0 + lrow) * K2 + kk + lcg * 8;
        const u32 da = sb + stage * STAGEB + lrow * ROWB + lcg * 16;
        cpa16(da, as);              cpa16(da + 16, as + 8);
        cpa16(da + TILEB, bs);      cpa16(da + TILEB + 16, bs + 8);
        CP_COMMIT();
    };

    auto compute = [&](int stage) {
        const u32 ab = sb + stage * STAGEB;
        const u32 bb = ab + TILEB;
        #pragma unroll
        for (int kb = 0; kb < 2; kb++) {
            u32 a[4][4], b[2][4];
            #pragma unroll
            for (int mf = 0; mf < 4; mf++) {
                u32 addr = ab + (u32)(wr * 64 + mf * 16 + (lane & 15)) * ROWB
                              + kb * 32 + (lane >> 4) * 16;
                ldsm4(a[mf], addr);
            }
            #pragma unroll
            for (int nfp = 0; nfp < 2; nfp++) {
                u32 addr = bb + (u32)(wc * 32 + nfp * 16 + ((lane >> 4) << 3) + (lane & 7)) * ROWB
                              + kb * 32 + ((lane >> 3) & 1) * 16;
                ldsm4(b[nfp], addr);
            }
            #pragma unroll
            for (int mf = 0; mf < 4; mf++)
                #pragma unroll
                for (int nf = 0; nf < 4; nf++)
                    mma16816h(acc[mf][nf], a[mf], &b[nf >> 1][(nf & 1) * 2]);
        }
    };

    issue(0); issue(1); issue(2);
    for (int i = 0; i < total; i++) {
        if (i < total - 2)       CP_WAIT(2);
        else if (i == total - 2) CP_WAIT(1);
        else                     CP_WAIT(0);
        __syncthreads();
        compute(i & (NSTAGE - 1));
        if (i + 3 < total) issue(i + 3);
    }

    if (isKv) {
        // per-head instance norm (+rotary on k) + bf16 split -> planes.
        __syncthreads();
        float* red = (float*)smem;
        float s8[8], q8[8], mean[8], inv[8];
        #pragma unroll
        for (int mf = 0; mf < 4; mf++)
            #pragma unroll
            for (int rb = 0; rb < 2; rb++) {
                const int ri = mf * 2 + rb;
                float s = 0.f, q = 0.f;
                #pragma unroll
                for (int nf = 0; nf < 4; nf++)
                    #pragma unroll
                    for (int cb = 0; cb < 2; cb++) {
                        float a = acc[mf][nf][rb * 2 + cb];
                        s += a; q += a * a;
                    }
                s += __shfl_xor_sync(0xffffffffu, s, 1); q += __shfl_xor_sync(0xffffffffu, q, 1);
                s += __shfl_xor_sync(0xffffffffu, s, 2); q += __shfl_xor_sync(0xffffffffu, q, 2);
                s8[ri] = s; q8[ri] = q;
            }
        if ((lane & 3) == 0) {
            #pragma unroll
            for (int ri = 0; ri < 8; ri++) {
                const int idx = (((wr * 4 + wc) * 8) + ri) * 8 + (lane >> 2);
                red[idx * 2] = s8[ri]; red[idx * 2 + 1] = q8[ri];
            }
        }
        __syncthreads();
        #pragma unroll
        for (int ri = 0; ri < 8; ri++) {
            const int idx = (((wr * 4 + (wc ^ 1)) * 8) + ri) * 8 + (lane >> 2);
            const float ts = s8[ri] + red[idx * 2];
            const float tq = q8[ri] + red[idx * 2 + 1];
            const float mu = ts * (1.f / 64.f);
            mean[ri] = mu;
            inv[ri] = rsqrtf(fmaxf(tq * (1.f / 64.f) - mu * mu, 0.f) + 1e-5f);
        }

        const int isK = (bx < 4);
        const int g = (isK ? bx : bx - 4) * 2 + (wc >> 1);
        const int half = wc & 1;
        const int lq = lane & 3;
        __nv_bfloat16* base0 = Cb + (isK ? 0 : 2 * PL);
        #pragma unroll
        for (int mf = 0; mf < 4; mf++)
            #pragma unroll
            for (int rb = 0; rb < 2; rb++) {
                const int ri = mf * 2 + rb;
                const int m = m0 + wr * 64 + mf * 16 + (lane >> 2) + rb * 8;
                const int bb = m >> 12, tt = m & 4095;
                const size_t rowoff = ((size_t)(bb * 8 + g) * 4096 + tt) * 64;
                const float mu = mean[ri], iv = inv[ri];
                if (isK) {
                    const float pp = z_pos[(size_t)m * 2 + half] * 64.f;
                    #pragma unroll
                    for (int nf2 = 0; nf2 < 2; nf2++) {
                        float o[4];
                        #pragma unroll
                        for (int cb = 0; cb < 2; cb++) {
                            const int j = nf2 * 8 + lq * 2 + cb;
                            const float invf = exp2f(-(float)j * (13.287712379549449f / 16.f));
                            float sn, co; sincosf(pp * invf, &sn, &co);
                            const float vlo = (acc[mf][nf2][rb * 2 + cb]     - mu) * iv;
                            const float vhi = (acc[mf][nf2 + 2][rb * 2 + cb] - mu) * iv;
                            o[cb]     = vlo * co - vhi * sn;
                            o[2 + cb] = vhi * co + vlo * sn;
                        }
                        const int cg = half * 32 + nf2 * 8 + lq * 2;
                        __nv_bfloat16 h0, l0, h1, l1;
                        split1(o[0], h0, l0); split1(o[1], h1, l1);
                        *(__nv_bfloat162*)&base0[rowoff + cg]      = __nv_bfloat162{h0, h1};
                        *(__nv_bfloat162*)&base0[PL + rowoff + cg] = __nv_bfloat162{l0, l1};
                        split1(o[2], h0, l0); split1(o[3], h1, l1);
                        *(__nv_bfloat162*)&base0[rowoff + cg + 16]      = __nv_bfloat162{h0, h1};
                        *(__nv_bfloat162*)&base0[PL + rowoff + cg + 16] = __nv_bfloat162{l0, l1};
                    }
                } else {
                    #pragma unroll
                    for (int nf = 0; nf < 4; nf++) {
                        const int cg = half * 32 + nf * 8 + lq * 2;
                        const float a0 = (acc[mf][nf][rb * 2]     - mu) * iv;
                        const float a1 = (acc[mf][nf][rb * 2 + 1] - mu) * iv;
                        __nv_bfloat16 h0, l0, h1, l1;
                        split1(a0, h0, l0); split1(a1, h1, l1);
                        *(__nv_bfloat162*)&base0[rowoff + cg]      = __nv_bfloat162{h0, h1};
                        *(__nv_bfloat162*)&base0[PL + rowoff + cg] = __nv_bfloat162{l0, l1};
                    }
                }
            }
    } else {
        // q branch: rotary + fp16 store -> Cq [M, 512]
        const int half = wc & 1;
        const int lq = lane & 3;
        #pragma unroll
        for (int mf = 0; mf < 4; mf++) {
            #pragma unroll
            for (int rb = 0; rb < 2; rb++) {
                const int r = m0 + wr * 64 + mf * 16 + (lane >> 2) + rb * 8;
                const float pp = x_pos[(size_t)r * 2 + half] * 64.f;
                const size_t rowb = (size_t)r * 512;
                #pragma unroll
                for (int nf2 = 0; nf2 < 2; nf2++) {
                    float o[4];
                    #pragma unroll
                    for (int cb = 0; cb < 2; cb++) {
                        const int j = nf2 * 8 + lq * 2 + cb;
                        const float invf = exp2f(-(float)j * (13.287712379549449f / 16.f));
                        float s, co; sincosf(pp * invf, &s, &co);
                        const int idx = rb * 2 + cb;
                        const float vlo = acc[mf][nf2][idx];
                        const float vhi = acc[mf][nf2 + 2][idx];
                        o[cb]     = vlo * co - vhi * s;
                        o[2 + cb] = vhi * co + vlo * s;
                    }
                    const int cg = n0 + wc * 32 + nf2 * 8 + lq * 2;
                    *(__half2*)&Cq[rowb + cg] =
                        __half2{__float2half_rn(o[0]), __float2half_rn(o[1])};
                    *(__half2*)&Cq[rowb + cg + 16] =
                        __half2{__float2half_rn(o[2]), __float2half_rn(o[3])};
                }
            }
        }
    }
}

// ---------------- epilogue GEMM: out[b] = q2[b] @ W2s[b]^T + bout ----------------------
__global__ __launch_bounds__(256, 2) void gemm_epi(
    const __half* __restrict__ A2, const __half* __restrict__ B2,
    float* __restrict__ C, const float* __restrict__ bias)
{
    extern __shared__ __align__(1024) char smem[];
    A2 += (size_t)blockIdx.z * ((long)NTOKS * 512);
    B2 += (size_t)blockIdx.z * ((long)256 * 512);
    C  += (size_t)blockIdx.z * ((long)NTOKS * 256);
    const int m0 = blockIdx.y * 128, n0 = blockIdx.x * 128;
    const int tid = threadIdx.x, lane = tid & 31, wid = tid >> 5;
    const int wr = wid >> 2, wc = wid & 3;
    const u32 sb = smem_u32(smem);

    const int K2 = 512, total = 16;
    const int lrow = tid >> 1;
    const int lcg = (tid & 1) * 2;

    float acc[4][4][4];
    #pragma unroll
    for (int i = 0; i < 4; i++)
        #pragma unroll
        for (int j = 0; j < 4; j++)
            #pragma unroll
            for (int r = 0; r < 4; r++) acc[i][j][r] = 0.f;

    auto issue = [&](int it) {
        const int stage = it & (NSTAGE - 1);
        const int kk = it * 32;
        const __half* as = A2 + (size_t)(m0 + lrow) * K2 + kk + lcg * 8;
        const __half* bs = B2 + (size_t)(n0 + lrow) * K2 + kk + lcg * 8;
        const u32 da = sb + stage * STAGEB + lrow * ROWB + lcg * 16;
        cpa16(da, as);              cpa16(da + 16, as + 8);
        cpa16(da + TILEB, bs);      cpa16(da + TILEB + 16, bs + 8);
        CP_COMMIT();
    };

    auto compute = [&](int stage) {
        const u32 ab = sb + stage * STAGEB;
        const u32 bb = ab + TILEB;
        #pragma unroll
        for (int kb = 0; kb < 2; kb++) {
            u32 a[4][4], b[2][4];
            #pragma unroll
            for (int mf = 0; mf < 4; mf++) {
                u32 addr = ab + (u32)(wr * 64 + mf * 16 + (lane & 15)) * ROWB
                              + kb * 32 + (lane >> 4) * 16;
                ldsm4(a[mf], addr);
            }
            #pragma unroll
            for (int nfp = 0; nfp < 2; nfp++) {
                u32 addr = bb + (u32)(wc * 32 + nfp * 16 + ((lane >> 4) << 3) + (lane & 7)) * ROWB
                              + kb * 32 + ((lane >> 3) & 1) * 16;
                ldsm4(b[nfp], addr);
            }
            #pragma unroll
            for (int mf = 0; mf < 4; mf++)
                #pragma unroll
                for (int nf = 0; nf < 4; nf++)
                    mma16816h(acc[mf][nf], a[mf], &b[nf >> 1][(nf & 1) * 2]);
        }
    };

    issue(0); issue(1); issue(2);
    for (int i = 0; i < total; i++) {
        if (i < total - 2)       CP_WAIT(2);
        else if (i == total - 2) CP_WAIT(1);
        else                     CP_WAIT(0);
        __syncthreads();
        compute(i & (NSTAGE - 1));
        if (i + 3 < total) issue(i + 3);
    }

    const int rbase = m0 + wr * 64 + (lane >> 2);
    const int cbase = n0 + wc * 32 + (lane & 3) * 2;
    #pragma unroll
    for (int nf = 0; nf < 4; nf++) {
        const int c = cbase + nf * 8;
        const float bx = bias[c], by = bias[c + 1];
        #pragma unroll
        for (int mf = 0; mf < 4; mf++) {
            const int r = rbase + mf * 16;
            *(float2*)&C[(size_t)r * 256 + c] =
                make_float2(acc[mf][nf][0] + bx, acc[mf][nf][1] + by);
            *(float2*)&C[(size_t)(r + 8) * 256 + c] =
                make_float2(acc[mf][nf][2] + bx, acc[mf][nf][3] + by);
        }
    }
}

// ---------------- dots: pure streaming bf16 3-term Gram MMA ----------------
#define DROWB 144
#define DTILE (64 * DROWB)
#define DSTG4 (4 * DTILE)
#define DSM_BYTES (2 * DSTG4)

__global__ __launch_bounds__(256, 2) void dots_pure(const __nv_bfloat16* __restrict__ kvs,
                                                    float* __restrict__ part) {
    extern __shared__ __align__(1024) char dsm[];
    const u32 sb = smem_u32(dsm);

    const int split = blockIdx.x;
    const int bh = blockIdx.y;
    const int tid = threadIdx.x;
    const int w = tid >> 5, lane = tid & 31;
    const int wr = w >> 1, wc = w & 1;

    float acc[4][4];
    #pragma unroll
    for (int i = 0; i < 4; i++)
        #pragma unroll
        for (int j = 0; j < 4; j++) acc[i][j] = 0.f;

    auto issue = [&](int c) {
        const int t0 = split * 256 + c * 64;
        const u32 sbase = sb + (c & 1) * DSTG4;
        #pragma unroll
        for (int i = 0; i < 8; i++) {
            const int idx = i * 256 + tid;
            const int plane = idx >> 9;
            const int r = (idx >> 3) & 63;
            const int seg = idx & 7;
            const __nv_bfloat16* src = kvs + (size_t)plane * PL
                + ((size_t)bh * 4096 + t0 + r) * 64 + seg * 8;
            cpa16(sbase + plane * DTILE + r * DROWB + seg * 16, src);
        }
        CP_COMMIT();
    };

    issue(0);
    for (int c = 0; c < 4; c++) {
        if (c < 3) { issue(c + 1); CP_WAIT(1); } else { CP_WAIT(0); }
        __syncthreads();
        const u32 khb = sb + (c & 1) * DSTG4;
        const u32 klb = khb + DTILE;
        const u32 vhb = khb + 2 * DTILE;
        const u32 vlb = khb + 3 * DTILE;
        #pragma unroll
        for (int kt = 0; kt < 4; kt++) {
            const u32 arow = (u32)(kt * 16 + (lane & 7) + ((lane >> 4) << 3));
            const u32 acol = (u32)(wr * 16 + ((lane >> 3) & 1) * 8);
            const u32 aoff = arow * DROWB + acol * 2;
            u32 ah[4], al[4];
            ldsm4t(ah, khb + aoff);
            ldsm4t(al, klb + aoff);
            const u32 brow = (u32)(kt * 16 + (lane & 7) + ((lane >> 3) & 1) * 8);
            const u32 bcol = (u32)(wc * 32 + ((lane >> 4) << 3));
            const u32 boff = brow * DROWB + bcol * 2;
            u32 bh0[4], bl0[4], bh1[4], bl1[4];
            ldsm4t(bh0, vhb + boff);
            ldsm4t(bl0, vlb + boff);
            ldsm4t(bh1, vhb + boff + 32);
            ldsm4t(bl1, vlb + boff + 32);
            mma16816(acc[0], ah, &bh0[0]); mma16816(acc[0], al, &bh0[0]); mma16816(acc[0], ah, &bl0[0]);
            mma16816(acc[1], ah, &bh0[2]); mma16816(acc[1], al, &bh0[2]); mma16816(acc[1], ah, &bl0[2]);
            mma16816(acc[2], ah, &bh1[0]); mma16816(acc[2], al, &bh1[0]); mma16816(acc[2], ah, &bl1[0]);
            mma16816(acc[3], ah, &bh1[2]); mma16816(acc[3], al, &bh1[2]); mma16816(acc[3], ah, &bl1[2]);
        }
        __syncthreads();
    }

    float* dst = part + ((size_t)bh * NSPLIT + split) * 4096;
    const int dr = wr * 16 + (lane >> 2);
    const int ec = wc * 32 + (lane & 3) * 2;
    #pragma unroll
    for (int nf = 0; nf < 4; nf++) {
        *(float2*)&dst[(size_t)dr * 64 + ec + nf * 8]       = make_float2(acc[nf][0], acc[nf][1]);
        *(float2*)&dst[(size_t)(dr + 8) * 64 + ec + nf * 8] = make_float2(acc[nf][2], acc[nf][3]);
    }
}

// ---------------- W2s[b][c][.] = fp16( ((sum dots)/n2 @ Wout)^T ) ----------------------
__global__ __launch_bounds__(256) void w2k(const float* __restrict__ part, const float* __restrict__ Wout,
                                           __half* __restrict__ W2s) {
    const int bh = blockIdx.x, dhalf = blockIdx.y;
    const int b = bh >> 3, h = bh & 7;
    __shared__ float ds[2048];
    const int tid = threadIdx.x;
    // vectorized split reduction: 512 float4 per block, 2 per thread, 16 independent loads each
    #pragma unroll
    for (int j = 0; j < 2; j++) {
        const int i4 = j * 256 + tid;
        float4 s = make_float4(0.f, 0.f, 0.f, 0.f);
        #pragma unroll
        for (int sp = 0; sp < NSPLIT; sp++) {
            const float4 v = *((const float4*)(part + ((size_t)bh * NSPLIT + sp) * 4096
                                               + dhalf * 2048) + i4);
            s.x += v.x; s.y += v.y; s.z += v.z; s.w += v.w;
        }
        *(float4*)&ds[i4 * 4] = make_float4(s.x * (1.f / 4096.f), s.y * (1.f / 4096.f),
                                            s.z * (1.f / 4096.f), s.w * (1.f / 4096.f));
    }
    __syncthreads();

    const int p = tid & 127, g = tid >> 7;
    u64 acc[16];
    #pragma unroll
    for (int d = 0; d < 16; d++) acc[d] = 0ull;
    for (int e = 0; e < 64; e++) {
        u64 w2 = *(const u64*)&Wout[(size_t)(h * 64 + e) * 256 + 2 * p];
        const float* dsr = &ds[(g * 16) * 64 + e];
        #pragma unroll
        for (int d = 0; d < 16; d++) {
            float val = dsr[d * 64];
            acc[d] = ffma2(pack2(val, val), w2, acc[d]);
        }
    }
    #pragma unroll
    for (int d = 0; d < 16; d++) {
        float o0, o1; unpack2(acc[d], o0, o1);
        const int dg = h * 64 + dhalf * 32 + g * 16 + d;
        size_t r0 = ((size_t)b * 256 + 2 * p) * 512;
        W2s[r0 + dg]       = __float2half_rn(o0);
        W2s[r0 + 512 + dg] = __float2half_rn(o1);
    }
}

// ---------------- launch ----------------
extern "C" void kernel_launch(void* const* d_in, const int* in_sizes, int n_in,
                              void* d_out, int out_size) {
    const float* x     = (const float*)d_in[0];
    const float* z     = (const float*)d_in[1];
    const float* x_pos = (const float*)d_in[2];
    const float* z_pos = (const float*)d_in[3];
    const float* Wq    = (const float*)d_in[4];
    const float* Wkv   = (const float*)d_in[5];
    const float* Wout  = (const float*)d_in[6];
    const float* bout  = (const float*)d_in[7];
    float* out = (float*)d_out;

    float* dotp;
    __nv_bfloat16* kvs;
    __half *z2, *x2, *wkv2, *wq2, *q2, *w2s;
    cudaGetSymbolAddress((void**)&kvs,  g_kvs);
    cudaGetSymbolAddress((void**)&dotp, g_dotp);
    cudaGetSymbolAddress((void**)&z2,   g_z2);
    cudaGetSymbolAddress((void**)&x2,   g_x2);
    cudaGetSymbolAddress((void**)&wkv2, g_wkv2);
    cudaGetSymbolAddress((void**)&wq2,  g_wq2);
    cudaGetSymbolAddress((void**)&q2,   g_q2);
    cudaGetSymbolAddress((void**)&w2s,  g_w2s);

    cudaFuncSetAttribute(gemm_main, cudaFuncAttributeMaxDynamicSharedMemorySize, GSMEM);
    cudaFuncSetAttribute(gemm_epi,  cudaFuncAttributeMaxDynamicSharedMemorySize, GSMEM);
    cudaFuncSetAttribute(dots_pure, cudaFuncAttributeMaxDynamicSharedMemorySize, DSM_BYTES);

    // one prep launch: fp16 conversions of z, x, Wkv, Wq
    prep<<<17920, 256>>>(z, x, Wkv, Wq, z2, x2, wkv2, wq2);

    // kv GEMM (norm+rot+bf16 planes) and q GEMM (rot+fp16) in one launch, K=256
    gemm_main<<<dim3(12, 256), 256, GSMEM>>>(z2, wkv2, x2, wq2, kvs, q2, z_pos, x_pos);

    // Gram partials + W2
    dots_pure<<<dim3(NSPLIT, 64), 256, DSM_BYTES>>>(kvs, dotp);
    w2k<<<dim3(64, 2), 256>>>(dotp, Wout, w2s);

    // out[b] = q2[b] @ W2s[b]^T + bout
    gemm_epi<<<dim3(2, 32, BATCH), 256, GSMEM>>>(q2, w2s, out, bout);
}

// round 13
// speedup vs baseline: 2.4454x; 1.1695x over previous
#include <cuda_runtime.h>
#include <cuda_bf16.h>
#include <cuda_fp16.h>
#include <math.h>
#include <cstdint>

typedef unsigned long long u64;
typedef unsigned int u32;

#define HEADS 8
#define NDIM  256
#define INNER 512
#define NTOKS 4096
#define BATCH 8
#define MTOT  (BATCH * NTOKS)   // 32768
#define NSPLIT 16
#define PL ((size_t)64 * 4096 * 64)   // one fp16 plane: [b*8+h][t][64]

// ---------------- scratch (device globals: allocation-guard safe) ----------------
__device__ __half g_kvs [(size_t)2 * PL];            // plane 0: k~, plane 1: v~ (fp16)
__device__ float g_dotp[(size_t)64 * NSPLIT * 64 * 64];
__device__ __half g_z2  [(size_t)MTOT * 256];        // z fp16
__device__ __half g_x2  [(size_t)MTOT * 256];
__device__ __half g_wkv2[(size_t)1024 * 256];        // Wkv^T fp16
__device__ __half g_wq2 [(size_t)512 * 256];         // Wq^T fp16
__device__ __half g_q2  [(size_t)MTOT * 512];        // q rot fp16 [M, INNER]
__device__ __half g_w2s [(size_t)BATCH * 256 * 512]; // W2^T fp16

// ---------------- MMA / async helpers ----------------
__device__ __forceinline__ u32 smem_u32(const void* p) {
    u32 a; asm("{ .reg .u64 t; cvta.to.shared.u64 t, %1; cvt.u32.u64 %0, t; }" : "=r"(a) : "l"(p));
    return a;
}
__device__ __forceinline__ void cpa16(u32 dst, const void* src) {
    asm volatile("cp.async.cg.shared.global [%0], [%1], 16;" :: "r"(dst), "l"(src));
}
#define CP_COMMIT() asm volatile("cp.async.commit_group;" ::: "memory")
#define CP_WAIT(n)  asm volatile("cp.async.wait_group %0;" :: "n"(n) : "memory")

__device__ __forceinline__ void ldsm4(u32* r, u32 a) {
    asm volatile("ldmatrix.sync.aligned.m8n8.x4.shared.b16 {%0,%1,%2,%3}, [%4];"
        : "=r"(r[0]), "=r"(r[1]), "=r"(r[2]), "=r"(r[3]) : "r"(a));
}
__device__ __forceinline__ void ldsm4t(u32* r, u32 a) {
    asm volatile("ldmatrix.sync.aligned.m8n8.x4.trans.shared.b16 {%0,%1,%2,%3}, [%4];"
        : "=r"(r[0]), "=r"(r[1]), "=r"(r[2]), "=r"(r[3]) : "r"(a));
}
__device__ __forceinline__ void mma16816h(float* c, const u32* a, const u32* b) {
    asm volatile("mma.sync.aligned.m16n8k16.row.col.f32.f16.f16.f32 "
        "{%0,%1,%2,%3}, {%4,%5,%6,%7}, {%8,%9}, {%0,%1,%2,%3};"
        : "+f"(c[0]), "+f"(c[1]), "+f"(c[2]), "+f"(c[3])
        : "r"(a[0]), "r"(a[1]), "r"(a[2]), "r"(a[3]), "r"(b[0]), "r"(b[1]));
}

// ---------------- f32x2 helpers ----------------
__device__ __forceinline__ u64 pack2(float x, float y) {
    u64 r; asm("mov.b64 %0, {%1,%2};" : "=l"(r) : "f"(x), "f"(y)); return r;
}
__device__ __forceinline__ u64 ffma2(u64 a, u64 b, u64 c) {
    u64 d; asm("fma.rn.f32x2 %0, %1, %2, %3;" : "=l"(d) : "l"(a), "l"(b), "l"(c)); return d;
}
__device__ __forceinline__ void unpack2(u64 v, float& x, float& y) {
    asm("mov.b64 {%0,%1}, %2;" : "=f"(x), "=f"(y) : "l"(v));
}

// ---------------- unified prep: fp16 convert z, x (rows) + Wkv, Wq (transpose) ----------
__global__ void prep(const float* __restrict__ z, const float* __restrict__ x,
                     const float* __restrict__ Wkv, const float* __restrict__ Wq,
                     __half* __restrict__ z2, __half* __restrict__ x2,
                     __half* __restrict__ wkv2, __half* __restrict__ wq2) {
    const int bid = blockIdx.x;
    const int tid = threadIdx.x;
    if (bid < 16384) {
        const float* in = (bid < 8192) ? z : x;
        __half* out = (bid < 8192) ? z2 : x2;
        size_t idx = (size_t)(bid & 8191) * 256 + tid;
        float4 v = ((const float4*)in)[idx];
        __half2 p0 = __half2{__float2half_rn(v.x), __float2half_rn(v.y)};
        __half2 p1 = __half2{__float2half_rn(v.z), __float2half_rn(v.w)};
        __half2* dst = (__half2*)(out + idx * 4);
        dst[0] = p0; dst[1] = p1;
    } else {
        const int isKv = (bid < 17408);
        const int n = isKv ? (bid - 16384) : (bid - 17408);
        const int N = isKv ? 1024 : 512;
        const float* W = isKv ? Wkv : Wq;
        __half* out = isKv ? wkv2 : wq2;
        out[(size_t)n * 256 + tid] = __float2half_rn(W[(size_t)tid * N + n]);
    }
}

// ---------------- main GEMM (K2=256): kv (norm+rot+fp16 planes) and q (rot+fp16) -------
#define ROWB 80
#define TILEB (128 * ROWB)
#define STAGEB (2 * TILEB)
#define NSTAGE 4
#define GSMEM (NSTAGE * STAGEB)

__global__ __launch_bounds__(256, 2) void gemm_main(
    const __half* __restrict__ z2, const __half* __restrict__ wkv2,
    const __half* __restrict__ x2, const __half* __restrict__ wq2,
    __half* __restrict__ Ckv, __half* __restrict__ Cq,
    const float* __restrict__ z_pos, const float* __restrict__ x_pos)
{
    extern __shared__ __align__(1024) char smem[];
    const int bx = blockIdx.x;
    const int isKv = (bx < 8);
    const __half* A2 = isKv ? z2 : x2;
    const __half* B2 = isKv ? wkv2 : wq2;
    const int n0 = (isKv ? bx : bx - 8) * 128;
    const int m0 = blockIdx.y * 128;
    const int tid = threadIdx.x, lane = tid & 31, wid = tid >> 5;
    const int wr = wid >> 2, wc = wid & 3;
    const u32 sb = smem_u32(smem);

    const int K2 = 256, total = 8;
    const int lrow = tid >> 1;
    const int lcg = (tid & 1) * 2;

    float acc[4][4][4];
    #pragma unroll
    for (int i = 0; i < 4; i++)
        #pragma unroll
        for (int j = 0; j < 4; j++)
            #pragma unroll
            for (int r = 0; r < 4; r++) acc[i][j][r] = 0.f;

    auto issue = [&](int it) {
        const int stage = it & (NSTAGE - 1);
        const int kk = it * 32;
        const __half* as = A2 + (size_t)(m0 + lrow) * K2 + kk + lcg * 8;
        const __half* bs = B2 + (size_t)(n0 + lrow) * K2 + kk + lcg * 8;
        const u32 da = sb + stage * STAGEB + lrow * ROWB + lcg * 16;
        cpa16(da, as);              cpa16(da + 16, as + 8);
        cpa16(da + TILEB, bs);      cpa16(da + TILEB + 16, bs + 8);
        CP_COMMIT();
    };

    auto compute = [&](int stage) {
        const u32 ab = sb + stage * STAGEB;
        const u32 bb = ab + TILEB;
        #pragma unroll
        for (int kb = 0; kb < 2; kb++) {
            u32 a[4][4], b[2][4];
            #pragma unroll
            for (int mf = 0; mf < 4; mf++) {
                u32 addr = ab + (u32)(wr * 64 + mf * 16 + (lane & 15)) * ROWB
                              + kb * 32 + (lane >> 4) * 16;
                ldsm4(a[mf], addr);
            }
            #pragma unroll
            for (int nfp = 0; nfp < 2; nfp++) {
                u32 addr = bb + (u32)(wc * 32 + nfp * 16 + ((lane >> 4) << 3) + (lane & 7)) * ROWB
                              + kb * 32 + ((lane >> 3) & 1) * 16;
                ldsm4(b[nfp], addr);
            }
            #pragma unroll
            for (int mf = 0; mf < 4; mf++)
                #pragma unroll
                for (int nf = 0; nf < 4; nf++)
                    mma16816h(acc[mf][nf], a[mf], &b[nf >> 1][(nf & 1) * 2]);
        }
    };

    issue(0); issue(1); issue(2);
    for (int i = 0; i < total; i++) {
        if (i < total - 2)       CP_WAIT(2);
        else if (i == total - 2) CP_WAIT(1);
        else                     CP_WAIT(0);
        __syncthreads();
        compute(i & (NSTAGE - 1));
        if (i + 3 < total) issue(i + 3);
    }

    if (isKv) {
        // per-head instance norm (+rotary on k) -> single fp16 plane.
        __syncthreads();
        float* red = (float*)smem;
        float s8[8], q8[8], mean[8], inv[8];
        #pragma unroll
        for (int mf = 0; mf < 4; mf++)
            #pragma unroll
            for (int rb = 0; rb < 2; rb++) {
                const int ri = mf * 2 + rb;
                float s = 0.f, q = 0.f;
                #pragma unroll
                for (int nf = 0; nf < 4; nf++)
                    #pragma unroll
                    for (int cb = 0; cb < 2; cb++) {
                        float a = acc[mf][nf][rb * 2 + cb];
                        s += a; q += a * a;
                    }
                s += __shfl_xor_sync(0xffffffffu, s, 1); q += __shfl_xor_sync(0xffffffffu, q, 1);
                s += __shfl_xor_sync(0xffffffffu, s, 2); q += __shfl_xor_sync(0xffffffffu, q, 2);
                s8[ri] = s; q8[ri] = q;
            }
        if ((lane & 3) == 0) {
            #pragma unroll
            for (int ri = 0; ri < 8; ri++) {
                const int idx = (((wr * 4 + wc) * 8) + ri) * 8 + (lane >> 2);
                red[idx * 2] = s8[ri]; red[idx * 2 + 1] = q8[ri];
            }
        }
        __syncthreads();
        #pragma unroll
        for (int ri = 0; ri < 8; ri++) {
            const int idx = (((wr * 4 + (wc ^ 1)) * 8) + ri) * 8 + (lane >> 2);
            const float ts = s8[ri] + red[idx * 2];
            const float tq = q8[ri] + red[idx * 2 + 1];
            const float mu = ts * (1.f / 64.f);
            mean[ri] = mu;
            inv[ri] = rsqrtf(fmaxf(tq * (1.f / 64.f) - mu * mu, 0.f) + 1e-5f);
        }

        const int isK = (bx < 4);
        const int g = (isK ? bx : bx - 4) * 2 + (wc >> 1);
        const int half = wc & 1;
        const int lq = lane & 3;
        __half* base0 = Ckv + (isK ? 0 : PL);
        #pragma unroll
        for (int mf = 0; mf < 4; mf++)
            #pragma unroll
            for (int rb = 0; rb < 2; rb++) {
                const int ri = mf * 2 + rb;
                const int m = m0 + wr * 64 + mf * 16 + (lane >> 2) + rb * 8;
                const int bb = m >> 12, tt = m & 4095;
                const size_t rowoff = ((size_t)(bb * 8 + g) * 4096 + tt) * 64;
                const float mu = mean[ri], iv = inv[ri];
                if (isK) {
                    const float pp = z_pos[(size_t)m * 2 + half] * 64.f;
                    #pragma unroll
                    for (int nf2 = 0; nf2 < 2; nf2++) {
                        float o[4];
                        #pragma unroll
                        for (int cb = 0; cb < 2; cb++) {
                            const int j = nf2 * 8 + lq * 2 + cb;
                            const float invf = exp2f(-(float)j * (13.287712379549449f / 16.f));
                            float sn, co; sincosf(pp * invf, &sn, &co);
                            const float vlo = (acc[mf][nf2][rb * 2 + cb]     - mu) * iv;
                            const float vhi = (acc[mf][nf2 + 2][rb * 2 + cb] - mu) * iv;
                            o[cb]     = vlo * co - vhi * sn;
                            o[2 + cb] = vhi * co + vlo * sn;
                        }
                        const int cg = half * 32 + nf2 * 8 + lq * 2;
                        *(__half2*)&base0[rowoff + cg] =
                            __half2{__float2half_rn(o[0]), __float2half_rn(o[1])};
                        *(__half2*)&base0[rowoff + cg + 16] =
                            __half2{__float2half_rn(o[2]), __float2half_rn(o[3])};
                    }
                } else {
                    #pragma unroll
                    for (int nf = 0; nf < 4; nf++) {
                        const int cg = half * 32 + nf * 8 + lq * 2;
                        const float a0 = (acc[mf][nf][rb * 2]     - mu) * iv;
                        const float a1 = (acc[mf][nf][rb * 2 + 1] - mu) * iv;
                        *(__half2*)&base0[rowoff + cg] =
                            __half2{__float2half_rn(a0), __float2half_rn(a1)};
                    }
                }
            }
    } else {
        // q branch: rotary + fp16 store -> Cq [M, 512]
        const int half = wc & 1;
        const int lq = lane & 3;
        #pragma unroll
        for (int mf = 0; mf < 4; mf++) {
            #pragma unroll
            for (int rb = 0; rb < 2; rb++) {
                const int r = m0 + wr * 64 + mf * 16 + (lane >> 2) + rb * 8;
                const float pp = x_pos[(size_t)r * 2 + half] * 64.f;
                const size_t rowb = (size_t)r * 512;
                #pragma unroll
                for (int nf2 = 0; nf2 < 2; nf2++) {
                    float o[4];
                    #pragma unroll
                    for (int cb = 0; cb < 2; cb++) {
                        const int j = nf2 * 8 + lq * 2 + cb;
                        const float invf = exp2f(-(float)j * (13.287712379549449f / 16.f));
                        float s, co; sincosf(pp * invf, &s, &co);
                        const int idx = rb * 2 + cb;
                        const float vlo = acc[mf][nf2][idx];
                        const float vhi = acc[mf][nf2 + 2][idx];
                        o[cb]     = vlo * co - vhi * s;
                        o[2 + cb] = vhi * co + vlo * s;
                    }
                    const int cg = n0 + wc * 32 + nf2 * 8 + lq * 2;
                    *(__half2*)&Cq[rowb + cg] =
                        __half2{__float2half_rn(o[0]), __float2half_rn(o[1])};
                    *(__half2*)&Cq[rowb + cg + 16] =
                        __half2{__float2half_rn(o[2]), __float2half_rn(o[3])};
                }
            }
        }
    }
}

// ---------------- epilogue GEMM: out[b] = q2[b] @ W2s[b]^T + bout ----------------------
__global__ __launch_bounds__(256, 2) void gemm_epi(
    const __half* __restrict__ A2, const __half* __restrict__ B2,
    float* __restrict__ C, const float* __restrict__ bias)
{
    extern __shared__ __align__(1024) char smem[];
    A2 += (size_t)blockIdx.z * ((long)NTOKS * 512);
    B2 += (size_t)blockIdx.z * ((long)256 * 512);
    C  += (size_t)blockIdx.z * ((long)NTOKS * 256);
    const int m0 = blockIdx.y * 128, n0 = blockIdx.x * 128;
    const int tid = threadIdx.x, lane = tid & 31, wid = tid >> 5;
    const int wr = wid >> 2, wc = wid & 3;
    const u32 sb = smem_u32(smem);

    const int K2 = 512, total = 16;
    const int lrow = tid >> 1;
    const int lcg = (tid & 1) * 2;

    float acc[4][4][4];
    #pragma unroll
    for (int i = 0; i < 4; i++)
        #pragma unroll
        for (int j = 0; j < 4; j++)
            #pragma unroll
            for (int r = 0; r < 4; r++) acc[i][j][r] = 0.f;

    auto issue = [&](int it) {
        const int stage = it & (NSTAGE - 1);
        const int kk = it * 32;
        const __half* as = A2 + (size_t)(m0 + lrow) * K2 + kk + lcg * 8;
        const __half* bs = B2 + (size_t)(n0 + lrow) * K2 + kk + lcg * 8;
        const u32 da = sb + stage * STAGEB + lrow * ROWB + lcg * 16;
        cpa16(da, as);              cpa16(da + 16, as + 8);
        cpa16(da + TILEB, bs);      cpa16(da + TILEB + 16, bs + 8);
        CP_COMMIT();
    };

    auto compute = [&](int stage) {
        const u32 ab = sb + stage * STAGEB;
        const u32 bb = ab + TILEB;
        #pragma unroll
        for (int kb = 0; kb < 2; kb++) {
            u32 a[4][4], b[2][4];
            #pragma unroll
            for (int mf = 0; mf < 4; mf++) {
                u32 addr = ab + (u32)(wr * 64 + mf * 16 + (lane & 15)) * ROWB
                              + kb * 32 + (lane >> 4) * 16;
                ldsm4(a[mf], addr);
            }
            #pragma unroll
            for (int nfp = 0; nfp < 2; nfp++) {
                u32 addr = bb + (u32)(wc * 32 + nfp * 16 + ((lane >> 4) << 3) + (lane & 7)) * ROWB
                              + kb * 32 + ((lane >> 3) & 1) * 16;
                ldsm4(b[nfp], addr);
            }
            #pragma unroll
            for (int mf = 0; mf < 4; mf++)
                #pragma unroll
                for (int nf = 0; nf < 4; nf++)
                    mma16816h(acc[mf][nf], a[mf], &b[nf >> 1][(nf & 1) * 2]);
        }
    };

    issue(0); issue(1); issue(2);
    for (int i = 0; i < total; i++) {
        if (i < total - 2)       CP_WAIT(2);
        else if (i == total - 2) CP_WAIT(1);
        else                     CP_WAIT(0);
        __syncthreads();
        compute(i & (NSTAGE - 1));
        if (i + 3 < total) issue(i + 3);
    }

    const int rbase = m0 + wr * 64 + (lane >> 2);
    const int cbase = n0 + wc * 32 + (lane & 3) * 2;
    #pragma unroll
    for (int nf = 0; nf < 4; nf++) {
        const int c = cbase + nf * 8;
        const float bx = bias[c], by = bias[c + 1];
        #pragma unroll
        for (int mf = 0; mf < 4; mf++) {
            const int r = rbase + mf * 16;
            *(float2*)&C[(size_t)r * 256 + c] =
                make_float2(acc[mf][nf][0] + bx, acc[mf][nf][1] + by);
            *(float2*)&C[(size_t)(r + 8) * 256 + c] =
                make_float2(acc[mf][nf][2] + bx, acc[mf][nf][3] + by);
        }
    }
}

// ---------------- dots: pure streaming fp16 Gram MMA (single term) ----------------
#define DROWB 144
#define DTILE (64 * DROWB)       // 9216
#define DSTG2 (2 * DTILE)        // 18432: k, v tiles for one chunk
#define DSM_BYTES (2 * DSTG2)    // 36864

__global__ __launch_bounds__(256, 2) void dots_pure(const __half* __restrict__ kvs,
                                                    float* __restrict__ part) {
    extern __shared__ __align__(1024) char dsm[];
    const u32 sb = smem_u32(dsm);

    const int split = blockIdx.x;
    const int bh = blockIdx.y;
    const int tid = threadIdx.x;
    const int w = tid >> 5, lane = tid & 31;
    const int wr = w >> 1, wc = w & 1;

    float acc[4][4];
    #pragma unroll
    for (int i = 0; i < 4; i++)
        #pragma unroll
        for (int j = 0; j < 4; j++) acc[i][j] = 0.f;

    auto issue = [&](int c) {
        const int t0 = split * 256 + c * 64;
        const u32 sbase = sb + (c & 1) * DSTG2;
        #pragma unroll
        for (int i = 0; i < 4; i++) {
            const int idx = i * 256 + tid;      // 0..1023
            const int plane = idx >> 9;
            const int r = (idx >> 3) & 63;
            const int seg = idx & 7;
            const __half* src = kvs + (size_t)plane * PL
                + ((size_t)bh * 4096 + t0 + r) * 64 + seg * 8;
            cpa16(sbase + plane * DTILE + r * DROWB + seg * 16, src);
        }
        CP_COMMIT();
    };

    issue(0);
    for (int c = 0; c < 4; c++) {
        if (c < 3) { issue(c + 1); CP_WAIT(1); } else { CP_WAIT(0); }
        __syncthreads();
        const u32 khb = sb + (c & 1) * DSTG2;
        const u32 vhb = khb + DTILE;
        #pragma unroll
        for (int kt = 0; kt < 4; kt++) {
            const u32 arow = (u32)(kt * 16 + (lane & 7) + ((lane >> 4) << 3));
            const u32 acol = (u32)(wr * 16 + ((lane >> 3) & 1) * 8);
            u32 ah[4];
            ldsm4t(ah, khb + arow * DROWB + acol * 2);
            const u32 brow = (u32)(kt * 16 + (lane & 7) + ((lane >> 3) & 1) * 8);
            const u32 bcol = (u32)(wc * 32 + ((lane >> 4) << 3));
            const u32 boff = brow * DROWB + bcol * 2;
            u32 bh0[4], bh1[4];
            ldsm4t(bh0, vhb + boff);
            ldsm4t(bh1, vhb + boff + 32);
            mma16816h(acc[0], ah, &bh0[0]);
            mma16816h(acc[1], ah, &bh0[2]);
            mma16816h(acc[2], ah, &bh1[0]);
            mma16816h(acc[3], ah, &bh1[2]);
        }
        __syncthreads();
    }

    float* dst = part + ((size_t)bh * NSPLIT + split) * 4096;
    const int dr = wr * 16 + (lane >> 2);
    const int ec = wc * 32 + (lane & 3) * 2;
    #pragma unroll
    for (int nf = 0; nf < 4; nf++) {
        *(float2*)&dst[(size_t)dr * 64 + ec + nf * 8]       = make_float2(acc[nf][0], acc[nf][1]);
        *(float2*)&dst[(size_t)(dr + 8) * 64 + ec + nf * 8] = make_float2(acc[nf][2], acc[nf][3]);
    }
}

// ---------------- w2k: W2s = fp16( ((sum dots)/n2 @ Wout)^T ), regrid (64, 8) ----------
__global__ __launch_bounds__(256) void w2k(const float* __restrict__ part, const float* __restrict__ Wout,
                                           __half* __restrict__ W2s) {
    const int bh = blockIdx.x, dg = blockIdx.y;   // dg: group of 8 d-rows
    const int b = bh >> 3, h = bh & 7;
    __shared__ float ds[512];                      // [8 d][64 e]
    const int tid = threadIdx.x;
    // reduce 8x64 floats over NSPLIT partials; 128 float4 slots, threads 0..127
    if (tid < 128) {
        float4 s = make_float4(0.f, 0.f, 0.f, 0.f);
        const float4* base = (const float4*)(part + (size_t)bh * NSPLIT * 4096 + dg * 512) + tid;
        #pragma unroll
        for (int sp = 0; sp < NSPLIT; sp++) {
            const float4 v = base[sp * 1024];
            s.x += v.x; s.y += v.y; s.z += v.z; s.w += v.w;
        }
        *(float4*)&ds[tid * 4] = make_float4(s.x * (1.f / 4096.f), s.y * (1.f / 4096.f),
                                             s.z * (1.f / 4096.f), s.w * (1.f / 4096.f));
    }
    __syncthreads();

    const int p = tid & 127, dq = tid >> 7;        // col pair, d-half (4 rows each)
    u64 acc[4];
    #pragma unroll
    for (int d = 0; d < 4; d++) acc[d] = 0ull;
    for (int e = 0; e < 64; e++) {
        u64 w2 = *(const u64*)&Wout[(size_t)(h * 64 + e) * 256 + 2 * p];
        const float* dsr = &ds[(dq * 4) * 64 + e];
        #pragma unroll
        for (int d = 0; d < 4; d++) {
            float val = dsr[d * 64];
            acc[d] = ffma2(pack2(val, val), w2, acc[d]);
        }
    }
    #pragma unroll
    for (int d = 0; d < 4; d++) {
        float o0, o1; unpack2(acc[d], o0, o1);
        const int dgg = h * 64 + dg * 8 + dq * 4 + d;
        size_t r0 = ((size_t)b * 256 + 2 * p) * 512;
        W2s[r0 + dgg]       = __float2half_rn(o0);
        W2s[r0 + 512 + dgg] = __float2half_rn(o1);
    }
}

// ---------------- launch ----------------
extern "C" void kernel_launch(void* const* d_in, const int* in_sizes, int n_in,
                              void* d_out, int out_size) {
    const float* x     = (const float*)d_in[0];
    const float* z     = (const float*)d_in[1];
    const float* x_pos = (const float*)d_in[2];
    const float* z_pos = (const float*)d_in[3];
    const float* Wq    = (const float*)d_in[4];
    const float* Wkv   = (const float*)d_in[5];
    const float* Wout  = (const float*)d_in[6];
    const float* bout  = (const float*)d_in[7];
    float* out = (float*)d_out;

    float* dotp;
    __half *kvs, *z2, *x2, *wkv2, *wq2, *q2, *w2s;
    cudaGetSymbolAddress((void**)&kvs,  g_kvs);
    cudaGetSymbolAddress((void**)&dotp, g_dotp);
    cudaGetSymbolAddress((void**)&z2,   g_z2);
    cudaGetSymbolAddress((void**)&x2,   g_x2);
    cudaGetSymbolAddress((void**)&wkv2, g_wkv2);
    cudaGetSymbolAddress((void**)&wq2,  g_wq2);
    cudaGetSymbolAddress((void**)&q2,   g_q2);
    cudaGetSymbolAddress((void**)&w2s,  g_w2s);

    cudaFuncSetAttribute(gemm_main, cudaFuncAttributeMaxDynamicSharedMemorySize, GSMEM);
    cudaFuncSetAttribute(gemm_epi,  cudaFuncAttributeMaxDynamicSharedMemorySize, GSMEM);
    cudaFuncSetAttribute(dots_pure, cudaFuncAttributeMaxDynamicSharedMemorySize, DSM_BYTES);

    // one prep launch: fp16 conversions of z, x, Wkv, Wq
    prep<<<17920, 256>>>(z, x, Wkv, Wq, z2, x2, wkv2, wq2);

    // kv GEMM (norm+rot+fp16 planes) and q GEMM (rot+fp16) in one launch, K=256
    gemm_main<<<dim3(12, 256), 256, GSMEM>>>(z2, wkv2, x2, wq2, kvs, q2, z_pos, x_pos);

    // Gram partials + W2
    dots_pure<<<dim3(NSPLIT, 64), 256, DSM_BYTES>>>(kvs, dotp);
    w2k<<<dim3(64, 8), 256>>>(dotp, Wout, w2s);

    // out[b] = q2[b] @ W2s[b]^T + bout
    gemm_epi<<<dim3(2, 32, BATCH), 256, GSMEM>>>(q2, w2s, out, bout);
}

// round 14
// speedup vs baseline: 2.5067x; 1.0251x over previous
#include <cuda_runtime.h>
#include <cuda_bf16.h>
#include <cuda_fp16.h>
#include <math.h>
#include <cstdint>

typedef unsigned long long u64;
typedef unsigned int u32;

#define HEADS 8
#define NDIM  256
#define INNER 512
#define NTOKS 4096
#define BATCH 8
#define MTOT  (BATCH * NTOKS)   // 32768
#define NSPLIT 16
#define PL ((size_t)64 * 4096 * 64)   // one fp16 plane: [b*8+h][t][64]

// ---------------- scratch (device globals: allocation-guard safe) ----------------
__device__ __half g_kvs [(size_t)2 * PL];            // plane 0: k~, plane 1: v~ (fp16)
__device__ float g_dotp[(size_t)64 * NSPLIT * 64 * 64];
__device__ __half g_z2  [(size_t)MTOT * 256];        // z fp16
__device__ __half g_x2  [(size_t)MTOT * 256];
__device__ __half g_wkv2[(size_t)1024 * 256];        // Wkv^T fp16
__device__ __half g_wq2 [(size_t)512 * 256];         // Wq^T fp16
__device__ __half g_q2  [(size_t)MTOT * 512];        // q rot fp16 [M, INNER]
__device__ __half g_w2s [(size_t)BATCH * 256 * 512]; // W2^T fp16

// ---------------- MMA / async helpers ----------------
__device__ __forceinline__ u32 smem_u32(const void* p) {
    u32 a; asm("{ .reg .u64 t; cvta.to.shared.u64 t, %1; cvt.u32.u64 %0, t; }" : "=r"(a) : "l"(p));
    return a;
}
__device__ __forceinline__ void cpa16(u32 dst, const void* src) {
    asm volatile("cp.async.cg.shared.global [%0], [%1], 16;" :: "r"(dst), "l"(src));
}
#define CP_COMMIT() asm volatile("cp.async.commit_group;" ::: "memory")
#define CP_WAIT(n)  asm volatile("cp.async.wait_group %0;" :: "n"(n) : "memory")

__device__ __forceinline__ void ldsm4(u32* r, u32 a) {
    asm volatile("ldmatrix.sync.aligned.m8n8.x4.shared.b16 {%0,%1,%2,%3}, [%4];"
        : "=r"(r[0]), "=r"(r[1]), "=r"(r[2]), "=r"(r[3]) : "r"(a));
}
__device__ __forceinline__ void ldsm4t(u32* r, u32 a) {
    asm volatile("ldmatrix.sync.aligned.m8n8.x4.trans.shared.b16 {%0,%1,%2,%3}, [%4];"
        : "=r"(r[0]), "=r"(r[1]), "=r"(r[2]), "=r"(r[3]) : "r"(a));
}
__device__ __forceinline__ void mma16816h(float* c, const u32* a, const u32* b) {
    asm volatile("mma.sync.aligned.m16n8k16.row.col.f32.f16.f16.f32 "
        "{%0,%1,%2,%3}, {%4,%5,%6,%7}, {%8,%9}, {%0,%1,%2,%3};"
        : "+f"(c[0]), "+f"(c[1]), "+f"(c[2]), "+f"(c[3])
        : "r"(a[0]), "r"(a[1]), "r"(a[2]), "r"(a[3]), "r"(b[0]), "r"(b[1]));
}

// ---------------- f32x2 helpers ----------------
__device__ __forceinline__ u64 pack2(float x, float y) {
    u64 r; asm("mov.b64 %0, {%1,%2};" : "=l"(r) : "f"(x), "f"(y)); return r;
}
__device__ __forceinline__ u64 ffma2(u64 a, u64 b, u64 c) {
    u64 d; asm("fma.rn.f32x2 %0, %1, %2, %3;" : "=l"(d) : "l"(a), "l"(b), "l"(c)); return d;
}
__device__ __forceinline__ void unpack2(u64 v, float& x, float& y) {
    asm("mov.b64 {%0,%1}, %2;" : "=f"(x), "=f"(y) : "l"(v));
}

// ---------------- unified prep: fp16 convert z, x (rows) + Wkv, Wq (transpose) ----------
__global__ void prep(const float* __restrict__ z, const float* __restrict__ x,
                     const float* __restrict__ Wkv, const float* __restrict__ Wq,
                     __half* __restrict__ z2, __half* __restrict__ x2,
                     __half* __restrict__ wkv2, __half* __restrict__ wq2) {
    const int bid = blockIdx.x;
    const int tid = threadIdx.x;
    if (bid < 16384) {
        const float* in = (bid < 8192) ? z : x;
        __half* out = (bid < 8192) ? z2 : x2;
        size_t idx = (size_t)(bid & 8191) * 256 + tid;
        float4 v = ((const float4*)in)[idx];
        __half2 p0 = __half2{__float2half_rn(v.x), __float2half_rn(v.y)};
        __half2 p1 = __half2{__float2half_rn(v.z), __float2half_rn(v.w)};
        __half2* dst = (__half2*)(out + idx * 4);
        dst[0] = p0; dst[1] = p1;
    } else {
        const int isKv = (bid < 17408);
        const int n = isKv ? (bid - 16384) : (bid - 17408);
        const int N = isKv ? 1024 : 512;
        const float* W = isKv ? Wkv : Wq;
        __half* out = isKv ? wkv2 : wq2;
        out[(size_t)n * 256 + tid] = __float2half_rn(W[(size_t)tid * N + n]);
    }
}

// ---------------- main GEMM (K2=256): bx<8 -> kv (norm+rot planes), bx>=8 -> q --------
#define ROWB 80
#define TILEB (128 * ROWB)
#define STAGEB (2 * TILEB)
#define NSTAGE 4
#define GSMEM (NSTAGE * STAGEB)

__global__ __launch_bounds__(256, 2) void gemm_main(
    const __half* __restrict__ z2, const __half* __restrict__ wkv2,
    const __half* __restrict__ x2, const __half* __restrict__ wq2,
    __half* __restrict__ Ckv, __half* __restrict__ Cq,
    const float* __restrict__ z_pos, const float* __restrict__ x_pos, int bx0)
{
    extern __shared__ __align__(1024) char smem[];
    const int bx = blockIdx.x + bx0;
    const int isKv = (bx < 8);
    const __half* A2 = isKv ? z2 : x2;
    const __half* B2 = isKv ? wkv2 : wq2;
    const int n0 = (isKv ? bx : bx - 8) * 128;
    const int m0 = blockIdx.y * 128;
    const int tid = threadIdx.x, lane = tid & 31, wid = tid >> 5;
    const int wr = wid >> 2, wc = wid & 3;
    const u32 sb = smem_u32(smem);

    const int K2 = 256, total = 8;
    const int lrow = tid >> 1;
    const int lcg = (tid & 1) * 2;

    float acc[4][4][4];
    #pragma unroll
    for (int i = 0; i < 4; i++)
        #pragma unroll
        for (int j = 0; j < 4; j++)
            #pragma unroll
            for (int r = 0; r < 4; r++) acc[i][j][r] = 0.f;

    auto issue = [&](int it) {
        const int stage = it & (NSTAGE - 1);
        const int kk = it * 32;
        const __half* as = A2 + (size_t)(m0 + lrow) * K2 + kk + lcg * 8;
        const __half* bs = B2 + (size_t)(n0 + lrow) * K2 + kk + lcg * 8;
        const u32 da = sb + stage * STAGEB + lrow * ROWB + lcg * 16;
        cpa16(da, as);              cpa16(da + 16, as + 8);
        cpa16(da + TILEB, bs);      cpa16(da + TILEB + 16, bs + 8);
        CP_COMMIT();
    };

    auto compute = [&](int stage) {
        const u32 ab = sb + stage * STAGEB;
        const u32 bb = ab + TILEB;
        #pragma unroll
        for (int kb = 0; kb < 2; kb++) {
            u32 a[4][4], b[2][4];
            #pragma unroll
            for (int mf = 0; mf < 4; mf++) {
                u32 addr = ab + (u32)(wr * 64 + mf * 16 + (lane & 15)) * ROWB
                              + kb * 32 + (lane >> 4) * 16;
                ldsm4(a[mf], addr);
            }
            #pragma unroll
            for (int nfp = 0; nfp < 2; nfp++) {
                u32 addr = bb + (u32)(wc * 32 + nfp * 16 + ((lane >> 4) << 3) + (lane & 7)) * ROWB
                              + kb * 32 + ((lane >> 3) & 1) * 16;
                ldsm4(b[nfp], addr);
            }
            #pragma unroll
            for (int mf = 0; mf < 4; mf++)
                #pragma unroll
                for (int nf = 0; nf < 4; nf++)
                    mma16816h(acc[mf][nf], a[mf], &b[nf >> 1][(nf & 1) * 2]);
        }
    };

    issue(0); issue(1); issue(2);
    for (int i = 0; i < total; i++) {
        if (i < total - 2)       CP_WAIT(2);
        else if (i == total - 2) CP_WAIT(1);
        else                     CP_WAIT(0);
        __syncthreads();
        compute(i & (NSTAGE - 1));
        if (i + 3 < total) issue(i + 3);
    }

    if (isKv) {
        __syncthreads();
        float* red = (float*)smem;
        float s8[8], q8[8], mean[8], inv[8];
        #pragma unroll
        for (int mf = 0; mf < 4; mf++)
            #pragma unroll
            for (int rb = 0; rb < 2; rb++) {
                const int ri = mf * 2 + rb;
                float s = 0.f, q = 0.f;
                #pragma unroll
                for (int nf = 0; nf < 4; nf++)
                    #pragma unroll
                    for (int cb = 0; cb < 2; cb++) {
                        float a = acc[mf][nf][rb * 2 + cb];
                        s += a; q += a * a;
                    }
                s += __shfl_xor_sync(0xffffffffu, s, 1); q += __shfl_xor_sync(0xffffffffu, q, 1);
                s += __shfl_xor_sync(0xffffffffu, s, 2); q += __shfl_xor_sync(0xffffffffu, q, 2);
                s8[ri] = s; q8[ri] = q;
            }
        if ((lane & 3) == 0) {
            #pragma unroll
            for (int ri = 0; ri < 8; ri++) {
                const int idx = (((wr * 4 + wc) * 8) + ri) * 8 + (lane >> 2);
                red[idx * 2] = s8[ri]; red[idx * 2 + 1] = q8[ri];
            }
        }
        __syncthreads();
        #pragma unroll
        for (int ri = 0; ri < 8; ri++) {
            const int idx = (((wr * 4 + (wc ^ 1)) * 8) + ri) * 8 + (lane >> 2);
            const float ts = s8[ri] + red[idx * 2];
            const float tq = q8[ri] + red[idx * 2 + 1];
            const float mu = ts * (1.f / 64.f);
            mean[ri] = mu;
            inv[ri] = rsqrtf(fmaxf(tq * (1.f / 64.f) - mu * mu, 0.f) + 1e-5f);
        }

        const int isK = (bx < 4);
        const int g = (isK ? bx : bx - 4) * 2 + (wc >> 1);
        const int half = wc & 1;
        const int lq = lane & 3;
        __half* base0 = Ckv + (isK ? 0 : PL);
        #pragma unroll
        for (int mf = 0; mf < 4; mf++)
            #pragma unroll
            for (int rb = 0; rb < 2; rb++) {
                const int ri = mf * 2 + rb;
                const int m = m0 + wr * 64 + mf * 16 + (lane >> 2) + rb * 8;
                const int bb = m >> 12, tt = m & 4095;
                const size_t rowoff = ((size_t)(bb * 8 + g) * 4096 + tt) * 64;
                const float mu = mean[ri], iv = inv[ri];
                if (isK) {
                    const float pp = z_pos[(size_t)m * 2 + half] * 64.f;
                    #pragma unroll
                    for (int nf2 = 0; nf2 < 2; nf2++) {
                        float o[4];
                        #pragma unroll
                        for (int cb = 0; cb < 2; cb++) {
                            const int j = nf2 * 8 + lq * 2 + cb;
                            const float invf = exp2f(-(float)j * (13.287712379549449f / 16.f));
                            float sn, co; sincosf(pp * invf, &sn, &co);
                            const float vlo = (acc[mf][nf2][rb * 2 + cb]     - mu) * iv;
                            const float vhi = (acc[mf][nf2 + 2][rb * 2 + cb] - mu) * iv;
                            o[cb]     = vlo * co - vhi * sn;
                            o[2 + cb] = vhi * co + vlo * sn;
                        }
                        const int cg = half * 32 + nf2 * 8 + lq * 2;
                        *(__half2*)&base0[rowoff + cg] =
                            __half2{__float2half_rn(o[0]), __float2half_rn(o[1])};
                        *(__half2*)&base0[rowoff + cg + 16] =
                            __half2{__float2half_rn(o[2]), __float2half_rn(o[3])};
                    }
                } else {
                    #pragma unroll
                    for (int nf = 0; nf < 4; nf++) {
                        const int cg = half * 32 + nf * 8 + lq * 2;
                        const float a0 = (acc[mf][nf][rb * 2]     - mu) * iv;
                        const float a1 = (acc[mf][nf][rb * 2 + 1] - mu) * iv;
                        *(__half2*)&base0[rowoff + cg] =
                            __half2{__float2half_rn(a0), __float2half_rn(a1)};
                    }
                }
            }
    } else {
        const int half = wc & 1;
        const int lq = lane & 3;
        #pragma unroll
        for (int mf = 0; mf < 4; mf++) {
            #pragma unroll
            for (int rb = 0; rb < 2; rb++) {
                const int r = m0 + wr * 64 + mf * 16 + (lane >> 2) + rb * 8;
                const float pp = x_pos[(size_t)r * 2 + half] * 64.f;
                const size_t rowb = (size_t)r * 512;
                #pragma unroll
                for (int nf2 = 0; nf2 < 2; nf2++) {
                    float o[4];
                    #pragma unroll
                    for (int cb = 0; cb < 2; cb++) {
                        const int j = nf2 * 8 + lq * 2 + cb;
                        const float invf = exp2f(-(float)j * (13.287712379549449f / 16.f));
                        float s, co; sincosf(pp * invf, &s, &co);
                        const int idx = rb * 2 + cb;
                        const float vlo = acc[mf][nf2][idx];
                        const float vhi = acc[mf][nf2 + 2][idx];
                        o[cb]     = vlo * co - vhi * s;
                        o[2 + cb] = vhi * co + vlo * s;
                    }
                    const int cg = n0 + wc * 32 + nf2 * 8 + lq * 2;
                    *(__half2*)&Cq[rowb + cg] =
                        __half2{__float2half_rn(o[0]), __float2half_rn(o[1])};
                    *(__half2*)&Cq[rowb + cg + 16] =
                        __half2{__float2half_rn(o[2]), __float2half_rn(o[3])};
                }
            }
        }
    }
}

// ---------------- epilogue GEMM: out[b] = q2[b] @ W2s[b]^T + bout ----------------------
__global__ __launch_bounds__(256, 2) void gemm_epi(
    const __half* __restrict__ A2, const __half* __restrict__ B2,
    float* __restrict__ C, const float* __restrict__ bias)
{
    extern __shared__ __align__(1024) char smem[];
    A2 += (size_t)blockIdx.z * ((long)NTOKS * 512);
    B2 += (size_t)blockIdx.z * ((long)256 * 512);
    C  += (size_t)blockIdx.z * ((long)NTOKS * 256);
    const int m0 = blockIdx.y * 128, n0 = blockIdx.x * 128;
    const int tid = threadIdx.x, lane = tid & 31, wid = tid >> 5;
    const int wr = wid >> 2, wc = wid & 3;
    const u32 sb = smem_u32(smem);

    const int K2 = 512, total = 16;
    const int lrow = tid >> 1;
    const int lcg = (tid & 1) * 2;

    float acc[4][4][4];
    #pragma unroll
    for (int i = 0; i < 4; i++)
        #pragma unroll
        for (int j = 0; j < 4; j++)
            #pragma unroll
            for (int r = 0; r < 4; r++) acc[i][j][r] = 0.f;

    auto issue = [&](int it) {
        const int stage = it & (NSTAGE - 1);
        const int kk = it * 32;
        const __half* as = A2 + (size_t)(m0 + lrow) * K2 + kk + lcg * 8;
        const __half* bs = B2 + (size_t)(n0 + lrow) * K2 + kk + lcg * 8;
        const u32 da = sb + stage * STAGEB + lrow * ROWB + lcg * 16;
        cpa16(da, as);              cpa16(da + 16, as + 8);
        cpa16(da + TILEB, bs);      cpa16(da + TILEB + 16, bs + 8);
        CP_COMMIT();
    };

    auto compute = [&](int stage) {
        const u32 ab = sb + stage * STAGEB;
        const u32 bb = ab + TILEB;
        #pragma unroll
        for (int kb = 0; kb < 2; kb++) {
            u32 a[4][4], b[2][4];
            #pragma unroll
            for (int mf = 0; mf < 4; mf++) {
                u32 addr = ab + (u32)(wr * 64 + mf * 16 + (lane & 15)) * ROWB
                              + kb * 32 + (lane >> 4) * 16;
                ldsm4(a[mf], addr);
            }
            #pragma unroll
            for (int nfp = 0; nfp < 2; nfp++) {
                u32 addr = bb + (u32)(wc * 32 + nfp * 16 + ((lane >> 4) << 3) + (lane & 7)) * ROWB
                              + kb * 32 + ((lane >> 3) & 1) * 16;
                ldsm4(b[nfp], addr);
            }
            #pragma unroll
            for (int mf = 0; mf < 4; mf++)
                #pragma unroll
                for (int nf = 0; nf < 4; nf++)
                    mma16816h(acc[mf][nf], a[mf], &b[nf >> 1][(nf & 1) * 2]);
        }
    };

    issue(0); issue(1); issue(2);
    for (int i = 0; i < total; i++) {
        if (i < total - 2)       CP_WAIT(2);
        else if (i == total - 2) CP_WAIT(1);
        else                     CP_WAIT(0);
        __syncthreads();
        compute(i & (NSTAGE - 1));
        if (i + 3 < total) issue(i + 3);
    }

    const int rbase = m0 + wr * 64 + (lane >> 2);
    const int cbase = n0 + wc * 32 + (lane & 3) * 2;
    #pragma unroll
    for (int nf = 0; nf < 4; nf++) {
        const int c = cbase + nf * 8;
        const float bx = bias[c], by = bias[c + 1];
        #pragma unroll
        for (int mf = 0; mf < 4; mf++) {
            const int r = rbase + mf * 16;
            *(float2*)&C[(size_t)r * 256 + c] =
                make_float2(acc[mf][nf][0] + bx, acc[mf][nf][1] + by);
            *(float2*)&C[(size_t)(r + 8) * 256 + c] =
                make_float2(acc[mf][nf][2] + bx, acc[mf][nf][3] + by);
        }
    }
}

// ---------------- dots: pure streaming fp16 Gram MMA ----------------
#define DROWB 144
#define DTILE (64 * DROWB)
#define DSTG2 (2 * DTILE)
#define DSM_BYTES (2 * DSTG2)

__global__ __launch_bounds__(256, 2) void dots_pure(const __half* __restrict__ kvs,
                                                    float* __restrict__ part) {
    extern __shared__ __align__(1024) char dsm[];
    const u32 sb = smem_u32(dsm);

    const int split = blockIdx.x;
    const int bh = blockIdx.y;
    const int tid = threadIdx.x;
    const int w = tid >> 5, lane = tid & 31;
    const int wr = w >> 1, wc = w & 1;

    float acc[4][4];
    #pragma unroll
    for (int i = 0; i < 4; i++)
        #pragma unroll
        for (int j = 0; j < 4; j++) acc[i][j] = 0.f;

    auto issue = [&](int c) {
        const int t0 = split * 256 + c * 64;
        const u32 sbase = sb + (c & 1) * DSTG2;
        #pragma unroll
        for (int i = 0; i < 4; i++) {
            const int idx = i * 256 + tid;
            const int plane = idx >> 9;
            const int r = (idx >> 3) & 63;
            const int seg = idx & 7;
            const __half* src = kvs + (size_t)plane * PL
                + ((size_t)bh * 4096 + t0 + r) * 64 + seg * 8;
            cpa16(sbase + plane * DTILE + r * DROWB + seg * 16, src);
        }
        CP_COMMIT();
    };

    issue(0);
    for (int c = 0; c < 4; c++) {
        if (c < 3) { issue(c + 1); CP_WAIT(1); } else { CP_WAIT(0); }
        __syncthreads();
        const u32 khb = sb + (c & 1) * DSTG2;
        const u32 vhb = khb + DTILE;
        #pragma unroll
        for (int kt = 0; kt < 4; kt++) {
            const u32 arow = (u32)(kt * 16 + (lane & 7) + ((lane >> 4) << 3));
            const u32 acol = (u32)(wr * 16 + ((lane >> 3) & 1) * 8);
            u32 ah[4];
            ldsm4t(ah, khb + arow * DROWB + acol * 2);
            const u32 brow = (u32)(kt * 16 + (lane & 7) + ((lane >> 3) & 1) * 8);
            const u32 bcol = (u32)(wc * 32 + ((lane >> 4) << 3));
            const u32 boff = brow * DROWB + bcol * 2;
            u32 bh0[4], bh1[4];
            ldsm4t(bh0, vhb + boff);
            ldsm4t(bh1, vhb + boff + 32);
            mma16816h(acc[0], ah, &bh0[0]);
            mma16816h(acc[1], ah, &bh0[2]);
            mma16816h(acc[2], ah, &bh1[0]);
            mma16816h(acc[3], ah, &bh1[2]);
        }
        __syncthreads();
    }

    float* dst = part + ((size_t)bh * NSPLIT + split) * 4096;
    const int dr = wr * 16 + (lane >> 2);
    const int ec = wc * 32 + (lane & 3) * 2;
    #pragma unroll
    for (int nf = 0; nf < 4; nf++) {
        *(float2*)&dst[(size_t)dr * 64 + ec + nf * 8]       = make_float2(acc[nf][0], acc[nf][1]);
        *(float2*)&dst[(size_t)(dr + 8) * 64 + ec + nf * 8] = make_float2(acc[nf][2], acc[nf][3]);
    }
}

// ---------------- w2k: W2s = fp16( ((sum dots)/n2 @ Wout)^T ), 4-wide LDG batching -----
__global__ __launch_bounds__(256) void w2k(const float* __restrict__ part, const float* __restrict__ Wout,
                                           __half* __restrict__ W2s) {
    const int bh = blockIdx.x, dg = blockIdx.y;
    const int b = bh >> 3, h = bh & 7;
    __shared__ float ds[512];                      // [8 d][64 e]
    const int tid = threadIdx.x;
    if (tid < 128) {
        float4 s = make_float4(0.f, 0.f, 0.f, 0.f);
        const float4* base = (const float4*)(part + (size_t)bh * NSPLIT * 4096 + dg * 512) + tid;
        #pragma unroll
        for (int sp = 0; sp < NSPLIT; sp++) {
            const float4 v = base[sp * 1024];
            s.x += v.x; s.y += v.y; s.z += v.z; s.w += v.w;
        }
        *(float4*)&ds[tid * 4] = make_float4(s.x * (1.f / 4096.f), s.y * (1.f / 4096.f),
                                             s.z * (1.f / 4096.f), s.w * (1.f / 4096.f));
    }
    __syncthreads();

    const int p = tid & 127, dq = tid >> 7;
    u64 acc[4];
    #pragma unroll
    for (int d = 0; d < 4; d++) acc[d] = 0ull;
    const float* wbase = Wout + (size_t)(h * 64) * 256 + 2 * p;
    #pragma unroll 2
    for (int e = 0; e < 64; e += 4) {
        const u64 w0 = *(const u64*)(wbase + (size_t)(e + 0) * 256);
        const u64 w1 = *(const u64*)(wbase + (size_t)(e + 1) * 256);
        const u64 w2 = *(const u64*)(wbase + (size_t)(e + 2) * 256);
        const u64 w3 = *(const u64*)(wbase + (size_t)(e + 3) * 256);
        const float* dsr = &ds[(dq * 4) * 64 + e];
        #pragma unroll
        for (int d = 0; d < 4; d++) {
            const float* r = dsr + d * 64;
            acc[d] = ffma2(pack2(r[0], r[0]), w0, acc[d]);
            acc[d] = ffma2(pack2(r[1], r[1]), w1, acc[d]);
            acc[d] = ffma2(pack2(r[2], r[2]), w2, acc[d]);
            acc[d] = ffma2(pack2(r[3], r[3]), w3, acc[d]);
        }
    }
    #pragma unroll
    for (int d = 0; d < 4; d++) {
        float o0, o1; unpack2(acc[d], o0, o1);
        const int dgg = h * 64 + dg * 8 + dq * 4 + d;
        size_t r0 = ((size_t)b * 256 + 2 * p) * 512;
        W2s[r0 + dgg]       = __float2half_rn(o0);
        W2s[r0 + 512 + dgg] = __float2half_rn(o1);
    }
}

// ---------------- launch ----------------
extern "C" void kernel_launch(void* const* d_in, const int* in_sizes, int n_in,
                              void* d_out, int out_size) {
    const float* x     = (const float*)d_in[0];
    const float* z     = (const float*)d_in[1];
    const float* x_pos = (const float*)d_in[2];
    const float* z_pos = (const float*)d_in[3];
    const float* Wq    = (const float*)d_in[4];
    const float* Wkv   = (const float*)d_in[5];
    const float* Wout  = (const float*)d_in[6];
    const float* bout  = (const float*)d_in[7];
    float* out = (float*)d_out;

    float* dotp;
    __half *kvs, *z2, *x2, *wkv2, *wq2, *q2, *w2s;
    cudaGetSymbolAddress((void**)&kvs,  g_kvs);
    cudaGetSymbolAddress((void**)&dotp, g_dotp);
    cudaGetSymbolAddress((void**)&z2,   g_z2);
    cudaGetSymbolAddress((void**)&x2,   g_x2);
    cudaGetSymbolAddress((void**)&wkv2, g_wkv2);
    cudaGetSymbolAddress((void**)&wq2,  g_wq2);
    cudaGetSymbolAddress((void**)&q2,   g_q2);
    cudaGetSymbolAddress((void**)&w2s,  g_w2s);

    // lazy one-time host resources (no device memory involved)
    static cudaStream_t s2 = nullptr;
    static cudaEvent_t evPrep = nullptr, evQ = nullptr;
    if (!s2) {
        cudaStreamCreateWithFlags(&s2, cudaStreamNonBlocking);
        cudaEventCreateWithFlags(&evPrep, cudaEventDisableTiming);
        cudaEventCreateWithFlags(&evQ, cudaEventDisableTiming);
        cudaFuncSetAttribute(gemm_main, cudaFuncAttributeMaxDynamicSharedMemorySize, GSMEM);
        cudaFuncSetAttribute(gemm_epi,  cudaFuncAttributeMaxDynamicSharedMemorySize, GSMEM);
        cudaFuncSetAttribute(dots_pure, cudaFuncAttributeMaxDynamicSharedMemorySize, DSM_BYTES);
    }

    // prep (fp16 conversions) on main stream
    prep<<<17920, 256>>>(z, x, Wkv, Wq, z2, x2, wkv2, wq2);
    cudaEventRecord(evPrep, 0);

    // q GEMM on side stream (independent of kv chain)
    cudaStreamWaitEvent(s2, evPrep, 0);
    gemm_main<<<dim3(4, 256), 256, GSMEM, s2>>>(z2, wkv2, x2, wq2, kvs, q2, z_pos, x_pos, 8);
    cudaEventRecord(evQ, s2);

    // kv chain on main stream: kv GEMM -> dots -> w2k
    gemm_main<<<dim3(8, 256), 256, GSMEM>>>(z2, wkv2, x2, wq2, kvs, q2, z_pos, x_pos, 0);
    dots_pure<<<dim3(NSPLIT, 64), 256, DSM_BYTES>>>(kvs, dotp);
    w2k<<<dim3(64, 8), 256>>>(dotp, Wout, w2s);

    // join: epilogue needs q2 (side) + w2s (main)
    cudaStreamWaitEvent(0, evQ, 0);
    gemm_epi<<<dim3(2, 32, BATCH), 256, GSMEM>>>(q2, w2s, out, bout);
}